// round 1
// baseline (speedup 1.0000x reference)
#include <cuda_runtime.h>
#include <math.h>
#include <float.h>

// ---------------------------------------------------------------------------
// Problem constants
// ---------------------------------------------------------------------------
#define NB      4          // batch groups
#define NTOK    1024       // packed tokens per group
#define DIM     768
#define NHEAD   12
#define DHEAD   64
#define MLPD    3072
#define IMGS    4
#define NCLS    1000
#define TOKS    (NB*NTOK)  // 4096
#define BH      (NB*NHEAD) // 48

#define FBIAS 1
#define FGELU 2
#define FRES  4
#define FAV   8

// ---------------------------------------------------------------------------
// Device scratch (static globals — no allocation inside kernel_launch)
// ---------------------------------------------------------------------------
__device__ float g_x   [TOKS*DIM];
__device__ float g_xn  [TOKS*DIM];
__device__ float g_tmp [TOKS*MLPD];                 // q | kv, and MLP hidden
__device__ float g_qT  [BH*NTOK*DHEAD];
__device__ float g_kT  [BH*NTOK*DHEAD];
__device__ float g_vT  [BH*NTOK*DHEAD];
__device__ float g_ao  [TOKS*DIM];
__device__ float g_sc  [50331648];                  // 48*1024*1024 scores
__device__ float g_sm  [4096];                      // small vectors
__device__ float g_pattn[16*DIM];
__device__ float g_pool [16*DIM];
__device__ float g_pln  [16*DIM];

// ---------------------------------------------------------------------------
// LayerNorm over width 768 (blockDim=256, 3 elems/thread). Optional pos-embed add.
// ---------------------------------------------------------------------------
__global__ void ln_kernel(const float* __restrict__ in, const float* __restrict__ g,
                          float* __restrict__ out,
                          const float* __restrict__ pos_h, const float* __restrict__ pos_w,
                          const int* __restrict__ ppos)
{
    int row = blockIdx.x;
    int tid = threadIdx.x;
    const float* xr = in + (size_t)row * 768;
    float v[3]; float s = 0.f, q = 0.f;
#pragma unroll
    for (int i = 0; i < 3; i++) { float t = xr[tid + i*256]; v[i] = t; s += t; q += t*t; }
#pragma unroll
    for (int o = 16; o; o >>= 1) {
        s += __shfl_xor_sync(0xffffffffu, s, o);
        q += __shfl_xor_sync(0xffffffffu, q, o);
    }
    __shared__ float shs[8], shq[8], st[2];
    int w = tid >> 5;
    if ((tid & 31) == 0) { shs[w] = s; shq[w] = q; }
    __syncthreads();
    if (tid == 0) {
        float S = 0.f, Q = 0.f;
#pragma unroll
        for (int i = 0; i < 8; i++) { S += shs[i]; Q += shq[i]; }
        float mu = S * (1.f/768.f);
        st[0] = mu;
        st[1] = rsqrtf(Q * (1.f/768.f) - mu*mu + 1e-5f);
    }
    __syncthreads();
    float mu = st[0], rs = st[1];
    int p0 = 0, p1 = 0;
    if (ppos) { p0 = ppos[row*2]; p1 = ppos[row*2 + 1]; }
#pragma unroll
    for (int i = 0; i < 3; i++) {
        int c = tid + i*256;
        float y = (v[i] - mu) * rs * g[c];
        if (ppos) y += pos_h[p0*768 + c] + pos_w[p1*768 + c];
        out[(size_t)row*768 + c] = y;
    }
}

// ---------------------------------------------------------------------------
// Tiled fp32 GEMM: C[64x64 tile] = A(MxK,rm) @ B(KxN,rm), batched over z.
// Epilogue: +bias, gelu(erf), +residual. FAV mode scatters attn output into
// (b, n, h*64+d) layout with ldc=768.
// ---------------------------------------------------------------------------
__global__ void gemm_kernel(const float* __restrict__ A, const float* __restrict__ B,
                            const float* __restrict__ bias, const float* __restrict__ res,
                            float* __restrict__ C,
                            int M, int N, int K,
                            size_t sA, size_t sB, int flags)
{
    __shared__ float As[16][68];
    __shared__ float Bs[16][68];

    int z = blockIdx.z;
    const float* Ap = A + (size_t)z * sA;
    const float* Bp = B + (size_t)z * sB;

    size_t coff = 0;
    int ldc = N;
    if (flags & FAV) {
        int b = z / 12, h = z % 12;
        coff = (size_t)b * NTOK * DIM + (size_t)h * 64;
        ldc = DIM;
    }

    int tid = threadIdx.x;
    int tx = tid & 15, ty = tid >> 4;
    int bm = blockIdx.y * 64, bn = blockIdx.x * 64;

    float acc[4][4] = {};

    int a_m = tid >> 2;          // 0..63
    int a_k = (tid & 3) * 4;     // 0,4,8,12
    int b_k = tid >> 4;          // 0..15
    int b_n = (tid & 15) * 4;

    for (int k0 = 0; k0 < K; k0 += 16) {
        float4 av = *(const float4*)&Ap[(size_t)(bm + a_m)*K + k0 + a_k];
        As[a_k+0][a_m] = av.x; As[a_k+1][a_m] = av.y;
        As[a_k+2][a_m] = av.z; As[a_k+3][a_m] = av.w;
        float4 bv = *(const float4*)&Bp[(size_t)(k0 + b_k)*N + bn + b_n];
        Bs[b_k][b_n+0] = bv.x; Bs[b_k][b_n+1] = bv.y;
        Bs[b_k][b_n+2] = bv.z; Bs[b_k][b_n+3] = bv.w;
        __syncthreads();
#pragma unroll
        for (int k = 0; k < 16; k++) {
            float ra[4], rb[4];
#pragma unroll
            for (int i = 0; i < 4; i++) ra[i] = As[k][ty*4 + i];
#pragma unroll
            for (int j = 0; j < 4; j++) rb[j] = Bs[k][tx*4 + j];
#pragma unroll
            for (int i = 0; i < 4; i++)
#pragma unroll
                for (int j = 0; j < 4; j++) acc[i][j] += ra[i] * rb[j];
        }
        __syncthreads();
    }

#pragma unroll
    for (int i = 0; i < 4; i++) {
#pragma unroll
        for (int j = 0; j < 4; j++) {
            int m = bm + ty*4 + i, n = bn + tx*4 + j;
            float v = acc[i][j];
            if (flags & FBIAS) v += bias[n];
            if (flags & FGELU) v = 0.5f * v * (1.f + erff(v * 0.70710678118654752f));
            size_t idx = coff + (size_t)m * ldc + n;
            if (flags & FRES) v += res[idx];
            C[idx] = v;
        }
    }
}

// ---------------------------------------------------------------------------
// QK-RMSNorm (per head, 64 dims) + transpose (n, h*64+d) -> (b, h, n, d).
// g==nullptr => plain transpose (used for V). blockDim = 384 (12 warps).
// ---------------------------------------------------------------------------
__global__ void rmsT_kernel(const float* __restrict__ in, int ld, int off,
                            const float* __restrict__ g, float* __restrict__ outT)
{
    int token = blockIdx.x;
    int b = token >> 10, n = token & 1023;
    int w = threadIdx.x >> 5, lane = threadIdx.x & 31;
    const float* src = in + (size_t)token * ld + off + w*64;
    float v0 = src[lane], v1 = src[lane + 32];
    if (g) {
        float ss = v0*v0 + v1*v1;
#pragma unroll
        for (int o = 16; o; o >>= 1) ss += __shfl_xor_sync(0xffffffffu, ss, o);
        float inv = 8.0f / fmaxf(sqrtf(ss), 1e-12f);
        v0 *= inv * g[w*64 + lane];
        v1 *= inv * g[w*64 + lane + 32];
    }
    float* dst = outT + ((size_t)(b*12 + w) * 1024 + n) * 64;
    dst[lane] = v0; dst[lane + 32] = v1;
}

// ---------------------------------------------------------------------------
// S[i,j] = q_i . k_j with block-diagonal image mask. grid (16,16,48), 256 thr.
// ---------------------------------------------------------------------------
__global__ void scores_kernel(const float* __restrict__ qT, const float* __restrict__ kT,
                              const int* __restrict__ image_ids, const int* __restrict__ lengths,
                              float* __restrict__ S)
{
    __shared__ float Qs[64][65];
    __shared__ float Ks[64][65];
    int z = blockIdx.z;
    int b = z / 12;
    int i0 = blockIdx.y * 64, j0 = blockIdx.x * 64;
    const float* Q = qT + ((size_t)z * 1024 + i0) * 64;
    const float* K = kT + ((size_t)z * 1024 + j0) * 64;
    int tid = threadIdx.x;

#pragma unroll
    for (int t = 0; t < 4; t++) {
        int e = tid + t*256;       // over 1024 float4s
        int r = e >> 4;
        int c = (e & 15) * 4;
        float4 qv = *(const float4*)&Q[(size_t)r*64 + c];
        Qs[r][c] = qv.x; Qs[r][c+1] = qv.y; Qs[r][c+2] = qv.z; Qs[r][c+3] = qv.w;
        float4 kv = *(const float4*)&K[(size_t)r*64 + c];
        Ks[r][c] = kv.x; Ks[r][c+1] = kv.y; Ks[r][c+2] = kv.z; Ks[r][c+3] = kv.w;
    }
    __syncthreads();

    int tx = tid & 15, ty = tid >> 4;
    float acc[4][4] = {};
#pragma unroll
    for (int k = 0; k < 64; k++) {
        float ra[4], rb[4];
#pragma unroll
        for (int i = 0; i < 4; i++) ra[i] = Qs[ty*4 + i][k];
#pragma unroll
        for (int j = 0; j < 4; j++) rb[j] = Ks[tx*4 + j][k];
#pragma unroll
        for (int i = 0; i < 4; i++)
#pragma unroll
            for (int j = 0; j < 4; j++) acc[i][j] += ra[i] * rb[j];
    }

    int len = lengths[b];
    int img_i[4], img_j[4];
#pragma unroll
    for (int i = 0; i < 4; i++) img_i[i] = image_ids[b*1024 + i0 + ty*4 + i];
#pragma unroll
    for (int j = 0; j < 4; j++) img_j[j] = image_ids[b*1024 + j0 + tx*4 + j];

#pragma unroll
    for (int i = 0; i < 4; i++) {
#pragma unroll
        for (int j = 0; j < 4; j++) {
            int ii = i0 + ty*4 + i, jj = j0 + tx*4 + j;
            bool ok = (img_i[i] == img_j[j]) && (jj < len);
            S[((size_t)z * 1024 + ii) * 1024 + jj] = ok ? acc[i][j] : -FLT_MAX;
        }
    }
}

// ---------------------------------------------------------------------------
// Row softmax over 1024 cols. grid = 49152, 256 threads, float4 each.
// ---------------------------------------------------------------------------
__global__ void softmax_kernel(float* __restrict__ S)
{
    size_t row = blockIdx.x;
    float4* p = reinterpret_cast<float4*>(S + row * 1024);
    int tid = threadIdx.x;
    float4 v = p[tid];
    float m = fmaxf(fmaxf(v.x, v.y), fmaxf(v.z, v.w));
#pragma unroll
    for (int o = 16; o; o >>= 1) m = fmaxf(m, __shfl_xor_sync(0xffffffffu, m, o));
    __shared__ float sh[8]; __shared__ float bs[2];
    int w = tid >> 5;
    if ((tid & 31) == 0) sh[w] = m;
    __syncthreads();
    if (tid == 0) { float mm = sh[0]; for (int i = 1; i < 8; i++) mm = fmaxf(mm, sh[i]); bs[0] = mm; }
    __syncthreads();
    m = bs[0];
    float e0 = __expf(v.x - m), e1 = __expf(v.y - m), e2 = __expf(v.z - m), e3 = __expf(v.w - m);
    float s = e0 + e1 + e2 + e3;
#pragma unroll
    for (int o = 16; o; o >>= 1) s += __shfl_xor_sync(0xffffffffu, s, o);
    if ((tid & 31) == 0) sh[w] = s;
    __syncthreads();
    if (tid == 0) { float ss = 0.f; for (int i = 0; i < 8; i++) ss += sh[i]; bs[1] = 1.f / ss; }
    __syncthreads();
    float inv = bs[1];
    p[tid] = make_float4(e0*inv, e1*inv, e2*inv, e3*inv);
}

// ---------------------------------------------------------------------------
// Attention pooling: 192 blocks = (b, img, h). Query is the single shared
// rmsnormed pool query vector (identical across b, img).
// ---------------------------------------------------------------------------
__global__ void pool_attn_kernel(const float* __restrict__ pqn, const float* __restrict__ kT,
                                 const float* __restrict__ vT, const int* __restrict__ image_ids,
                                 const int* __restrict__ lengths, float* __restrict__ out)
{
    int idx = blockIdx.x;
    int h = idx % 12, img = (idx / 12) % 4, b = idx / 48;
    int tid = threadIdx.x;
    __shared__ float q[64];
    __shared__ float p[1024];
    __shared__ float sh[8];
    __shared__ float bs[2];
    __shared__ float sred[256];
    if (tid < 64) q[tid] = pqn[h*64 + tid];
    __syncthreads();

    const float* K = kT + (size_t)(b*12 + h) * 1024 * 64;
    int len = lengths[b];
    float loc[4]; float mx = -FLT_MAX;
#pragma unroll
    for (int t = 0; t < 4; t++) {
        int j = tid + t*256;
        const float* kr = K + (size_t)j * 64;
        float dot = 0.f;
#pragma unroll
        for (int d = 0; d < 64; d++) dot += q[d] * kr[d];
        bool ok = (image_ids[b*1024 + j] == img) && (j < len);
        loc[t] = ok ? dot : -FLT_MAX;
        mx = fmaxf(mx, loc[t]);
    }
#pragma unroll
    for (int o = 16; o; o >>= 1) mx = fmaxf(mx, __shfl_xor_sync(0xffffffffu, mx, o));
    int w = tid >> 5;
    if ((tid & 31) == 0) sh[w] = mx;
    __syncthreads();
    if (tid == 0) { float mm = sh[0]; for (int i = 1; i < 8; i++) mm = fmaxf(mm, sh[i]); bs[0] = mm; }
    __syncthreads();
    mx = bs[0];
    float s = 0.f;
#pragma unroll
    for (int t = 0; t < 4; t++) {
        float e = __expf(loc[t] - mx);
        p[tid + t*256] = e;
        s += e;
    }
#pragma unroll
    for (int o = 16; o; o >>= 1) s += __shfl_xor_sync(0xffffffffu, s, o);
    if ((tid & 31) == 0) sh[w] = s;
    __syncthreads();
    if (tid == 0) { float ss = 0.f; for (int i = 0; i < 8; i++) ss += sh[i]; bs[1] = 1.f / ss; }
    __syncthreads();
    float inv = bs[1];

    const float* V = vT + (size_t)(b*12 + h) * 1024 * 64;
    int d = tid & 63, grp = tid >> 6;
    float acc = 0.f;
    for (int j = grp; j < 1024; j += 4) acc += p[j] * V[(size_t)j*64 + d];
    sred[tid] = acc;
    __syncthreads();
    if (grp == 0) {
        float r = (sred[d] + sred[d + 64]) + (sred[d + 128] + sred[d + 192]);
        out[(size_t)(b*4 + img) * 768 + h*64 + d] = r * inv;
    }
}

// ---------------------------------------------------------------------------
// Per-head RMSNorm of a single 768-vector (pool q). 384 threads.
// ---------------------------------------------------------------------------
__global__ void rms_vec_kernel(const float* __restrict__ in, const float* __restrict__ g,
                               float* __restrict__ out)
{
    int w = threadIdx.x >> 5, lane = threadIdx.x & 31;
    float v0 = in[w*64 + lane], v1 = in[w*64 + lane + 32];
    float ss = v0*v0 + v1*v1;
#pragma unroll
    for (int o = 16; o; o >>= 1) ss += __shfl_xor_sync(0xffffffffu, ss, o);
    float inv = 8.0f / fmaxf(sqrtf(ss), 1e-12f);
    out[w*64 + lane]      = v0 * inv * g[w*64 + lane];
    out[w*64 + lane + 32] = v1 * inv * g[w*64 + lane + 32];
}

// ---------------------------------------------------------------------------
// Small GEMM (M<=16, K<=768): C[row, n] = A[row,:] . W[:, n] (+ addvec[n]).
// grid (ceil(N/256), M), 256 threads.
// ---------------------------------------------------------------------------
__global__ void small_gemm_kernel(const float* __restrict__ A, const float* __restrict__ W,
                                  const float* __restrict__ addvec, float* __restrict__ C,
                                  int N, int K)
{
    __shared__ float a[768];
    int row = blockIdx.y;
    for (int i = threadIdx.x; i < K; i += 256) a[i] = A[(size_t)row*K + i];
    __syncthreads();
    int n = blockIdx.x * 256 + threadIdx.x;
    if (n >= N) return;
    float acc = addvec ? addvec[n] : 0.f;
#pragma unroll 4
    for (int k = 0; k < K; k++) acc += a[k] * W[(size_t)k*N + n];
    C[(size_t)row*N + n] = acc;
}

// ---------------------------------------------------------------------------
// Host side
// ---------------------------------------------------------------------------
static void launch_gemm(const float* A, const float* B, const float* bias, const float* res,
                        float* C, int M, int N, int K, size_t sA, size_t sB, int flags, int batch)
{
    dim3 grid(N / 64, M / 64, batch);
    gemm_kernel<<<grid, 256>>>(A, B, bias, res, C, M, N, K, sA, sB, flags);
}

extern "C" void kernel_launch(void* const* d_in, const int* in_sizes, int n_in,
                              void* d_out, int out_size)
{
    (void)in_sizes; (void)n_in; (void)out_size;
    const float* patches    = (const float*)d_in[0];
    const int*   ppos       = (const int*)  d_in[1];
    const int*   image_ids  = (const int*)  d_in[2];
    const int*   lengths    = (const int*)  d_in[3];
    const float* emb_ln_g   = (const float*)d_in[4];
    const float* W_emb      = (const float*)d_in[5];
    const float* b_emb      = (const float*)d_in[6];
    const float* emb_ln2_g  = (const float*)d_in[7];
    const float* pos_h      = (const float*)d_in[8];
    const float* pos_w      = (const float*)d_in[9];
    const float* ln_attn_g  = (const float*)d_in[10];
    const float* Wq         = (const float*)d_in[11];
    const float* Wkv        = (const float*)d_in[12];
    const float* qn_g       = (const float*)d_in[13];
    const float* kn_g       = (const float*)d_in[14];
    const float* Wo         = (const float*)d_in[15];
    const float* ln_ff_g    = (const float*)d_in[16];
    const float* W1         = (const float*)d_in[17];
    const float* b1         = (const float*)d_in[18];
    const float* W2         = (const float*)d_in[19];
    const float* b2         = (const float*)d_in[20];
    const float* final_ln_g = (const float*)d_in[21];
    const float* pool_q     = (const float*)d_in[22];
    const float* pool_ln_g  = (const float*)d_in[23];
    const float* pWq        = (const float*)d_in[24];
    const float* pWkv       = (const float*)d_in[25];
    const float* p_qn_g     = (const float*)d_in[26];
    const float* p_kn_g     = (const float*)d_in[27];
    const float* pWo        = (const float*)d_in[28];
    const float* head_ln_g  = (const float*)d_in[29];
    const float* W_head     = (const float*)d_in[30];

    float *x, *xn, *tmp, *qT, *kT, *vT, *ao, *sc, *sm, *pattn, *pool, *pln;
    cudaGetSymbolAddress((void**)&x,    g_x);
    cudaGetSymbolAddress((void**)&xn,   g_xn);
    cudaGetSymbolAddress((void**)&tmp,  g_tmp);
    cudaGetSymbolAddress((void**)&qT,   g_qT);
    cudaGetSymbolAddress((void**)&kT,   g_kT);
    cudaGetSymbolAddress((void**)&vT,   g_vT);
    cudaGetSymbolAddress((void**)&ao,   g_ao);
    cudaGetSymbolAddress((void**)&sc,   g_sc);
    cudaGetSymbolAddress((void**)&sm,   g_sm);
    cudaGetSymbolAddress((void**)&pattn,g_pattn);
    cudaGetSymbolAddress((void**)&pool, g_pool);
    cudaGetSymbolAddress((void**)&pln,  g_pln);

    float* qbuf  = tmp;
    float* kvbuf = tmp + (size_t)TOKS * DIM;

    // ---- Embedding ----
    ln_kernel<<<TOKS, 256>>>(patches, emb_ln_g, xn, nullptr, nullptr, nullptr);
    launch_gemm(xn, W_emb, b_emb, nullptr, x, TOKS, DIM, DIM, 0, 0, FBIAS, 1);
    ln_kernel<<<TOKS, 256>>>(x, emb_ln2_g, x, pos_h, pos_w, ppos);

    // ---- Transformer layers ----
    for (int l = 0; l < 4; l++) {
        ln_kernel<<<TOKS, 256>>>(x, ln_attn_g + l*DIM, xn, nullptr, nullptr, nullptr);
        launch_gemm(xn, Wq  + (size_t)l*DIM*DIM,   nullptr, nullptr, qbuf,  TOKS, DIM,    DIM, 0, 0, 0, 1);
        launch_gemm(xn, Wkv + (size_t)l*DIM*2*DIM, nullptr, nullptr, kvbuf, TOKS, 2*DIM,  DIM, 0, 0, 0, 1);
        rmsT_kernel<<<TOKS, 384>>>(qbuf,  DIM,   0,   qn_g + l*DIM, qT);
        rmsT_kernel<<<TOKS, 384>>>(kvbuf, 2*DIM, 0,   kn_g + l*DIM, kT);
        rmsT_kernel<<<TOKS, 384>>>(kvbuf, 2*DIM, DIM, nullptr,      vT);
        scores_kernel<<<dim3(16, 16, BH), 256>>>(qT, kT, image_ids, lengths, sc);
        softmax_kernel<<<BH * NTOK, 256>>>(sc);
        launch_gemm(sc, vT, nullptr, nullptr, ao, NTOK, DHEAD, NTOK,
                    (size_t)NTOK*NTOK, (size_t)NTOK*DHEAD, FAV, BH);
        launch_gemm(ao, Wo + (size_t)l*DIM*DIM, nullptr, x, x, TOKS, DIM, DIM, 0, 0, FRES, 1);
        ln_kernel<<<TOKS, 256>>>(x, ln_ff_g + l*DIM, xn, nullptr, nullptr, nullptr);
        launch_gemm(xn,  W1 + (size_t)l*DIM*MLPD, b1 + l*MLPD, nullptr, tmp, TOKS, MLPD, DIM,  0, 0, FBIAS|FGELU, 1);
        launch_gemm(tmp, W2 + (size_t)l*MLPD*DIM, b2 + l*DIM,  x,       x,   TOKS, DIM,  MLPD, 0, 0, FBIAS|FRES, 1);
    }

    // ---- Final LN ----
    ln_kernel<<<TOKS, 256>>>(x, final_ln_g, xn, nullptr, nullptr, nullptr);

    // ---- Attention pooling ----
    ln_kernel<<<1, 256>>>(pool_q, pool_ln_g, sm, nullptr, nullptr, nullptr);       // sm[0:768] = LN(pool_q)
    small_gemm_kernel<<<dim3(3, 1), 256>>>(sm, pWq, nullptr, sm + 768, DIM, DIM);  // pq
    rms_vec_kernel<<<1, 384>>>(sm + 768, p_qn_g, sm + 1536);                       // pq_n
    launch_gemm(xn, pWkv, nullptr, nullptr, kvbuf, TOKS, 2*DIM, DIM, 0, 0, 0, 1);
    rmsT_kernel<<<TOKS, 384>>>(kvbuf, 2*DIM, 0,   p_kn_g, kT);
    rmsT_kernel<<<TOKS, 384>>>(kvbuf, 2*DIM, DIM, nullptr, vT);
    pool_attn_kernel<<<NB*IMGS*NHEAD, 256>>>(sm + 1536, kT, vT, image_ids, lengths, pattn);
    small_gemm_kernel<<<dim3(3, 16), 256>>>(pattn, pWo, pool_q, pool, DIM, DIM);   // + residual (queries)
    ln_kernel<<<16, 256>>>(pool, head_ln_g, pln, nullptr, nullptr, nullptr);
    small_gemm_kernel<<<dim3(4, 16), 256>>>(pln, W_head, nullptr, (float*)d_out, NCLS, DIM);
}

// round 3
// speedup vs baseline: 1.3739x; 1.3739x over previous
#include <cuda_runtime.h>
#include <cuda_bf16.h>
#include <math.h>
#include <float.h>
#include <stdint.h>

// ---------------------------------------------------------------------------
// Problem constants
// ---------------------------------------------------------------------------
#define NB      4
#define NTOK    1024
#define DIM     768
#define NHEAD   12
#define DHEAD   64
#define MLPD    3072
#define IMGS    4
#define NCLS    1000
#define TOKS    (NB*NTOK)
#define BH      (NB*NHEAD)

#define FBIAS 1
#define FGELU 2
#define FRES  4
#define FAV   8
#define FSC   16

// Converted-weight layout (elements, [N,K] bf16, hi and lo separate buffers)
#define WOFF_EMB 0ULL
#define WPERL    7077888ULL
#define WOFF_L(l)   (589824ULL + (unsigned long long)(l)*WPERL)
#define WOFF_Q(l)   (WOFF_L(l) + 0ULL)
#define WOFF_KV(l)  (WOFF_L(l) + 589824ULL)
#define WOFF_O(l)   (WOFF_L(l) + 1769472ULL)
#define WOFF_W1(l)  (WOFF_L(l) + 2359296ULL)
#define WOFF_W2(l)  (WOFF_L(l) + 4718592ULL)
#define WOFF_PKV    (589824ULL + 4ULL*WPERL)
#define WTOTAL      30081024ULL

#define SMB 65536   // dynamic smem: Ahi|Alo|Bhi|Blo, 16KB each

// ---------------------------------------------------------------------------
// Device scratch
// ---------------------------------------------------------------------------
__device__ float g_x   [TOKS*DIM];
__device__ float g_xn  [TOKS*DIM];
__device__ float g_tmp [TOKS*MLPD];
__device__ float g_qT  [BH*NTOK*DHEAD];
__device__ float g_kT  [BH*NTOK*DHEAD];
__device__ float g_vT  [BH*NTOK*DHEAD];   // [z][n][d] for pool
__device__ float g_vTt [BH*NTOK*DHEAD];   // [z][d][n] for AV gemm
__device__ float g_ao  [TOKS*DIM];
__device__ float g_sc  [50331648];
__device__ float g_sm  [4096];
__device__ float g_pattn[16*DIM];
__device__ float g_pool [16*DIM];
__device__ float g_pln  [16*DIM];
__device__ __nv_bfloat16 g_whi[WTOTAL];
__device__ __nv_bfloat16 g_wlo[WTOTAL];

// ---------------------------------------------------------------------------
// Helpers
// ---------------------------------------------------------------------------
__device__ __forceinline__ uint32_t smem_u32(const void* p) {
    uint32_t a;
    asm("{ .reg .u64 t; cvta.to.shared.u64 t, %1; cvt.u32.u64 %0, t; }" : "=r"(a) : "l"(p));
    return a;
}

#define LDSM4(r, addr) \
    asm volatile("ldmatrix.sync.aligned.m8n8.x4.shared.b16 {%0,%1,%2,%3}, [%4];" \
        : "=r"((r)[0]), "=r"((r)[1]), "=r"((r)[2]), "=r"((r)[3]) : "r"(addr))

#define MMA16816(d, a, b) \
    asm volatile("mma.sync.aligned.m16n8k16.row.col.f32.bf16.bf16.f32 " \
        "{%0,%1,%2,%3}, {%4,%5,%6,%7}, {%8,%9}, {%0,%1,%2,%3};" \
        : "+f"((d)[0]), "+f"((d)[1]), "+f"((d)[2]), "+f"((d)[3]) \
        : "r"((a)[0]), "r"((a)[1]), "r"((a)[2]), "r"((a)[3]), "r"((b)[0]), "r"((b)[1]))

// ---------------------------------------------------------------------------
// Weight convert+transpose: W[K,N] fp32 -> hi/lo [N,K] bf16
// ---------------------------------------------------------------------------
__global__ void wconv_kernel(const float* __restrict__ W, __nv_bfloat16* __restrict__ hi,
                             __nv_bfloat16* __restrict__ lo, int K, int N)
{
    __shared__ float t[32][33];
    int n0 = blockIdx.x * 32, k0 = blockIdx.y * 32;
    int tx = threadIdx.x, ty = threadIdx.y;      // block 32x8
#pragma unroll
    for (int r = 0; r < 4; r++)
        t[ty + r*8][tx] = W[(size_t)(k0 + ty + r*8) * N + n0 + tx];
    __syncthreads();
#pragma unroll
    for (int r = 0; r < 4; r++) {
        int n = n0 + ty + r*8, k = k0 + tx;
        float v = t[tx][ty + r*8];
        __nv_bfloat16 h = __float2bfloat16(v);
        hi[(size_t)n * K + k] = h;
        lo[(size_t)n * K + k] = __float2bfloat16(v - __bfloat162float(h));
    }
}

// ---------------------------------------------------------------------------
// Tile loaders into swizzled smem (bf16 hi/lo, rows x 64 cols, 128B rows SW128)
// ---------------------------------------------------------------------------
__device__ __forceinline__ void load_f32_tile(const float* __restrict__ src, int ldk, int rows,
                                              char* sm_hi, char* sm_lo, int tid)
{
    int n4 = rows * 16;
    for (int i = tid; i < n4; i += 256) {
        int r = i >> 4, c4 = i & 15;
        float4 v = *(const float4*)(src + (size_t)r * ldk + c4 * 4);
        __nv_bfloat16 h0 = __float2bfloat16(v.x), h1 = __float2bfloat16(v.y);
        __nv_bfloat16 h2 = __float2bfloat16(v.z), h3 = __float2bfloat16(v.w);
        __nv_bfloat16 l0 = __float2bfloat16(v.x - __bfloat162float(h0));
        __nv_bfloat16 l1 = __float2bfloat16(v.y - __bfloat162float(h1));
        __nv_bfloat16 l2 = __float2bfloat16(v.z - __bfloat162float(h2));
        __nv_bfloat16 l3 = __float2bfloat16(v.w - __bfloat162float(h3));
        uint2 hw, lw;
        hw.x = (uint32_t)__bfloat16_as_ushort(h0) | ((uint32_t)__bfloat16_as_ushort(h1) << 16);
        hw.y = (uint32_t)__bfloat16_as_ushort(h2) | ((uint32_t)__bfloat16_as_ushort(h3) << 16);
        lw.x = (uint32_t)__bfloat16_as_ushort(l0) | ((uint32_t)__bfloat16_as_ushort(l1) << 16);
        lw.y = (uint32_t)__bfloat16_as_ushort(l2) | ((uint32_t)__bfloat16_as_ushort(l3) << 16);
        uint32_t off = r * 128 + c4 * 8;
        uint32_t sw = off ^ ((off >> 3) & 0x70);
        *(uint2*)(sm_hi + sw) = hw;
        *(uint2*)(sm_lo + sw) = lw;
    }
}

__device__ __forceinline__ void load_bf16_tile(const __nv_bfloat16* __restrict__ hi,
                                               const __nv_bfloat16* __restrict__ lo,
                                               int ldk, int rows, char* sm_hi, char* sm_lo, int tid)
{
    int nc = rows * 8;
    for (int i = tid; i < nc; i += 256) {
        int r = i >> 3, c = i & 7;
        uint4 vh = *((const uint4*)(hi + (size_t)r * ldk) + c);
        uint4 vl = *((const uint4*)(lo + (size_t)r * ldk) + c);
        uint32_t off = r * 128 + c * 16;
        uint32_t sw = off ^ ((off >> 3) & 0x70);
        *(uint4*)(sm_hi + sw) = vh;
        *(uint4*)(sm_lo + sw) = vl;
    }
}

// ---------------------------------------------------------------------------
// mma.sync GEMM: C[M,N] = A[M,K](fp32,rm) @ B^T, B stored [N,K] (bf16 hi/lo
// pre-converted weights, or fp32 converted on the fly).
// bf16 hi/lo split: 3 passes (AhBh + AhBl + AlBh) into fp32 accumulators.
// CTA tile 128 x NT (template: 128 or 64), K-tile 64, 8 warps (2M x 4N).
// ---------------------------------------------------------------------------
template<int NT>
__global__ void __launch_bounds__(256, 1) mma_gemm(
    const float* __restrict__ A, long sA,
    const __nv_bfloat16* __restrict__ Bhi, const __nv_bfloat16* __restrict__ Blo,
    const float* __restrict__ Bf32, long sB,
    const float* __restrict__ bias, const float* __restrict__ res,
    const int* __restrict__ image_ids, const int* __restrict__ lengths,
    float* __restrict__ C, int M, int N, int K, int flags)
{
    constexpr int NX4    = (NT == 128) ? 2 : 1;   // B ldmatrix.x4 per warp
    constexpr int NTILES = 2 * NX4;               // 8-wide n tiles per warp
    constexpr int NW     = NT / 4;                // warp n-span

    extern __shared__ char smem[];
    char* sAhi = smem;
    char* sAlo = smem + 16384;
    char* sBhi = smem + 32768;
    char* sBlo = smem + 49152;
    uint32_t uAhi = smem_u32(sAhi), uAlo = smem_u32(sAlo);
    uint32_t uBhi = smem_u32(sBhi), uBlo = smem_u32(sBlo);

    const int tid = threadIdx.x;
    const int wid = tid >> 5, lane = tid & 31;
    const int z = blockIdx.z;
    const int m0 = blockIdx.y * 128, n0 = blockIdx.x * NT;
    const int wm = wid & 1, wn = wid >> 1;

    float acc[4][NTILES][4] = {};

    // ldmatrix lane address components
    const int a_row = wm * 64 + (lane & 15);          // + mt*16
    const int a_cb  = (lane >> 4) * 16;
    const int b_row = wn * NW + (lane & 7) + ((lane >> 4) << 3);  // + q*16
    const int b_cb  = ((lane >> 3) & 1) * 16;

    const float* Ap = A + (size_t)z * sA + (size_t)m0 * K;

    const int KT = K >> 6;
    for (int kt = 0; kt < KT; kt++) {
        load_f32_tile(Ap + kt * 64, K, 128, sAhi, sAlo, tid);
        if (Bf32) {
            load_f32_tile(Bf32 + (size_t)z * sB + (size_t)n0 * K + kt * 64, K, NT, sBhi, sBlo, tid);
        } else {
            load_bf16_tile(Bhi + (size_t)n0 * K + kt * 64, Blo + (size_t)n0 * K + kt * 64,
                           K, NT, sBhi, sBlo, tid);
        }
        __syncthreads();

#pragma unroll
        for (int ks = 0; ks < 4; ks++) {
            uint32_t ah[4][4], al[4][4], bh[NX4][4], bl[NX4][4];
#pragma unroll
            for (int mt = 0; mt < 4; mt++) {
                int row = a_row + mt * 16;
                uint32_t off = row * 128 + ((a_cb + ks * 32) ^ ((row & 7) << 4));
                LDSM4(ah[mt], uAhi + off);
                LDSM4(al[mt], uAlo + off);
            }
#pragma unroll
            for (int q = 0; q < NX4; q++) {
                int row = b_row + q * 16;
                uint32_t off = row * 128 + ((b_cb + ks * 32) ^ ((row & 7) << 4));
                LDSM4(bh[q], uBhi + off);
                LDSM4(bl[q], uBlo + off);
            }
#pragma unroll
            for (int mt = 0; mt < 4; mt++)
#pragma unroll
                for (int nt = 0; nt < NTILES; nt++)
                    MMA16816(acc[mt][nt], ah[mt], &bh[nt >> 1][(nt & 1) * 2]);
#pragma unroll
            for (int mt = 0; mt < 4; mt++)
#pragma unroll
                for (int nt = 0; nt < NTILES; nt++)
                    MMA16816(acc[mt][nt], ah[mt], &bl[nt >> 1][(nt & 1) * 2]);
#pragma unroll
            for (int mt = 0; mt < 4; mt++)
#pragma unroll
                for (int nt = 0; nt < NTILES; nt++)
                    MMA16816(acc[mt][nt], al[mt], &bh[nt >> 1][(nt & 1) * 2]);
        }
        __syncthreads();
    }

    // ---- epilogue ----
    int b_ = 0;
    long cbase; int ldc;
    if (flags & FAV)      { b_ = z / 12; int h_ = z % 12; cbase = (long)b_ * NTOK * DIM + h_ * 64; ldc = DIM; }
    else if (flags & FSC) { b_ = z / 12; cbase = (long)z * NTOK * NTOK; ldc = N; }
    else                  { cbase = 0; ldc = N; }
    int len = (flags & FSC) ? lengths[b_] : 0;

    const int rbase = m0 + wm * 64;
#pragma unroll
    for (int mt = 0; mt < 4; mt++) {
#pragma unroll
        for (int nt = 0; nt < NTILES; nt++) {
            int c = n0 + wn * NW + nt * 8 + (lane & 3) * 2;
            float bv0 = 0.f, bv1 = 0.f;
            if (flags & FBIAS) { bv0 = bias[c]; bv1 = bias[c + 1]; }
            int jm0 = 0, jm1 = 0;
            if (flags & FSC) {
                jm0 = image_ids[b_ * NTOK + c];
                jm1 = image_ids[b_ * NTOK + c + 1];
            }
#pragma unroll
            for (int half = 0; half < 2; half++) {
                int r = rbase + mt * 16 + (lane >> 2) + half * 8;
                float v0 = acc[mt][nt][half * 2 + 0];
                float v1 = acc[mt][nt][half * 2 + 1];
                if (flags & FBIAS) { v0 += bv0; v1 += bv1; }
                if (flags & FGELU) {
                    v0 = 0.5f * v0 * (1.f + erff(v0 * 0.70710678118654752f));
                    v1 = 0.5f * v1 * (1.f + erff(v1 * 0.70710678118654752f));
                }
                long idx = cbase + (long)r * ldc + ((flags & FAV) ? (c - n0) : c);
                if (flags & FRES) { v0 += res[idx]; v1 += res[idx + 1]; }
                if (flags & FSC) {
                    int ii = image_ids[b_ * NTOK + r];
                    v0 = (ii == jm0 && c     < len) ? v0 : -FLT_MAX;
                    v1 = (ii == jm1 && c + 1 < len) ? v1 : -FLT_MAX;
                }
                *(float2*)(C + idx) = make_float2(v0, v1);
            }
        }
    }
}

// ---------------------------------------------------------------------------
// LayerNorm over width 768 (blockDim=256). Optional pos-embed add.
// ---------------------------------------------------------------------------
__global__ void ln_kernel(const float* __restrict__ in, const float* __restrict__ g,
                          float* __restrict__ out,
                          const float* __restrict__ pos_h, const float* __restrict__ pos_w,
                          const int* __restrict__ ppos)
{
    int row = blockIdx.x;
    int tid = threadIdx.x;
    const float* xr = in + (size_t)row * 768;
    float v[3]; float s = 0.f, q = 0.f;
#pragma unroll
    for (int i = 0; i < 3; i++) { float t = xr[tid + i*256]; v[i] = t; s += t; q += t*t; }
#pragma unroll
    for (int o = 16; o; o >>= 1) {
        s += __shfl_xor_sync(0xffffffffu, s, o);
        q += __shfl_xor_sync(0xffffffffu, q, o);
    }
    __shared__ float shs[8], shq[8], st[2];
    int w = tid >> 5;
    if ((tid & 31) == 0) { shs[w] = s; shq[w] = q; }
    __syncthreads();
    if (tid == 0) {
        float S = 0.f, Q = 0.f;
#pragma unroll
        for (int i = 0; i < 8; i++) { S += shs[i]; Q += shq[i]; }
        float mu = S * (1.f/768.f);
        st[0] = mu;
        st[1] = rsqrtf(Q * (1.f/768.f) - mu*mu + 1e-5f);
    }
    __syncthreads();
    float mu = st[0], rs = st[1];
    int p0 = 0, p1 = 0;
    if (ppos) { p0 = ppos[row*2]; p1 = ppos[row*2 + 1]; }
#pragma unroll
    for (int i = 0; i < 3; i++) {
        int c = tid + i*256;
        float y = (v[i] - mu) * rs * g[c];
        if (ppos) y += pos_h[p0*768 + c] + pos_w[p1*768 + c];
        out[(size_t)row*768 + c] = y;
    }
}

// ---------------------------------------------------------------------------
// QK-RMSNorm + transpose (n, h*64+d) -> (b, h, n, d). g==nullptr: plain copy.
// ---------------------------------------------------------------------------
__global__ void rmsT_kernel(const float* __restrict__ in, int ld, int off,
                            const float* __restrict__ g, float* __restrict__ outT)
{
    int token = blockIdx.x;
    int b = token >> 10, n = token & 1023;
    int w = threadIdx.x >> 5, lane = threadIdx.x & 31;
    const float* src = in + (size_t)token * ld + off + w*64;
    float v0 = src[lane], v1 = src[lane + 32];
    if (g) {
        float ss = v0*v0 + v1*v1;
#pragma unroll
        for (int o = 16; o; o >>= 1) ss += __shfl_xor_sync(0xffffffffu, ss, o);
        float inv = 8.0f / fmaxf(sqrtf(ss), 1e-12f);
        v0 *= inv * g[w*64 + lane];
        v1 *= inv * g[w*64 + lane + 32];
    }
    float* dst = outT + ((size_t)(b*12 + w) * 1024 + n) * 64;
    dst[lane] = v0; dst[lane + 32] = v1;
}

// V transpose to [z][d][n] for the AV tensor-core GEMM.
__global__ void rmsTv_kernel(const float* __restrict__ in, int ld, int off,
                             float* __restrict__ outT)
{
    int token = blockIdx.x;
    int b = token >> 10, n = token & 1023;
    int w = threadIdx.x >> 5, lane = threadIdx.x & 31;
    const float* src = in + (size_t)token * ld + off + w*64;
    float v0 = src[lane], v1 = src[lane + 32];
    float* dst = outT + ((size_t)(b*12 + w) * 64) * 1024 + n;
    dst[(size_t)lane * 1024]        = v0;
    dst[(size_t)(lane + 32) * 1024] = v1;
}

// ---------------------------------------------------------------------------
// Row softmax over 1024 cols.
// ---------------------------------------------------------------------------
__global__ void softmax_kernel(float* __restrict__ S)
{
    size_t row = blockIdx.x;
    float4* p = reinterpret_cast<float4*>(S + row * 1024);
    int tid = threadIdx.x;
    float4 v = p[tid];
    float m = fmaxf(fmaxf(v.x, v.y), fmaxf(v.z, v.w));
#pragma unroll
    for (int o = 16; o; o >>= 1) m = fmaxf(m, __shfl_xor_sync(0xffffffffu, m, o));
    __shared__ float sh[8]; __shared__ float bs[2];
    int w = tid >> 5;
    if ((tid & 31) == 0) sh[w] = m;
    __syncthreads();
    if (tid == 0) { float mm = sh[0]; for (int i = 1; i < 8; i++) mm = fmaxf(mm, sh[i]); bs[0] = mm; }
    __syncthreads();
    m = bs[0];
    float e0 = __expf(v.x - m), e1 = __expf(v.y - m), e2 = __expf(v.z - m), e3 = __expf(v.w - m);
    float s = e0 + e1 + e2 + e3;
#pragma unroll
    for (int o = 16; o; o >>= 1) s += __shfl_xor_sync(0xffffffffu, s, o);
    if ((tid & 31) == 0) sh[w] = s;
    __syncthreads();
    if (tid == 0) { float ss = 0.f; for (int i = 0; i < 8; i++) ss += sh[i]; bs[1] = 1.f / ss; }
    __syncthreads();
    float inv = bs[1];
    p[tid] = make_float4(e0*inv, e1*inv, e2*inv, e3*inv);
}

// ---------------------------------------------------------------------------
// Attention pooling (192 blocks = b*img*h).
// ---------------------------------------------------------------------------
__global__ void pool_attn_kernel(const float* __restrict__ pqn, const float* __restrict__ kT,
                                 const float* __restrict__ vT, const int* __restrict__ image_ids,
                                 const int* __restrict__ lengths, float* __restrict__ out)
{
    int idx = blockIdx.x;
    int h = idx % 12, img = (idx / 12) % 4, b = idx / 48;
    int tid = threadIdx.x;
    __shared__ float q[64];
    __shared__ float p[1024];
    __shared__ float sh[8];
    __shared__ float bs[2];
    __shared__ float sred[256];
    if (tid < 64) q[tid] = pqn[h*64 + tid];
    __syncthreads();

    const float* K = kT + (size_t)(b*12 + h) * 1024 * 64;
    int len = lengths[b];
    float loc[4]; float mx = -FLT_MAX;
#pragma unroll
    for (int t = 0; t < 4; t++) {
        int j = tid + t*256;
        const float* kr = K + (size_t)j * 64;
        float dot = 0.f;
#pragma unroll
        for (int d = 0; d < 64; d++) dot += q[d] * kr[d];
        bool ok = (image_ids[b*1024 + j] == img) && (j < len);
        loc[t] = ok ? dot : -FLT_MAX;
        mx = fmaxf(mx, loc[t]);
    }
#pragma unroll
    for (int o = 16; o; o >>= 1) mx = fmaxf(mx, __shfl_xor_sync(0xffffffffu, mx, o));
    int w = tid >> 5;
    if ((tid & 31) == 0) sh[w] = mx;
    __syncthreads();
    if (tid == 0) { float mm = sh[0]; for (int i = 1; i < 8; i++) mm = fmaxf(mm, sh[i]); bs[0] = mm; }
    __syncthreads();
    mx = bs[0];
    float s = 0.f;
#pragma unroll
    for (int t = 0; t < 4; t++) {
        float e = __expf(loc[t] - mx);
        p[tid + t*256] = e;
        s += e;
    }
#pragma unroll
    for (int o = 16; o; o >>= 1) s += __shfl_xor_sync(0xffffffffu, s, o);
    if ((tid & 31) == 0) sh[w] = s;
    __syncthreads();
    if (tid == 0) { float ss = 0.f; for (int i = 0; i < 8; i++) ss += sh[i]; bs[1] = 1.f / ss; }
    __syncthreads();
    float inv = bs[1];

    const float* V = vT + (size_t)(b*12 + h) * 1024 * 64;
    int d = tid & 63, grp = tid >> 6;
    float acc = 0.f;
    for (int j = grp; j < 1024; j += 4) acc += p[j] * V[(size_t)j*64 + d];
    sred[tid] = acc;
    __syncthreads();
    if (grp == 0) {
        float r = (sred[d] + sred[d + 64]) + (sred[d + 128] + sred[d + 192]);
        out[(size_t)(b*4 + img) * 768 + h*64 + d] = r * inv;
    }
}

__global__ void rms_vec_kernel(const float* __restrict__ in, const float* __restrict__ g,
                               float* __restrict__ out)
{
    int w = threadIdx.x >> 5, lane = threadIdx.x & 31;
    float v0 = in[w*64 + lane], v1 = in[w*64 + lane + 32];
    float ss = v0*v0 + v1*v1;
#pragma unroll
    for (int o = 16; o; o >>= 1) ss += __shfl_xor_sync(0xffffffffu, ss, o);
    float inv = 8.0f / fmaxf(sqrtf(ss), 1e-12f);
    out[w*64 + lane]      = v0 * inv * g[w*64 + lane];
    out[w*64 + lane + 32] = v1 * inv * g[w*64 + lane + 32];
}

__global__ void small_gemm_kernel(const float* __restrict__ A, const float* __restrict__ W,
                                  const float* __restrict__ addvec, float* __restrict__ C,
                                  int N, int K)
{
    __shared__ float a[768];
    int row = blockIdx.y;
    for (int i = threadIdx.x; i < K; i += 256) a[i] = A[(size_t)row*K + i];
    __syncthreads();
    int n = blockIdx.x * 256 + threadIdx.x;
    if (n >= N) return;
    float acc = addvec ? addvec[n] : 0.f;
#pragma unroll 4
    for (int k = 0; k < K; k++) acc += a[k] * W[(size_t)k*N + n];
    C[(size_t)row*N + n] = acc;
}

// ---------------------------------------------------------------------------
// Host side
// ---------------------------------------------------------------------------
extern "C" void kernel_launch(void* const* d_in, const int* in_sizes, int n_in,
                              void* d_out, int out_size)
{
    (void)in_sizes; (void)n_in; (void)out_size;
    const float* patches    = (const float*)d_in[0];
    const int*   ppos       = (const int*)  d_in[1];
    const int*   image_ids  = (const int*)  d_in[2];
    const int*   lengths    = (const int*)  d_in[3];
    const float* emb_ln_g   = (const float*)d_in[4];
    const float* W_emb      = (const float*)d_in[5];
    const float* b_emb      = (const float*)d_in[6];
    const float* emb_ln2_g  = (const float*)d_in[7];
    const float* pos_h      = (const float*)d_in[8];
    const float* pos_w      = (const float*)d_in[9];
    const float* ln_attn_g  = (const float*)d_in[10];
    const float* Wq         = (const float*)d_in[11];
    const float* Wkv        = (const float*)d_in[12];
    const float* qn_g       = (const float*)d_in[13];
    const float* kn_g       = (const float*)d_in[14];
    const float* Wo         = (const float*)d_in[15];
    const float* ln_ff_g    = (const float*)d_in[16];
    const float* W1         = (const float*)d_in[17];
    const float* b1         = (const float*)d_in[18];
    const float* W2         = (const float*)d_in[19];
    const float* b2         = (const float*)d_in[20];
    const float* final_ln_g = (const float*)d_in[21];
    const float* pool_q     = (const float*)d_in[22];
    const float* pool_ln_g  = (const float*)d_in[23];
    const float* pWq        = (const float*)d_in[24];
    const float* pWkv       = (const float*)d_in[25];
    const float* p_qn_g     = (const float*)d_in[26];
    const float* p_kn_g     = (const float*)d_in[27];
    const float* pWo        = (const float*)d_in[28];
    const float* head_ln_g  = (const float*)d_in[29];
    const float* W_head     = (const float*)d_in[30];

    float *x, *xn, *tmp, *qT, *kT, *vT, *vTt, *ao, *sc, *sm, *pattn, *pool, *pln;
    __nv_bfloat16 *whi, *wlo;
    cudaGetSymbolAddress((void**)&x,    g_x);
    cudaGetSymbolAddress((void**)&xn,   g_xn);
    cudaGetSymbolAddress((void**)&tmp,  g_tmp);
    cudaGetSymbolAddress((void**)&qT,   g_qT);
    cudaGetSymbolAddress((void**)&kT,   g_kT);
    cudaGetSymbolAddress((void**)&vT,   g_vT);
    cudaGetSymbolAddress((void**)&vTt,  g_vTt);
    cudaGetSymbolAddress((void**)&ao,   g_ao);
    cudaGetSymbolAddress((void**)&sc,   g_sc);
    cudaGetSymbolAddress((void**)&sm,   g_sm);
    cudaGetSymbolAddress((void**)&pattn,g_pattn);
    cudaGetSymbolAddress((void**)&pool, g_pool);
    cudaGetSymbolAddress((void**)&pln,  g_pln);
    cudaGetSymbolAddress((void**)&whi,  g_whi);
    cudaGetSymbolAddress((void**)&wlo,  g_wlo);

    cudaFuncSetAttribute(mma_gemm<128>, cudaFuncAttributeMaxDynamicSharedMemorySize, SMB);
    cudaFuncSetAttribute(mma_gemm<64>,  cudaFuncAttributeMaxDynamicSharedMemorySize, SMB);

    float* qbuf  = tmp;
    float* kvbuf = tmp + (size_t)TOKS * DIM;

    // ---- Convert + transpose all weights to bf16 hi/lo [N,K] ----
    dim3 wb(32, 8);
    wconv_kernel<<<dim3(DIM/32,  DIM/32),  wb>>>(W_emb, whi + WOFF_EMB, wlo + WOFF_EMB, DIM, DIM);
    for (int l = 0; l < 4; l++) {
        wconv_kernel<<<dim3(DIM/32,    DIM/32),  wb>>>(Wq  + (size_t)l*DIM*DIM,    whi + WOFF_Q(l),  wlo + WOFF_Q(l),  DIM,  DIM);
        wconv_kernel<<<dim3(2*DIM/32,  DIM/32),  wb>>>(Wkv + (size_t)l*DIM*2*DIM,  whi + WOFF_KV(l), wlo + WOFF_KV(l), DIM,  2*DIM);
        wconv_kernel<<<dim3(DIM/32,    DIM/32),  wb>>>(Wo  + (size_t)l*DIM*DIM,    whi + WOFF_O(l),  wlo + WOFF_O(l),  DIM,  DIM);
        wconv_kernel<<<dim3(MLPD/32,   DIM/32),  wb>>>(W1  + (size_t)l*DIM*MLPD,   whi + WOFF_W1(l), wlo + WOFF_W1(l), DIM,  MLPD);
        wconv_kernel<<<dim3(DIM/32,    MLPD/32), wb>>>(W2  + (size_t)l*MLPD*DIM,   whi + WOFF_W2(l), wlo + WOFF_W2(l), MLPD, DIM);
    }
    wconv_kernel<<<dim3(2*DIM/32, DIM/32), wb>>>(pWkv, whi + WOFF_PKV, wlo + WOFF_PKV, DIM, 2*DIM);

    auto tcw = [&](const float* A, const __nv_bfloat16* bh, const __nv_bfloat16* bl,
                   const float* bias, const float* res, float* Cp, int M, int N, int K, int flags) {
        dim3 g(N/128, M/128, 1);
        mma_gemm<128><<<g, 256, SMB>>>(A, 0, bh, bl, nullptr, 0, bias, res, nullptr, nullptr,
                                       Cp, M, N, K, flags);
    };

    // ---- Embedding ----
    ln_kernel<<<TOKS, 256>>>(patches, emb_ln_g, xn, nullptr, nullptr, nullptr);
    tcw(xn, whi + WOFF_EMB, wlo + WOFF_EMB, b_emb, nullptr, x, TOKS, DIM, DIM, FBIAS);
    ln_kernel<<<TOKS, 256>>>(x, emb_ln2_g, x, pos_h, pos_w, ppos);

    // ---- Transformer layers ----
    for (int l = 0; l < 4; l++) {
        ln_kernel<<<TOKS, 256>>>(x, ln_attn_g + l*DIM, xn, nullptr, nullptr, nullptr);
        tcw(xn, whi + WOFF_Q(l),  wlo + WOFF_Q(l),  nullptr, nullptr, qbuf,  TOKS, DIM,   DIM, 0);
        tcw(xn, whi + WOFF_KV(l), wlo + WOFF_KV(l), nullptr, nullptr, kvbuf, TOKS, 2*DIM, DIM, 0);
        rmsT_kernel<<<TOKS, 384>>>(qbuf,  DIM,   0,   qn_g + l*DIM, qT);
        rmsT_kernel<<<TOKS, 384>>>(kvbuf, 2*DIM, 0,   kn_g + l*DIM, kT);
        rmsTv_kernel<<<TOKS, 384>>>(kvbuf, 2*DIM, DIM, vTt);
        // scores: per-(b,h): S = qT @ kT^T (both fp32, split on the fly), masked epilogue
        mma_gemm<128><<<dim3(8, 8, BH), 256, SMB>>>(qT, (long)NTOK*DHEAD, nullptr, nullptr,
                                                    kT, (long)NTOK*DHEAD, nullptr, nullptr,
                                                    image_ids, lengths, sc, NTOK, NTOK, DHEAD, FSC);
        softmax_kernel<<<BH * NTOK, 256>>>(sc);
        // AV: per-(b,h): O = P @ V (B = vTt [64,1024] fp32), scatter epilogue
        mma_gemm<64><<<dim3(1, 8, BH), 256, SMB>>>(sc, (long)NTOK*NTOK, nullptr, nullptr,
                                                   vTt, (long)DHEAD*NTOK, nullptr, nullptr,
                                                   nullptr, nullptr, ao, NTOK, DHEAD, NTOK, FAV);
        tcw(ao, whi + WOFF_O(l), wlo + WOFF_O(l), nullptr, x, x, TOKS, DIM, DIM, FRES);
        ln_kernel<<<TOKS, 256>>>(x, ln_ff_g + l*DIM, xn, nullptr, nullptr, nullptr);
        tcw(xn,  whi + WOFF_W1(l), wlo + WOFF_W1(l), b1 + l*MLPD, nullptr, tmp, TOKS, MLPD, DIM,  FBIAS|FGELU);
        tcw(tmp, whi + WOFF_W2(l), wlo + WOFF_W2(l), b2 + l*DIM,  x,       x,   TOKS, DIM,  MLPD, FBIAS|FRES);
    }

    // ---- Final LN ----
    ln_kernel<<<TOKS, 256>>>(x, final_ln_g, xn, nullptr, nullptr, nullptr);

    // ---- Attention pooling ----
    ln_kernel<<<1, 256>>>(pool_q, pool_ln_g, sm, nullptr, nullptr, nullptr);
    small_gemm_kernel<<<dim3(3, 1), 256>>>(sm, pWq, nullptr, sm + 768, DIM, DIM);
    rms_vec_kernel<<<1, 384>>>(sm + 768, p_qn_g, sm + 1536);
    tcw(xn, whi + WOFF_PKV, wlo + WOFF_PKV, nullptr, nullptr, kvbuf, TOKS, 2*DIM, DIM, 0);
    rmsT_kernel<<<TOKS, 384>>>(kvbuf, 2*DIM, 0,   p_kn_g, kT);
    rmsT_kernel<<<TOKS, 384>>>(kvbuf, 2*DIM, DIM, nullptr, vT);
    pool_attn_kernel<<<NB*IMGS*NHEAD, 256>>>(sm + 1536, kT, vT, image_ids, lengths, pattn);
    small_gemm_kernel<<<dim3(3, 16), 256>>>(pattn, pWo, pool_q, pool, DIM, DIM);
    ln_kernel<<<16, 256>>>(pool, head_ln_g, pln, nullptr, nullptr, nullptr);
    small_gemm_kernel<<<dim3(4, 16), 256>>>(pln, W_head, nullptr, (float*)d_out, NCLS, DIM);
}

// round 4
// speedup vs baseline: 2.2460x; 1.6348x over previous
#include <cuda_runtime.h>
#include <cuda_bf16.h>
#include <math.h>
#include <float.h>
#include <stdint.h>

// ---------------------------------------------------------------------------
// Problem constants
// ---------------------------------------------------------------------------
#define NB      4
#define NTOK    1024
#define DIM     768
#define NHEAD   12
#define DHEAD   64
#define MLPD    3072
#define IMGS    4
#define NCLS    1000
#define TOKS    (NB*NTOK)
#define BH      (NB*NHEAD)

#define FBIAS 1
#define FGELU 2
#define FRES  4
#define FAV   8
#define FSC   16

// Converted-weight layout (elements, [N,K] bf16, hi and lo separate buffers)
// Q and KV are adjacent so they fuse into one N=2304 GEMM.
#define WOFF_EMB 0ULL
#define WPERL    7077888ULL
#define WOFF_L(l)   (589824ULL + (unsigned long long)(l)*WPERL)
#define WOFF_Q(l)   (WOFF_L(l) + 0ULL)
#define WOFF_KV(l)  (WOFF_L(l) + 589824ULL)
#define WOFF_O(l)   (WOFF_L(l) + 1769472ULL)
#define WOFF_W1(l)  (WOFF_L(l) + 2359296ULL)
#define WOFF_W2(l)  (WOFF_L(l) + 4718592ULL)
#define WOFF_PKV    (589824ULL + 4ULL*WPERL)
#define WTOTAL      30081024ULL

// ---------------------------------------------------------------------------
// Device scratch
// ---------------------------------------------------------------------------
__device__ float g_x   [TOKS*DIM];
__device__ float g_qkv [TOKS*2304];                // qkv fp32; also pool kv (ld 1536)
__device__ float g_sc  [50331648];                 // 48*1024*1024 scores fp32
__device__ __nv_bfloat16 g_xnh[TOKS*DIM],  g_xnl[TOKS*DIM];
__device__ __nv_bfloat16 g_tmph[TOKS*MLPD], g_tmpl[TOKS*MLPD];
__device__ __nv_bfloat16 g_qTh[BH*NTOK*DHEAD], g_qTl[BH*NTOK*DHEAD];
__device__ __nv_bfloat16 g_kTh[BH*NTOK*DHEAD], g_kTl[BH*NTOK*DHEAD];
__device__ __nv_bfloat16 g_vTth[BH*DHEAD*NTOK], g_vTtl[BH*DHEAD*NTOK];
__device__ __nv_bfloat16 g_aoh[TOKS*DIM], g_aol[TOKS*DIM];
__device__ __nv_bfloat16 g_Ph[50331648], g_Pl[50331648];
__device__ float g_kTf[BH*NTOK*DHEAD], g_vTf[BH*NTOK*DHEAD];   // pool path fp32
__device__ float g_sm  [4096];
__device__ float g_pattn[16*DIM];
__device__ float g_pool [16*DIM];
__device__ float g_pln  [16*DIM];
__device__ __nv_bfloat16 g_whi[WTOTAL];
__device__ __nv_bfloat16 g_wlo[WTOTAL];

// ---------------------------------------------------------------------------
// Helpers
// ---------------------------------------------------------------------------
__device__ __forceinline__ uint32_t smem_u32(const void* p) {
    uint32_t a;
    asm("{ .reg .u64 t; cvta.to.shared.u64 t, %1; cvt.u32.u64 %0, t; }" : "=r"(a) : "l"(p));
    return a;
}

#define LDSM4(r, addr) \
    asm volatile("ldmatrix.sync.aligned.m8n8.x4.shared.b16 {%0,%1,%2,%3}, [%4];" \
        : "=r"((r)[0]), "=r"((r)[1]), "=r"((r)[2]), "=r"((r)[3]) : "r"(addr))

#define MMA16816(d, a, b) \
    asm volatile("mma.sync.aligned.m16n8k16.row.col.f32.bf16.bf16.f32 " \
        "{%0,%1,%2,%3}, {%4,%5,%6,%7}, {%8,%9}, {%0,%1,%2,%3};" \
        : "+f"((d)[0]), "+f"((d)[1]), "+f"((d)[2]), "+f"((d)[3]) \
        : "r"((a)[0]), "r"((a)[1]), "r"((a)[2]), "r"((a)[3]), "r"((b)[0]), "r"((b)[1]))

#define CPA16(dst, src) \
    asm volatile("cp.async.cg.shared.global [%0], [%1], 16;" :: "r"(dst), "l"(src))
#define CP_COMMIT() asm volatile("cp.async.commit_group;" ::: "memory")
#define CP_WAIT0()  asm volatile("cp.async.wait_group 0;" ::: "memory")
#define CP_WAIT1()  asm volatile("cp.async.wait_group 1;" ::: "memory")

__device__ __forceinline__ void split2(float v, __nv_bfloat16& h, __nv_bfloat16& l) {
    h = __float2bfloat16(v);
    l = __float2bfloat16(v - __bfloat162float(h));
}
__device__ __forceinline__ ushort bfu(__nv_bfloat16 b) { return __bfloat16_as_ushort(b); }

// cp.async a [rows x 64] bf16 tile (row stride ldk elems) into SW128 smem
__device__ __forceinline__ void cpa_tile(uint32_t smbase, const __nv_bfloat16* __restrict__ g,
                                         int ldk, int chunks, int tid)
{
    for (int i = tid; i < chunks; i += 256) {
        int r = i >> 3, c = i & 7;
        uint32_t off = r * 128 + c * 16;
        uint32_t sw = off ^ ((off >> 3) & 0x70);
        CPA16(smbase + sw, g + (size_t)r * ldk + c * 8);
    }
}

// ---------------------------------------------------------------------------
// Weight convert+transpose: W[K,N] fp32 -> hi/lo [N,K] bf16
// ---------------------------------------------------------------------------
__global__ void wconv_kernel(const float* __restrict__ W, __nv_bfloat16* __restrict__ hi,
                             __nv_bfloat16* __restrict__ lo, int K, int N)
{
    __shared__ float t[32][33];
    int n0 = blockIdx.x * 32, k0 = blockIdx.y * 32;
    int tx = threadIdx.x, ty = threadIdx.y;      // block 32x8
#pragma unroll
    for (int r = 0; r < 4; r++)
        t[ty + r*8][tx] = W[(size_t)(k0 + ty + r*8) * N + n0 + tx];
    __syncthreads();
#pragma unroll
    for (int r = 0; r < 4; r++) {
        int n = n0 + ty + r*8, k = k0 + tx;
        float v = t[tx][ty + r*8];
        __nv_bfloat16 h, l; split2(v, h, l);
        hi[(size_t)n * K + k] = h;
        lo[(size_t)n * K + k] = l;
    }
}

// ---------------------------------------------------------------------------
// Pipelined mma.sync GEMM. A,B pre-split bf16 hi/lo: A row-major [M,K],
// B [N,K]. 3 passes AhBh + AhBl + AlBh into fp32 acc.
// CTA 128 x NT, K-tile 64, cp.async double-buffered, 8 warps (2M x 4N).
// Output: fp32 C (nullable) and/or bf16 hi/lo pair (nullable).
// ---------------------------------------------------------------------------
template<int NT>
__global__ void __launch_bounds__(256, 1) mma_gemm(
    const __nv_bfloat16* __restrict__ Ahi, const __nv_bfloat16* __restrict__ Alo, long sA,
    const __nv_bfloat16* __restrict__ Bhi, const __nv_bfloat16* __restrict__ Blo, long sB,
    const float* __restrict__ bias, const float* __restrict__ res,
    const int* __restrict__ image_ids, const int* __restrict__ lengths,
    float* __restrict__ C, __nv_bfloat16* __restrict__ Chi, __nv_bfloat16* __restrict__ Clo,
    int M, int N, int K, int flags)
{
    constexpr int NX4    = (NT == 128) ? 2 : 1;
    constexpr int NTILES = 2 * NX4;
    constexpr int NW     = NT / 4;
    constexpr int BS     = NT * 128;                 // bytes per B buffer
    constexpr int STG    = 32768 + 2 * BS;           // stage size

    extern __shared__ char smem[];
    uint32_t uS = smem_u32(smem);

    const int tid = threadIdx.x;
    const int wid = tid >> 5, lane = tid & 31;
    const int z = blockIdx.z;
    const int m0 = blockIdx.y * 128, n0 = blockIdx.x * NT;
    const int wm = wid & 1, wn = wid >> 1;

    const __nv_bfloat16* Azh = Ahi + (size_t)z * sA + (size_t)m0 * K;
    const __nv_bfloat16* Azl = Alo + (size_t)z * sA + (size_t)m0 * K;
    const __nv_bfloat16* Bzh = Bhi + (size_t)z * sB + (size_t)n0 * K;
    const __nv_bfloat16* Bzl = Blo + (size_t)z * sB + (size_t)n0 * K;

    float acc[4][NTILES][4] = {};

    const int a_row = wm * 64 + (lane & 15);
    const int a_cb  = (lane >> 4) * 16;
    const int b_row = wn * NW + (lane & 7) + ((lane >> 4) << 3);
    const int b_cb  = ((lane >> 3) & 1) * 16;

    const int KT = K >> 6;

    // preload stage 0
    {
        uint32_t base = uS;
        cpa_tile(base,             Azh, K, 1024,   tid);
        cpa_tile(base + 16384,     Azl, K, 1024,   tid);
        cpa_tile(base + 32768,     Bzh, K, NT * 8, tid);
        cpa_tile(base + 32768 + BS, Bzl, K, NT * 8, tid);
        CP_COMMIT();
    }

    for (int kt = 0; kt < KT; kt++) {
        if (kt + 1 < KT) {
            uint32_t base = uS + ((kt + 1) & 1) * STG;
            cpa_tile(base,              Azh + (kt + 1) * 64, K, 1024,   tid);
            cpa_tile(base + 16384,      Azl + (kt + 1) * 64, K, 1024,   tid);
            cpa_tile(base + 32768,      Bzh + (kt + 1) * 64, K, NT * 8, tid);
            cpa_tile(base + 32768 + BS, Bzl + (kt + 1) * 64, K, NT * 8, tid);
            CP_COMMIT();
            CP_WAIT1();
        } else {
            CP_WAIT0();
        }
        __syncthreads();

        uint32_t bAh = uS + (kt & 1) * STG;
        uint32_t bAl = bAh + 16384;
        uint32_t bBh = bAh + 32768;
        uint32_t bBl = bBh + BS;

#pragma unroll
        for (int ks = 0; ks < 4; ks++) {
            uint32_t ah[4][4], al[4][4], bh[NX4][4], bl[NX4][4];
#pragma unroll
            for (int mt = 0; mt < 4; mt++) {
                int row = a_row + mt * 16;
                uint32_t off = row * 128 + ((a_cb + ks * 32) ^ ((row & 7) << 4));
                LDSM4(ah[mt], bAh + off);
                LDSM4(al[mt], bAl + off);
            }
#pragma unroll
            for (int q = 0; q < NX4; q++) {
                int row = b_row + q * 16;
                uint32_t off = row * 128 + ((b_cb + ks * 32) ^ ((row & 7) << 4));
                LDSM4(bh[q], bBh + off);
                LDSM4(bl[q], bBl + off);
            }
#pragma unroll
            for (int mt = 0; mt < 4; mt++)
#pragma unroll
                for (int nt = 0; nt < NTILES; nt++)
                    MMA16816(acc[mt][nt], ah[mt], &bh[nt >> 1][(nt & 1) * 2]);
#pragma unroll
            for (int mt = 0; mt < 4; mt++)
#pragma unroll
                for (int nt = 0; nt < NTILES; nt++)
                    MMA16816(acc[mt][nt], ah[mt], &bl[nt >> 1][(nt & 1) * 2]);
#pragma unroll
            for (int mt = 0; mt < 4; mt++)
#pragma unroll
                for (int nt = 0; nt < NTILES; nt++)
                    MMA16816(acc[mt][nt], al[mt], &bh[nt >> 1][(nt & 1) * 2]);
        }
        __syncthreads();
    }

    // ---- epilogue ----
    int b_ = 0;
    long cbase; int ldc;
    if (flags & FAV)      { b_ = z / 12; int h_ = z % 12; cbase = (long)b_ * NTOK * DIM + h_ * 64; ldc = DIM; }
    else if (flags & FSC) { b_ = z / 12; cbase = (long)z * NTOK * NTOK; ldc = N; }
    else                  { cbase = 0; ldc = N; }
    int len = (flags & FSC) ? lengths[b_] : 0;

    const int rbase = m0 + wm * 64;
#pragma unroll
    for (int mt = 0; mt < 4; mt++) {
#pragma unroll
        for (int nt = 0; nt < NTILES; nt++) {
            int c = n0 + wn * NW + nt * 8 + (lane & 3) * 2;
            float bv0 = 0.f, bv1 = 0.f;
            if (flags & FBIAS) { bv0 = bias[c]; bv1 = bias[c + 1]; }
            int jm0 = 0, jm1 = 0;
            if (flags & FSC) {
                jm0 = image_ids[b_ * NTOK + c];
                jm1 = image_ids[b_ * NTOK + c + 1];
            }
#pragma unroll
            for (int half = 0; half < 2; half++) {
                int r = rbase + mt * 16 + (lane >> 2) + half * 8;
                float v0 = acc[mt][nt][half * 2 + 0];
                float v1 = acc[mt][nt][half * 2 + 1];
                if (flags & FBIAS) { v0 += bv0; v1 += bv1; }
                if (flags & FGELU) {
                    v0 = 0.5f * v0 * (1.f + erff(v0 * 0.70710678118654752f));
                    v1 = 0.5f * v1 * (1.f + erff(v1 * 0.70710678118654752f));
                }
                long idx = cbase + (long)r * ldc + ((flags & FAV) ? (c - n0) : c);
                if (flags & FRES) { v0 += res[idx]; v1 += res[idx + 1]; }
                if (flags & FSC) {
                    int ii = image_ids[b_ * NTOK + r];
                    v0 = (ii == jm0 && c     < len) ? v0 : -FLT_MAX;
                    v1 = (ii == jm1 && c + 1 < len) ? v1 : -FLT_MAX;
                }
                if (C) *(float2*)(C + idx) = make_float2(v0, v1);
                if (Chi) {
                    __nv_bfloat16 h0, l0, h1, l1;
                    split2(v0, h0, l0); split2(v1, h1, l1);
                    ushort2 hh; hh.x = bfu(h0); hh.y = bfu(h1);
                    ushort2 ll; ll.x = bfu(l0); ll.y = bfu(l1);
                    *(ushort2*)(Chi + idx) = hh;
                    *(ushort2*)(Clo + idx) = ll;
                }
            }
        }
    }
}

// ---------------------------------------------------------------------------
// LayerNorm over width 768. Outputs: fp32 (nullable) and/or bf16 hi/lo pair.
// Optional pos-embed add (fp32 path).
// ---------------------------------------------------------------------------
__global__ void ln_kernel(const float* __restrict__ in, const float* __restrict__ g,
                          float* __restrict__ outf,
                          __nv_bfloat16* __restrict__ outhi, __nv_bfloat16* __restrict__ outlo,
                          const float* __restrict__ pos_h, const float* __restrict__ pos_w,
                          const int* __restrict__ ppos)
{
    int row = blockIdx.x;
    int tid = threadIdx.x;
    const float* xr = in + (size_t)row * 768;
    float v[3]; float s = 0.f, q = 0.f;
#pragma unroll
    for (int i = 0; i < 3; i++) { float t = xr[tid + i*256]; v[i] = t; s += t; q += t*t; }
#pragma unroll
    for (int o = 16; o; o >>= 1) {
        s += __shfl_xor_sync(0xffffffffu, s, o);
        q += __shfl_xor_sync(0xffffffffu, q, o);
    }
    __shared__ float shs[8], shq[8], st[2];
    int w = tid >> 5;
    if ((tid & 31) == 0) { shs[w] = s; shq[w] = q; }
    __syncthreads();
    if (tid == 0) {
        float S = 0.f, Q = 0.f;
#pragma unroll
        for (int i = 0; i < 8; i++) { S += shs[i]; Q += shq[i]; }
        float mu = S * (1.f/768.f);
        st[0] = mu;
        st[1] = rsqrtf(Q * (1.f/768.f) - mu*mu + 1e-5f);
    }
    __syncthreads();
    float mu = st[0], rs = st[1];
    int p0 = 0, p1 = 0;
    if (ppos) { p0 = ppos[row*2]; p1 = ppos[row*2 + 1]; }
#pragma unroll
    for (int i = 0; i < 3; i++) {
        int c = tid + i*256;
        float y = (v[i] - mu) * rs * g[c];
        if (ppos) y += pos_h[p0*768 + c] + pos_w[p1*768 + c];
        size_t idx = (size_t)row*768 + c;
        if (outf) outf[idx] = y;
        if (outhi) {
            __nv_bfloat16 h, l; split2(y, h, l);
            outhi[idx] = h; outlo[idx] = l;
        }
    }
}

// ---------------------------------------------------------------------------
// QK-RMSNorm + transpose -> [z][n][64], bf16 hi/lo output.
// ---------------------------------------------------------------------------
__global__ void rmsT_split(const float* __restrict__ in, int ld, int off,
                           const float* __restrict__ g,
                           __nv_bfloat16* __restrict__ oh, __nv_bfloat16* __restrict__ ol)
{
    int token = blockIdx.x;
    int b = token >> 10, n = token & 1023;
    int w = threadIdx.x >> 5, lane = threadIdx.x & 31;
    const float* src = in + (size_t)token * ld + off + w*64;
    float v0 = src[lane], v1 = src[lane + 32];
    float ss = v0*v0 + v1*v1;
#pragma unroll
    for (int o = 16; o; o >>= 1) ss += __shfl_xor_sync(0xffffffffu, ss, o);
    float inv = 8.0f / fmaxf(sqrtf(ss), 1e-12f);
    v0 *= inv * g[w*64 + lane];
    v1 *= inv * g[w*64 + lane + 32];
    size_t dst = ((size_t)(b*12 + w) * 1024 + n) * 64;
    __nv_bfloat16 h, l;
    split2(v0, h, l); oh[dst + lane] = h;      ol[dst + lane] = l;
    split2(v1, h, l); oh[dst + lane + 32] = h; ol[dst + lane + 32] = l;
}

// V transpose to [z][d][n] bf16 hi/lo for the AV GEMM B operand.
__global__ void rmsTv_split(const float* __restrict__ in, int ld, int off,
                            __nv_bfloat16* __restrict__ oh, __nv_bfloat16* __restrict__ ol)
{
    int token = blockIdx.x;
    int b = token >> 10, n = token & 1023;
    int w = threadIdx.x >> 5, lane = threadIdx.x & 31;
    const float* src = in + (size_t)token * ld + off + w*64;
    float v0 = src[lane], v1 = src[lane + 32];
    size_t base = ((size_t)(b*12 + w) * 64) * 1024 + n;
    __nv_bfloat16 h, l;
    split2(v0, h, l); oh[base + (size_t)lane * 1024] = h;        ol[base + (size_t)lane * 1024] = l;
    split2(v1, h, l); oh[base + (size_t)(lane + 32) * 1024] = h; ol[base + (size_t)(lane + 32) * 1024] = l;
}

// fp32 transpose variant for the pool path. g==nullptr: plain copy.
__global__ void rmsT_f32(const float* __restrict__ in, int ld, int off,
                         const float* __restrict__ g, float* __restrict__ outT)
{
    int token = blockIdx.x;
    int b = token >> 10, n = token & 1023;
    int w = threadIdx.x >> 5, lane = threadIdx.x & 31;
    const float* src = in + (size_t)token * ld + off + w*64;
    float v0 = src[lane], v1 = src[lane + 32];
    if (g) {
        float ss = v0*v0 + v1*v1;
#pragma unroll
        for (int o = 16; o; o >>= 1) ss += __shfl_xor_sync(0xffffffffu, ss, o);
        float inv = 8.0f / fmaxf(sqrtf(ss), 1e-12f);
        v0 *= inv * g[w*64 + lane];
        v1 *= inv * g[w*64 + lane + 32];
    }
    float* dst = outT + ((size_t)(b*12 + w) * 1024 + n) * 64;
    dst[lane] = v0; dst[lane + 32] = v1;
}

// ---------------------------------------------------------------------------
// Row softmax over 1024 cols; writes P as bf16 hi/lo.
// ---------------------------------------------------------------------------
__global__ void softmax_kernel(const float* __restrict__ S,
                               __nv_bfloat16* __restrict__ Phi, __nv_bfloat16* __restrict__ Plo)
{
    size_t row = blockIdx.x;
    const float4* p = reinterpret_cast<const float4*>(S + row * 1024);
    int tid = threadIdx.x;
    float4 v = p[tid];
    float m = fmaxf(fmaxf(v.x, v.y), fmaxf(v.z, v.w));
#pragma unroll
    for (int o = 16; o; o >>= 1) m = fmaxf(m, __shfl_xor_sync(0xffffffffu, m, o));
    __shared__ float sh[8]; __shared__ float bs[2];
    int w = tid >> 5;
    if ((tid & 31) == 0) sh[w] = m;
    __syncthreads();
    if (tid == 0) { float mm = sh[0]; for (int i = 1; i < 8; i++) mm = fmaxf(mm, sh[i]); bs[0] = mm; }
    __syncthreads();
    m = bs[0];
    float e0 = __expf(v.x - m), e1 = __expf(v.y - m), e2 = __expf(v.z - m), e3 = __expf(v.w - m);
    float s = e0 + e1 + e2 + e3;
#pragma unroll
    for (int o = 16; o; o >>= 1) s += __shfl_xor_sync(0xffffffffu, s, o);
    if ((tid & 31) == 0) sh[w] = s;
    __syncthreads();
    if (tid == 0) { float ss = 0.f; for (int i = 0; i < 8; i++) ss += sh[i]; bs[1] = 1.f / ss; }
    __syncthreads();
    float inv = bs[1];
    float r0 = e0*inv, r1 = e1*inv, r2 = e2*inv, r3 = e3*inv;
    __nv_bfloat16 h0,l0,h1,l1,h2,l2,h3,l3;
    split2(r0,h0,l0); split2(r1,h1,l1); split2(r2,h2,l2); split2(r3,h3,l3);
    uint2 hw, lw;
    hw.x = (uint32_t)bfu(h0) | ((uint32_t)bfu(h1) << 16);
    hw.y = (uint32_t)bfu(h2) | ((uint32_t)bfu(h3) << 16);
    lw.x = (uint32_t)bfu(l0) | ((uint32_t)bfu(l1) << 16);
    lw.y = (uint32_t)bfu(l2) | ((uint32_t)bfu(l3) << 16);
    *(uint2*)(Phi + row * 1024 + tid * 4) = hw;
    *(uint2*)(Plo + row * 1024 + tid * 4) = lw;
}

// ---------------------------------------------------------------------------
// Attention pooling (192 blocks = b*img*h), fp32 path.
// ---------------------------------------------------------------------------
__global__ void pool_attn_kernel(const float* __restrict__ pqn, const float* __restrict__ kT,
                                 const float* __restrict__ vT, const int* __restrict__ image_ids,
                                 const int* __restrict__ lengths, float* __restrict__ out)
{
    int idx = blockIdx.x;
    int h = idx % 12, img = (idx / 12) % 4, b = idx / 48;
    int tid = threadIdx.x;
    __shared__ float q[64];
    __shared__ float p[1024];
    __shared__ float sh[8];
    __shared__ float bs[2];
    __shared__ float sred[256];
    if (tid < 64) q[tid] = pqn[h*64 + tid];
    __syncthreads();

    const float* K = kT + (size_t)(b*12 + h) * 1024 * 64;
    int len = lengths[b];
    float loc[4]; float mx = -FLT_MAX;
#pragma unroll
    for (int t = 0; t < 4; t++) {
        int j = tid + t*256;
        const float* kr = K + (size_t)j * 64;
        float dot = 0.f;
#pragma unroll
        for (int d = 0; d < 64; d++) dot += q[d] * kr[d];
        bool ok = (image_ids[b*1024 + j] == img) && (j < len);
        loc[t] = ok ? dot : -FLT_MAX;
        mx = fmaxf(mx, loc[t]);
    }
#pragma unroll
    for (int o = 16; o; o >>= 1) mx = fmaxf(mx, __shfl_xor_sync(0xffffffffu, mx, o));
    int w = tid >> 5;
    if ((tid & 31) == 0) sh[w] = mx;
    __syncthreads();
    if (tid == 0) { float mm = sh[0]; for (int i = 1; i < 8; i++) mm = fmaxf(mm, sh[i]); bs[0] = mm; }
    __syncthreads();
    mx = bs[0];
    float s = 0.f;
#pragma unroll
    for (int t = 0; t < 4; t++) {
        float e = __expf(loc[t] - mx);
        p[tid + t*256] = e;
        s += e;
    }
#pragma unroll
    for (int o = 16; o; o >>= 1) s += __shfl_xor_sync(0xffffffffu, s, o);
    if ((tid & 31) == 0) sh[w] = s;
    __syncthreads();
    if (tid == 0) { float ss = 0.f; for (int i = 0; i < 8; i++) ss += sh[i]; bs[1] = 1.f / ss; }
    __syncthreads();
    float inv = bs[1];

    const float* V = vT + (size_t)(b*12 + h) * 1024 * 64;
    int d = tid & 63, grp = tid >> 6;
    float acc = 0.f;
    for (int j = grp; j < 1024; j += 4) acc += p[j] * V[(size_t)j*64 + d];
    sred[tid] = acc;
    __syncthreads();
    if (grp == 0) {
        float r = (sred[d] + sred[d + 64]) + (sred[d + 128] + sred[d + 192]);
        out[(size_t)(b*4 + img) * 768 + h*64 + d] = r * inv;
    }
}

__global__ void rms_vec_kernel(const float* __restrict__ in, const float* __restrict__ g,
                               float* __restrict__ out)
{
    int w = threadIdx.x >> 5, lane = threadIdx.x & 31;
    float v0 = in[w*64 + lane], v1 = in[w*64 + lane + 32];
    float ss = v0*v0 + v1*v1;
#pragma unroll
    for (int o = 16; o; o >>= 1) ss += __shfl_xor_sync(0xffffffffu, ss, o);
    float inv = 8.0f / fmaxf(sqrtf(ss), 1e-12f);
    out[w*64 + lane]      = v0 * inv * g[w*64 + lane];
    out[w*64 + lane + 32] = v1 * inv * g[w*64 + lane + 32];
}

__global__ void small_gemm_kernel(const float* __restrict__ A, const float* __restrict__ W,
                                  const float* __restrict__ addvec, float* __restrict__ C,
                                  int N, int K)
{
    __shared__ float a[768];
    int row = blockIdx.y;
    for (int i = threadIdx.x; i < K; i += 256) a[i] = A[(size_t)row*K + i];
    __syncthreads();
    int n = blockIdx.x * 256 + threadIdx.x;
    if (n >= N) return;
    float acc = addvec ? addvec[n] : 0.f;
#pragma unroll 4
    for (int k = 0; k < K; k++) acc += a[k] * W[(size_t)k*N + n];
    C[(size_t)row*N + n] = acc;
}

// ---------------------------------------------------------------------------
// Host side
// ---------------------------------------------------------------------------
extern "C" void kernel_launch(void* const* d_in, const int* in_sizes, int n_in,
                              void* d_out, int out_size)
{
    (void)in_sizes; (void)n_in; (void)out_size;
    const float* patches    = (const float*)d_in[0];
    const int*   ppos       = (const int*)  d_in[1];
    const int*   image_ids  = (const int*)  d_in[2];
    const int*   lengths    = (const int*)  d_in[3];
    const float* emb_ln_g   = (const float*)d_in[4];
    const float* W_emb      = (const float*)d_in[5];
    const float* b_emb      = (const float*)d_in[6];
    const float* emb_ln2_g  = (const float*)d_in[7];
    const float* pos_h      = (const float*)d_in[8];
    const float* pos_w      = (const float*)d_in[9];
    const float* ln_attn_g  = (const float*)d_in[10];
    const float* Wq         = (const float*)d_in[11];
    const float* Wkv        = (const float*)d_in[12];
    const float* qn_g       = (const float*)d_in[13];
    const float* kn_g       = (const float*)d_in[14];
    const float* Wo         = (const float*)d_in[15];
    const float* ln_ff_g    = (const float*)d_in[16];
    const float* W1         = (const float*)d_in[17];
    const float* b1         = (const float*)d_in[18];
    const float* W2         = (const float*)d_in[19];
    const float* b2         = (const float*)d_in[20];
    const float* final_ln_g = (const float*)d_in[21];
    const float* pool_q     = (const float*)d_in[22];
    const float* pool_ln_g  = (const float*)d_in[23];
    const float* pWq        = (const float*)d_in[24];
    const float* pWkv       = (const float*)d_in[25];
    const float* p_qn_g     = (const float*)d_in[26];
    const float* p_kn_g     = (const float*)d_in[27];
    const float* pWo        = (const float*)d_in[28];
    const float* head_ln_g  = (const float*)d_in[29];
    const float* W_head     = (const float*)d_in[30];

    float *x, *qkv, *sc, *kTf, *vTf, *sm, *pattn, *pool, *pln;
    __nv_bfloat16 *xnh, *xnl, *tmph, *tmpl, *qTh, *qTl, *kTh, *kTl, *vTth, *vTtl;
    __nv_bfloat16 *aoh, *aol, *Ph, *Pl, *whi, *wlo;
    cudaGetSymbolAddress((void**)&x,    g_x);
    cudaGetSymbolAddress((void**)&qkv,  g_qkv);
    cudaGetSymbolAddress((void**)&sc,   g_sc);
    cudaGetSymbolAddress((void**)&kTf,  g_kTf);
    cudaGetSymbolAddress((void**)&vTf,  g_vTf);
    cudaGetSymbolAddress((void**)&sm,   g_sm);
    cudaGetSymbolAddress((void**)&pattn,g_pattn);
    cudaGetSymbolAddress((void**)&pool, g_pool);
    cudaGetSymbolAddress((void**)&pln,  g_pln);
    cudaGetSymbolAddress((void**)&xnh,  g_xnh);
    cudaGetSymbolAddress((void**)&xnl,  g_xnl);
    cudaGetSymbolAddress((void**)&tmph, g_tmph);
    cudaGetSymbolAddress((void**)&tmpl, g_tmpl);
    cudaGetSymbolAddress((void**)&qTh,  g_qTh);
    cudaGetSymbolAddress((void**)&qTl,  g_qTl);
    cudaGetSymbolAddress((void**)&kTh,  g_kTh);
    cudaGetSymbolAddress((void**)&kTl,  g_kTl);
    cudaGetSymbolAddress((void**)&vTth, g_vTth);
    cudaGetSymbolAddress((void**)&vTtl, g_vTtl);
    cudaGetSymbolAddress((void**)&aoh,  g_aoh);
    cudaGetSymbolAddress((void**)&aol,  g_aol);
    cudaGetSymbolAddress((void**)&Ph,   g_Ph);
    cudaGetSymbolAddress((void**)&Pl,   g_Pl);
    cudaGetSymbolAddress((void**)&whi,  g_whi);
    cudaGetSymbolAddress((void**)&wlo,  g_wlo);

    constexpr int SMEM128 = 32768*2 + 2*2*128*128;   // 131072
    constexpr int SMEM64  = 32768*2 + 2*2*64*128;    // 98304
    cudaFuncSetAttribute(mma_gemm<128>, cudaFuncAttributeMaxDynamicSharedMemorySize, SMEM128);
    cudaFuncSetAttribute(mma_gemm<64>,  cudaFuncAttributeMaxDynamicSharedMemorySize, SMEM64);

    // ---- Convert + transpose all weights to bf16 hi/lo [N,K] ----
    dim3 wb(32, 8);
    wconv_kernel<<<dim3(DIM/32,  DIM/32),  wb>>>(W_emb, whi + WOFF_EMB, wlo + WOFF_EMB, DIM, DIM);
    for (int l = 0; l < 4; l++) {
        wconv_kernel<<<dim3(DIM/32,    DIM/32),  wb>>>(Wq  + (size_t)l*DIM*DIM,    whi + WOFF_Q(l),  wlo + WOFF_Q(l),  DIM,  DIM);
        wconv_kernel<<<dim3(2*DIM/32,  DIM/32),  wb>>>(Wkv + (size_t)l*DIM*2*DIM,  whi + WOFF_KV(l), wlo + WOFF_KV(l), DIM,  2*DIM);
        wconv_kernel<<<dim3(DIM/32,    DIM/32),  wb>>>(Wo  + (size_t)l*DIM*DIM,    whi + WOFF_O(l),  wlo + WOFF_O(l),  DIM,  DIM);
        wconv_kernel<<<dim3(MLPD/32,   DIM/32),  wb>>>(W1  + (size_t)l*DIM*MLPD,   whi + WOFF_W1(l), wlo + WOFF_W1(l), DIM,  MLPD);
        wconv_kernel<<<dim3(DIM/32,    MLPD/32), wb>>>(W2  + (size_t)l*MLPD*DIM,   whi + WOFF_W2(l), wlo + WOFF_W2(l), MLPD, DIM);
    }
    wconv_kernel<<<dim3(2*DIM/32, DIM/32), wb>>>(pWkv, whi + WOFF_PKV, wlo + WOFF_PKV, DIM, 2*DIM);

    // helper: weight GEMM with A = xn-like hi/lo pair
    auto G = [&](const __nv_bfloat16* ah, const __nv_bfloat16* al,
                 const __nv_bfloat16* bh, const __nv_bfloat16* bl,
                 const float* bias, const float* res,
                 float* C, __nv_bfloat16* Chi, __nv_bfloat16* Clo,
                 int M, int N, int K, int flags) {
        dim3 g(N/128, M/128, 1);
        mma_gemm<128><<<g, 256, SMEM128>>>(ah, al, 0, bh, bl, 0, bias, res, nullptr, nullptr,
                                           C, Chi, Clo, M, N, K, flags);
    };

    // ---- Embedding ----
    ln_kernel<<<TOKS, 256>>>(patches, emb_ln_g, nullptr, xnh, xnl, nullptr, nullptr, nullptr);
    G(xnh, xnl, whi + WOFF_EMB, wlo + WOFF_EMB, b_emb, nullptr, x, nullptr, nullptr, TOKS, DIM, DIM, FBIAS);
    ln_kernel<<<TOKS, 256>>>(x, emb_ln2_g, x, nullptr, nullptr, pos_h, pos_w, ppos);

    // ---- Transformer layers ----
    for (int l = 0; l < 4; l++) {
        ln_kernel<<<TOKS, 256>>>(x, ln_attn_g + l*DIM, nullptr, xnh, xnl, nullptr, nullptr, nullptr);
        // fused QKV: N = 2304 (Q|KV weights adjacent)
        G(xnh, xnl, whi + WOFF_Q(l), wlo + WOFF_Q(l), nullptr, nullptr, qkv, nullptr, nullptr,
          TOKS, 2304, DIM, 0);
        rmsT_split<<<TOKS, 384>>>(qkv, 2304, 0,    qn_g + l*DIM, qTh, qTl);
        rmsT_split<<<TOKS, 384>>>(qkv, 2304, 768,  kn_g + l*DIM, kTh, kTl);
        rmsTv_split<<<TOKS, 384>>>(qkv, 2304, 1536, vTth, vTtl);
        // scores: per-(b,h): S = q @ k^T, masked epilogue
        mma_gemm<128><<<dim3(8, 8, BH), 256, SMEM128>>>(
            qTh, qTl, (long)NTOK*DHEAD, kTh, kTl, (long)NTOK*DHEAD,
            nullptr, nullptr, image_ids, lengths, sc, nullptr, nullptr,
            NTOK, NTOK, DHEAD, FSC);
        softmax_kernel<<<BH * NTOK, 256>>>(sc, Ph, Pl);
        // AV: per-(b,h): O = P @ V^T (V stored [64,1024]), scatter epilogue -> ao hi/lo
        mma_gemm<64><<<dim3(1, 8, BH), 256, SMEM64>>>(
            Ph, Pl, (long)NTOK*NTOK, vTth, vTtl, (long)DHEAD*NTOK,
            nullptr, nullptr, nullptr, nullptr, nullptr, aoh, aol,
            NTOK, DHEAD, NTOK, FAV);
        G(aoh, aol, whi + WOFF_O(l), wlo + WOFF_O(l), nullptr, x, x, nullptr, nullptr,
          TOKS, DIM, DIM, FRES);
        ln_kernel<<<TOKS, 256>>>(x, ln_ff_g + l*DIM, nullptr, xnh, xnl, nullptr, nullptr, nullptr);
        G(xnh, xnl, whi + WOFF_W1(l), wlo + WOFF_W1(l), b1 + l*MLPD, nullptr,
          nullptr, tmph, tmpl, TOKS, MLPD, DIM, FBIAS|FGELU);
        G(tmph, tmpl, whi + WOFF_W2(l), wlo + WOFF_W2(l), b2 + l*DIM, x,
          x, nullptr, nullptr, TOKS, DIM, MLPD, FBIAS|FRES);
    }

    // ---- Final LN ----
    ln_kernel<<<TOKS, 256>>>(x, final_ln_g, nullptr, xnh, xnl, nullptr, nullptr, nullptr);

    // ---- Attention pooling (fp32 path, tiny) ----
    ln_kernel<<<1, 256>>>(pool_q, pool_ln_g, sm, nullptr, nullptr, nullptr, nullptr, nullptr);
    small_gemm_kernel<<<dim3(3, 1), 256>>>(sm, pWq, nullptr, sm + 768, DIM, DIM);
    rms_vec_kernel<<<1, 384>>>(sm + 768, p_qn_g, sm + 1536);
    G(xnh, xnl, whi + WOFF_PKV, wlo + WOFF_PKV, nullptr, nullptr, qkv, nullptr, nullptr,
      TOKS, 1536, DIM, 0);
    rmsT_f32<<<TOKS, 384>>>(qkv, 1536, 0,   p_kn_g, kTf);
    rmsT_f32<<<TOKS, 384>>>(qkv, 1536, 768, nullptr, vTf);
    pool_attn_kernel<<<NB*IMGS*NHEAD, 256>>>(sm + 1536, kTf, vTf, image_ids, lengths, pattn);
    small_gemm_kernel<<<dim3(3, 16), 256>>>(pattn, pWo, pool_q, pool, DIM, DIM);
    ln_kernel<<<16, 256>>>(pool, head_ln_g, pln, nullptr, nullptr, nullptr, nullptr, nullptr);
    small_gemm_kernel<<<dim3(4, 16), 256>>>(pln, W_head, nullptr, (float*)d_out, NCLS, DIM);
}

// round 5
// speedup vs baseline: 2.7306x; 1.2157x over previous
#include <cuda_runtime.h>
#include <cuda_bf16.h>
#include <math.h>
#include <float.h>
#include <stdint.h>

// ---------------------------------------------------------------------------
// Problem constants
// ---------------------------------------------------------------------------
#define NB      4
#define NTOK    1024
#define DIM     768
#define NHEAD   12
#define DHEAD   64
#define MLPD    3072
#define IMGS    4
#define NCLS    1000
#define TOKS    (NB*NTOK)
#define BH      (NB*NHEAD)

#define FBIAS 1
#define FGELU 2
#define FRES  4

// Converted-weight layout (elements, [N,K] bf16, hi and lo separate buffers)
#define WOFF_EMB 0ULL
#define WPERL    7077888ULL
#define WOFF_L(l)   (589824ULL + (unsigned long long)(l)*WPERL)
#define WOFF_Q(l)   (WOFF_L(l) + 0ULL)
#define WOFF_O(l)   (WOFF_L(l) + 1769472ULL)
#define WOFF_W1(l)  (WOFF_L(l) + 2359296ULL)
#define WOFF_W2(l)  (WOFF_L(l) + 4718592ULL)
#define WOFF_PKV    (589824ULL + 4ULL*WPERL)
#define WTOTAL      30081024ULL

// ---------------------------------------------------------------------------
// Device scratch
// ---------------------------------------------------------------------------
__device__ float g_x   [TOKS*DIM];
__device__ float g_qkv [TOKS*2304];
__device__ __nv_bfloat16 g_xnh[TOKS*DIM],  g_xnl[TOKS*DIM];
__device__ __nv_bfloat16 g_tmph[TOKS*MLPD], g_tmpl[TOKS*MLPD];
__device__ __nv_bfloat16 g_qTh[BH*NTOK*DHEAD], g_qTl[BH*NTOK*DHEAD];
__device__ __nv_bfloat16 g_kTh[BH*NTOK*DHEAD], g_kTl[BH*NTOK*DHEAD];
__device__ __nv_bfloat16 g_vTth[BH*DHEAD*NTOK], g_vTtl[BH*DHEAD*NTOK];
__device__ __nv_bfloat16 g_aoh[TOKS*DIM], g_aol[TOKS*DIM];
__device__ float g_kTf[BH*NTOK*DHEAD], g_vTf[BH*NTOK*DHEAD];
__device__ float g_sm  [4096];
__device__ float g_pattn[16*DIM];
__device__ float g_pool [16*DIM];
__device__ float g_pln  [16*DIM];
__device__ __nv_bfloat16 g_whi[WTOTAL];
__device__ __nv_bfloat16 g_wlo[WTOTAL];

// ---------------------------------------------------------------------------
// Helpers
// ---------------------------------------------------------------------------
__device__ __forceinline__ uint32_t smem_u32(const void* p) {
    uint32_t a;
    asm("{ .reg .u64 t; cvta.to.shared.u64 t, %1; cvt.u32.u64 %0, t; }" : "=r"(a) : "l"(p));
    return a;
}

#define LDSM4(r, addr) \
    asm volatile("ldmatrix.sync.aligned.m8n8.x4.shared.b16 {%0,%1,%2,%3}, [%4];" \
        : "=r"((r)[0]), "=r"((r)[1]), "=r"((r)[2]), "=r"((r)[3]) : "r"(addr))

#define MMA16816(d, a, b) \
    asm volatile("mma.sync.aligned.m16n8k16.row.col.f32.bf16.bf16.f32 " \
        "{%0,%1,%2,%3}, {%4,%5,%6,%7}, {%8,%9}, {%0,%1,%2,%3};" \
        : "+f"((d)[0]), "+f"((d)[1]), "+f"((d)[2]), "+f"((d)[3]) \
        : "r"((a)[0]), "r"((a)[1]), "r"((a)[2]), "r"((a)[3]), "r"((b)[0]), "r"((b)[1]))

#define CPA16(dst, src) \
    asm volatile("cp.async.cg.shared.global [%0], [%1], 16;" :: "r"(dst), "l"(src))
#define CP_COMMIT() asm volatile("cp.async.commit_group;" ::: "memory")
#define CP_WAIT0()  asm volatile("cp.async.wait_group 0;" ::: "memory")
#define CP_WAIT1()  asm volatile("cp.async.wait_group 1;" ::: "memory")

__device__ __forceinline__ void split2(float v, __nv_bfloat16& h, __nv_bfloat16& l) {
    h = __float2bfloat16(v);
    l = __float2bfloat16(v - __bfloat162float(h));
}
__device__ __forceinline__ uint32_t bfu(__nv_bfloat16 b) { return (uint32_t)__bfloat16_as_ushort(b); }

__device__ __forceinline__ void cpa_tile(uint32_t smbase, const __nv_bfloat16* __restrict__ g,
                                         int ldk, int chunks, int tid)
{
    for (int i = tid; i < chunks; i += 256) {
        int r = i >> 3, c = i & 7;
        uint32_t off = r * 128 + c * 16;
        uint32_t sw = off ^ ((off >> 3) & 0x70);
        CPA16(smbase + sw, g + (size_t)r * ldk + c * 8);
    }
}

// ---------------------------------------------------------------------------
// Weight convert+transpose: W[K,N] fp32 -> hi/lo [N,K] bf16
// ---------------------------------------------------------------------------
__global__ void wconv_kernel(const float* __restrict__ W, __nv_bfloat16* __restrict__ hi,
                             __nv_bfloat16* __restrict__ lo, int K, int N)
{
    __shared__ float t[32][33];
    int n0 = blockIdx.x * 32, k0 = blockIdx.y * 32;
    int tx = threadIdx.x, ty = threadIdx.y;
#pragma unroll
    for (int r = 0; r < 4; r++)
        t[ty + r*8][tx] = W[(size_t)(k0 + ty + r*8) * N + n0 + tx];
    __syncthreads();
#pragma unroll
    for (int r = 0; r < 4; r++) {
        int n = n0 + ty + r*8, k = k0 + tx;
        float v = t[tx][ty + r*8];
        __nv_bfloat16 h, l; split2(v, h, l);
        hi[(size_t)n * K + k] = h;
        lo[(size_t)n * K + k] = l;
    }
}

// ---------------------------------------------------------------------------
// Pipelined mma.sync GEMM (dense weight GEMMs only now).
// ---------------------------------------------------------------------------
__global__ void __launch_bounds__(256, 1) mma_gemm(
    const __nv_bfloat16* __restrict__ Ahi, const __nv_bfloat16* __restrict__ Alo,
    const __nv_bfloat16* __restrict__ Bhi, const __nv_bfloat16* __restrict__ Blo,
    const float* __restrict__ bias, const float* __restrict__ res,
    float* __restrict__ C, __nv_bfloat16* __restrict__ Chi, __nv_bfloat16* __restrict__ Clo,
    int M, int N, int K, int flags)
{
    constexpr int NT = 128;
    constexpr int BS = NT * 128;
    constexpr int STG = 32768 + 2 * BS;

    extern __shared__ char smem[];
    uint32_t uS = smem_u32(smem);

    const int tid = threadIdx.x;
    const int wid = tid >> 5, lane = tid & 31;
    const int m0 = blockIdx.y * 128, n0 = blockIdx.x * NT;
    const int wm = wid & 1, wn = wid >> 1;

    const __nv_bfloat16* Azh = Ahi + (size_t)m0 * K;
    const __nv_bfloat16* Azl = Alo + (size_t)m0 * K;
    const __nv_bfloat16* Bzh = Bhi + (size_t)n0 * K;
    const __nv_bfloat16* Bzl = Blo + (size_t)n0 * K;

    float acc[4][4][4] = {};

    const int a_row = wm * 64 + (lane & 15);
    const int a_cb  = (lane >> 4) * 16;
    const int b_row = wn * 32 + (lane & 7) + ((lane >> 4) << 3);
    const int b_cb  = ((lane >> 3) & 1) * 16;

    const int KT = K >> 6;
    {
        uint32_t base = uS;
        cpa_tile(base,              Azh, K, 1024, tid);
        cpa_tile(base + 16384,      Azl, K, 1024, tid);
        cpa_tile(base + 32768,      Bzh, K, NT * 8, tid);
        cpa_tile(base + 32768 + BS, Bzl, K, NT * 8, tid);
        CP_COMMIT();
    }

    for (int kt = 0; kt < KT; kt++) {
        if (kt + 1 < KT) {
            uint32_t base = uS + ((kt + 1) & 1) * STG;
            cpa_tile(base,              Azh + (kt + 1) * 64, K, 1024, tid);
            cpa_tile(base + 16384,      Azl + (kt + 1) * 64, K, 1024, tid);
            cpa_tile(base + 32768,      Bzh + (kt + 1) * 64, K, NT * 8, tid);
            cpa_tile(base + 32768 + BS, Bzl + (kt + 1) * 64, K, NT * 8, tid);
            CP_COMMIT();
            CP_WAIT1();
        } else {
            CP_WAIT0();
        }
        __syncthreads();

        uint32_t bAh = uS + (kt & 1) * STG;
        uint32_t bAl = bAh + 16384;
        uint32_t bBh = bAh + 32768;
        uint32_t bBl = bBh + BS;

#pragma unroll
        for (int ks = 0; ks < 4; ks++) {
            uint32_t ah[4][4], al[4][4], bh[2][4], bl[2][4];
#pragma unroll
            for (int mt = 0; mt < 4; mt++) {
                int row = a_row + mt * 16;
                uint32_t off = row * 128 + ((a_cb + ks * 32) ^ ((row & 7) << 4));
                LDSM4(ah[mt], bAh + off);
                LDSM4(al[mt], bAl + off);
            }
#pragma unroll
            for (int q = 0; q < 2; q++) {
                int row = b_row + q * 16;
                uint32_t off = row * 128 + ((b_cb + ks * 32) ^ ((row & 7) << 4));
                LDSM4(bh[q], bBh + off);
                LDSM4(bl[q], bBl + off);
            }
#pragma unroll
            for (int mt = 0; mt < 4; mt++)
#pragma unroll
                for (int nt = 0; nt < 4; nt++)
                    MMA16816(acc[mt][nt], ah[mt], &bh[nt >> 1][(nt & 1) * 2]);
#pragma unroll
            for (int mt = 0; mt < 4; mt++)
#pragma unroll
                for (int nt = 0; nt < 4; nt++)
                    MMA16816(acc[mt][nt], ah[mt], &bl[nt >> 1][(nt & 1) * 2]);
#pragma unroll
            for (int mt = 0; mt < 4; mt++)
#pragma unroll
                for (int nt = 0; nt < 4; nt++)
                    MMA16816(acc[mt][nt], al[mt], &bh[nt >> 1][(nt & 1) * 2]);
        }
        __syncthreads();
    }

    const int rbase = m0 + wm * 64;
#pragma unroll
    for (int mt = 0; mt < 4; mt++) {
#pragma unroll
        for (int nt = 0; nt < 4; nt++) {
            int c = n0 + wn * 32 + nt * 8 + (lane & 3) * 2;
            float bv0 = 0.f, bv1 = 0.f;
            if (flags & FBIAS) { bv0 = bias[c]; bv1 = bias[c + 1]; }
#pragma unroll
            for (int half = 0; half < 2; half++) {
                int r = rbase + mt * 16 + (lane >> 2) + half * 8;
                float v0 = acc[mt][nt][half * 2 + 0];
                float v1 = acc[mt][nt][half * 2 + 1];
                if (flags & FBIAS) { v0 += bv0; v1 += bv1; }
                if (flags & FGELU) {
                    v0 = 0.5f * v0 * (1.f + erff(v0 * 0.70710678118654752f));
                    v1 = 0.5f * v1 * (1.f + erff(v1 * 0.70710678118654752f));
                }
                long idx = (long)r * N + c;
                if (flags & FRES) { v0 += res[idx]; v1 += res[idx + 1]; }
                if (C) *(float2*)(C + idx) = make_float2(v0, v1);
                if (Chi) {
                    __nv_bfloat16 h0, l0, h1, l1;
                    split2(v0, h0, l0); split2(v1, h1, l1);
                    ushort2 hh; hh.x = (ushort)bfu(h0); hh.y = (ushort)bfu(h1);
                    ushort2 ll; ll.x = (ushort)bfu(l0); ll.y = (ushort)bfu(l1);
                    *(ushort2*)(Chi + idx) = hh;
                    *(ushort2*)(Clo + idx) = ll;
                }
            }
        }
    }
}

// ---------------------------------------------------------------------------
// Fused flash attention: per CTA = one 128-row block of one (b,h).
// Warp = 16 rows x full 128-col j-block. Online softmax, P->bf16 hi/lo in
// registers, PV accumulated in fp32. Data-derived j-block skip via image-id
// min/max overlap test (conservative => correct for any ids).
// ---------------------------------------------------------------------------
#define FA_SMEM 165504

__global__ void __launch_bounds__(256, 1) flash_attn(
    const __nv_bfloat16* __restrict__ Qh_, const __nv_bfloat16* __restrict__ Ql_,
    const __nv_bfloat16* __restrict__ Kh_, const __nv_bfloat16* __restrict__ Kl_,
    const __nv_bfloat16* __restrict__ Vh_, const __nv_bfloat16* __restrict__ Vl_,
    const int* __restrict__ image_ids, const int* __restrict__ lengths,
    __nv_bfloat16* __restrict__ Oh_, __nv_bfloat16* __restrict__ Ol_)
{
    extern __shared__ char smem[];
    uint32_t uS = smem_u32(smem);
    const int tid = threadIdx.x, wid = tid >> 5, lane = tid & 31;
    const int z = blockIdx.y, b = z / 12, h = z % 12;
    const int m0 = blockIdx.x * 128;

    int* s_cmin   = (int*)(smem + 163840);
    int* s_cmax   = s_cmin + 8;
    int* s_jlist  = s_cmax + 8;
    int* s_meta   = s_jlist + 8;
    int* s_imgRow = s_meta + 8;
    int* s_imgCol = s_imgRow + 128;   // 2 stages x 128

    const int len = lengths[b];

    {   // per-warp col-block min/max (warp w = block w)
        int4 v = *(const int4*)(image_ids + b*1024 + wid*128 + lane*4);
        int mn = min(min(v.x, v.y), min(v.z, v.w));
        int mx = max(max(v.x, v.y), max(v.z, v.w));
#pragma unroll
        for (int o = 16; o; o >>= 1) {
            mn = min(mn, __shfl_xor_sync(0xffffffffu, mn, o));
            mx = max(mx, __shfl_xor_sync(0xffffffffu, mx, o));
        }
        if (lane == 0) { s_cmin[wid] = mn; s_cmax[wid] = mx; }
    }
    if (tid < 128) s_imgRow[tid] = image_ids[b*1024 + m0 + tid];
    __syncthreads();
    if (tid == 0) {
        int rmin = s_cmin[blockIdx.x], rmax = s_cmax[blockIdx.x];
        int nj = 0;
        for (int jb = 0; jb < 8; jb++)
            if (jb * 128 < len && s_cmax[jb] >= rmin && s_cmin[jb] <= rmax)
                s_jlist[nj++] = jb;
        s_meta[0] = nj;
    }
    __syncthreads();
    const int nj = s_meta[0];

    // ---- prefetch Q + stage 0 ----
    const size_t qoff = ((size_t)z * 1024 + m0) * 64;
    cpa_tile(uS,         Qh_ + qoff, 64, 1024, tid);
    cpa_tile(uS + 16384, Ql_ + qoff, 64, 1024, tid);

    auto prefetch = [&](int t) {
        int jb = s_jlist[t];
        int st = t & 1;
        uint32_t base = uS + 32768 + st * 65536;
        size_t koff = ((size_t)z * 1024 + jb * 128) * 64;
        cpa_tile(base,         Kh_ + koff, 64, 1024, tid);
        cpa_tile(base + 16384, Kl_ + koff, 64, 1024, tid);
        const __nv_bfloat16* vh = Vh_ + (size_t)z * 64 * 1024 + jb * 128;
        const __nv_bfloat16* vl = Vl_ + (size_t)z * 64 * 1024 + jb * 128;
        for (int i = tid; i < 1024; i += 256) {       // 64 rows x 16 chunks
            int r = i >> 4, c = i & 15;
            int kc = c >> 3, cc = c & 7;
            uint32_t off = r * 128 + cc * 16;
            uint32_t sw = off ^ ((off >> 3) & 0x70);
            CPA16(base + 32768 + kc * 8192 + sw, vh + (size_t)r * 1024 + c * 8);
            CPA16(base + 49152 + kc * 8192 + sw, vl + (size_t)r * 1024 + c * 8);
        }
        if (tid < 128) s_imgCol[st * 128 + tid] = image_ids[b*1024 + jb*128 + tid];
    };
    prefetch(0);
    CP_COMMIT();

    float O[8][4] = {};
    float mA = -FLT_MAX, mB = -FLT_MAX, lA = 0.f, lB = 0.f;
    uint32_t qh[4][4], ql[4][4];
    bool qloaded = false;

    const int rA = lane >> 2;
    const int imgA = s_imgRow[wid * 16 + rA];
    const int imgB = s_imgRow[wid * 16 + rA + 8];

    const int a_row = wid * 16 + (lane & 15);
    const int a_cb  = (lane >> 4) * 16;
    const int b_row_base = (lane & 7) + ((lane >> 4) << 3);
    const int b_cb  = ((lane >> 3) & 1) * 16;

    for (int t = 0; t < nj; t++) {
        if (t + 1 < nj) { prefetch(t + 1); CP_COMMIT(); CP_WAIT1(); }
        else CP_WAIT0();
        __syncthreads();

        if (!qloaded) {
            qloaded = true;
#pragma unroll
            for (int ks = 0; ks < 4; ks++) {
                uint32_t off = a_row * 128 + ((a_cb + ks * 32) ^ ((a_row & 7) << 4));
                LDSM4(qh[ks], uS + off);
                LDSM4(ql[ks], uS + 16384 + off);
            }
        }

        int st = t & 1;
        uint32_t bK  = uS + 32768 + st * 65536;
        uint32_t bKl = bK + 16384;
        uint32_t bV  = bK + 32768;
        uint32_t bVl = bK + 49152;
        int jb = s_jlist[t];
        int j0 = jb * 128;
        const int* imgC = s_imgCol + st * 128;

        float S[16][4] = {};
#pragma unroll
        for (int ks = 0; ks < 4; ks++) {
#pragma unroll
            for (int nb = 0; nb < 8; nb++) {
                uint32_t bh4[4], bl4[4];
                int row = nb * 16 + b_row_base;
                uint32_t off = row * 128 + ((b_cb + ks * 32) ^ ((row & 7) << 4));
                LDSM4(bh4, bK + off);
                LDSM4(bl4, bKl + off);
                MMA16816(S[2*nb],   qh[ks], bh4);
                MMA16816(S[2*nb+1], qh[ks], bh4 + 2);
                MMA16816(S[2*nb],   qh[ks], bl4);
                MMA16816(S[2*nb+1], qh[ks], bl4 + 2);
                MMA16816(S[2*nb],   ql[ks], bh4);
                MMA16816(S[2*nb+1], ql[ks], bh4 + 2);
            }
        }

        // ---- mask + online softmax ----
        float mnA = mA, mnB = mB;
#pragma unroll
        for (int nt = 0; nt < 16; nt++) {
            int c0 = nt * 8 + (lane & 3) * 2;
            int i0 = imgC[c0], i1 = imgC[c0 + 1];
            bool v0 = (j0 + c0) < len, v1 = (j0 + c0 + 1) < len;
            if (i0 == imgA && v0) mnA = fmaxf(mnA, S[nt][0]);
            if (i1 == imgA && v1) mnA = fmaxf(mnA, S[nt][1]);
            if (i0 == imgB && v0) mnB = fmaxf(mnB, S[nt][2]);
            if (i1 == imgB && v1) mnB = fmaxf(mnB, S[nt][3]);
        }
#pragma unroll
        for (int o = 1; o <= 2; o <<= 1) {
            mnA = fmaxf(mnA, __shfl_xor_sync(0xffffffffu, mnA, o));
            mnB = fmaxf(mnB, __shfl_xor_sync(0xffffffffu, mnB, o));
        }
        float scA = __expf(mA - mnA), scB = __expf(mB - mnB);
        mA = mnA; mB = mnB;
        lA *= scA; lB *= scB;
#pragma unroll
        for (int nt = 0; nt < 16; nt++) {
            int c0 = nt * 8 + (lane & 3) * 2;
            int i0 = imgC[c0], i1 = imgC[c0 + 1];
            bool v0 = (j0 + c0) < len, v1 = (j0 + c0 + 1) < len;
            float p0 = (i0 == imgA && v0) ? __expf(S[nt][0] - mnA) : 0.f;
            float p1 = (i1 == imgA && v1) ? __expf(S[nt][1] - mnA) : 0.f;
            float p2 = (i0 == imgB && v0) ? __expf(S[nt][2] - mnB) : 0.f;
            float p3 = (i1 == imgB && v1) ? __expf(S[nt][3] - mnB) : 0.f;
            lA += p0 + p1; lB += p2 + p3;
            S[nt][0] = p0; S[nt][1] = p1; S[nt][2] = p2; S[nt][3] = p3;
        }
#pragma unroll
        for (int nt = 0; nt < 8; nt++) {
            O[nt][0] *= scA; O[nt][1] *= scA; O[nt][2] *= scB; O[nt][3] *= scB;
        }

        // ---- PV: P fragments straight from registers ----
#pragma unroll
        for (int kt = 0; kt < 8; kt++) {
            uint32_t ah4[4], al4[4];
            {
                __nv_bfloat16 h0, l0, h1, l1;
                split2(S[2*kt][0], h0, l0);   split2(S[2*kt][1], h1, l1);
                ah4[0] = bfu(h0) | (bfu(h1) << 16);  al4[0] = bfu(l0) | (bfu(l1) << 16);
                split2(S[2*kt][2], h0, l0);   split2(S[2*kt][3], h1, l1);
                ah4[1] = bfu(h0) | (bfu(h1) << 16);  al4[1] = bfu(l0) | (bfu(l1) << 16);
                split2(S[2*kt+1][0], h0, l0); split2(S[2*kt+1][1], h1, l1);
                ah4[2] = bfu(h0) | (bfu(h1) << 16);  al4[2] = bfu(l0) | (bfu(l1) << 16);
                split2(S[2*kt+1][2], h0, l0); split2(S[2*kt+1][3], h1, l1);
                ah4[3] = bfu(h0) | (bfu(h1) << 16);  al4[3] = bfu(l0) | (bfu(l1) << 16);
            }
            uint32_t tb  = bV  + (kt >> 2) * 8192;
            uint32_t tbl = bVl + (kt >> 2) * 8192;
#pragma unroll
            for (int nb = 0; nb < 4; nb++) {
                uint32_t vh4[4], vl4[4];
                int row = nb * 16 + b_row_base;
                uint32_t off = row * 128 + ((b_cb + (kt & 3) * 32) ^ ((row & 7) << 4));
                LDSM4(vh4, tb + off);
                LDSM4(vl4, tbl + off);
                MMA16816(O[2*nb],   ah4, vh4);
                MMA16816(O[2*nb+1], ah4, vh4 + 2);
                MMA16816(O[2*nb],   ah4, vl4);
                MMA16816(O[2*nb+1], ah4, vl4 + 2);
                MMA16816(O[2*nb],   al4, vh4);
                MMA16816(O[2*nb+1], al4, vh4 + 2);
            }
        }
        __syncthreads();
    }

    // ---- finalize ----
#pragma unroll
    for (int o = 1; o <= 2; o <<= 1) {
        lA += __shfl_xor_sync(0xffffffffu, lA, o);
        lB += __shfl_xor_sync(0xffffffffu, lB, o);
    }
    float iA = lA > 0.f ? 1.f / lA : 0.f;
    float iB = lB > 0.f ? 1.f / lB : 0.f;
    size_t rowA = (size_t)(b * 1024 + m0 + wid * 16 + rA);
#pragma unroll
    for (int nt = 0; nt < 8; nt++) {
        int c = nt * 8 + (lane & 3) * 2;
        __nv_bfloat16 h0, l0, h1, l1;
        float v0 = O[nt][0] * iA, v1 = O[nt][1] * iA;
        split2(v0, h0, l0); split2(v1, h1, l1);
        size_t idx = rowA * 768 + h * 64 + c;
        ushort2 hh; hh.x = (ushort)bfu(h0); hh.y = (ushort)bfu(h1);
        ushort2 ll; ll.x = (ushort)bfu(l0); ll.y = (ushort)bfu(l1);
        *(ushort2*)(Oh_ + idx) = hh;
        *(ushort2*)(Ol_ + idx) = ll;
        v0 = O[nt][2] * iB; v1 = O[nt][3] * iB;
        split2(v0, h0, l0); split2(v1, h1, l1);
        idx = (rowA + 8) * 768 + h * 64 + c;
        hh.x = (ushort)bfu(h0); hh.y = (ushort)bfu(h1);
        ll.x = (ushort)bfu(l0); ll.y = (ushort)bfu(l1);
        *(ushort2*)(Oh_ + idx) = hh;
        *(ushort2*)(Ol_ + idx) = ll;
    }
}

// ---------------------------------------------------------------------------
// LayerNorm over width 768. fp32 and/or bf16 hi/lo outputs. Optional pos add.
// ---------------------------------------------------------------------------
__global__ void ln_kernel(const float* __restrict__ in, const float* __restrict__ g,
                          float* __restrict__ outf,
                          __nv_bfloat16* __restrict__ outhi, __nv_bfloat16* __restrict__ outlo,
                          const float* __restrict__ pos_h, const float* __restrict__ pos_w,
                          const int* __restrict__ ppos)
{
    int row = blockIdx.x;
    int tid = threadIdx.x;
    const float* xr = in + (size_t)row * 768;
    float v[3]; float s = 0.f, q = 0.f;
#pragma unroll
    for (int i = 0; i < 3; i++) { float t = xr[tid + i*256]; v[i] = t; s += t; q += t*t; }
#pragma unroll
    for (int o = 16; o; o >>= 1) {
        s += __shfl_xor_sync(0xffffffffu, s, o);
        q += __shfl_xor_sync(0xffffffffu, q, o);
    }
    __shared__ float shs[8], shq[8], st[2];
    int w = tid >> 5;
    if ((tid & 31) == 0) { shs[w] = s; shq[w] = q; }
    __syncthreads();
    if (tid == 0) {
        float S = 0.f, Q = 0.f;
#pragma unroll
        for (int i = 0; i < 8; i++) { S += shs[i]; Q += shq[i]; }
        float mu = S * (1.f/768.f);
        st[0] = mu;
        st[1] = rsqrtf(Q * (1.f/768.f) - mu*mu + 1e-5f);
    }
    __syncthreads();
    float mu = st[0], rs = st[1];
    int p0 = 0, p1 = 0;
    if (ppos) { p0 = ppos[row*2]; p1 = ppos[row*2 + 1]; }
#pragma unroll
    for (int i = 0; i < 3; i++) {
        int c = tid + i*256;
        float y = (v[i] - mu) * rs * g[c];
        if (ppos) y += pos_h[p0*768 + c] + pos_w[p1*768 + c];
        size_t idx = (size_t)row*768 + c;
        if (outf) outf[idx] = y;
        if (outhi) {
            __nv_bfloat16 hh, ll; split2(y, hh, ll);
            outhi[idx] = hh; outlo[idx] = ll;
        }
    }
}

// ---------------------------------------------------------------------------
// QK-RMSNorm + transpose -> [z][n][64] hi/lo
// ---------------------------------------------------------------------------
__global__ void rmsT_split(const float* __restrict__ in, int ld, int off,
                           const float* __restrict__ g,
                           __nv_bfloat16* __restrict__ oh, __nv_bfloat16* __restrict__ ol)
{
    int token = blockIdx.x;
    int b = token >> 10, n = token & 1023;
    int w = threadIdx.x >> 5, lane = threadIdx.x & 31;
    const float* src = in + (size_t)token * ld + off + w*64;
    float v0 = src[lane], v1 = src[lane + 32];
    float ss = v0*v0 + v1*v1;
#pragma unroll
    for (int o = 16; o; o >>= 1) ss += __shfl_xor_sync(0xffffffffu, ss, o);
    float inv = 8.0f / fmaxf(sqrtf(ss), 1e-12f);
    v0 *= inv * g[w*64 + lane];
    v1 *= inv * g[w*64 + lane + 32];
    size_t dst = ((size_t)(b*12 + w) * 1024 + n) * 64;
    __nv_bfloat16 hh, ll;
    split2(v0, hh, ll); oh[dst + lane] = hh;      ol[dst + lane] = ll;
    split2(v1, hh, ll); oh[dst + lane + 32] = hh; ol[dst + lane + 32] = ll;
}

__global__ void rmsTv_split(const float* __restrict__ in, int ld, int off,
                            __nv_bfloat16* __restrict__ oh, __nv_bfloat16* __restrict__ ol)
{
    int token = blockIdx.x;
    int b = token >> 10, n = token & 1023;
    int w = threadIdx.x >> 5, lane = threadIdx.x & 31;
    const float* src = in + (size_t)token * ld + off + w*64;
    float v0 = src[lane], v1 = src[lane + 32];
    size_t base = ((size_t)(b*12 + w) * 64) * 1024 + n;
    __nv_bfloat16 hh, ll;
    split2(v0, hh, ll); oh[base + (size_t)lane * 1024] = hh;        ol[base + (size_t)lane * 1024] = ll;
    split2(v1, hh, ll); oh[base + (size_t)(lane + 32) * 1024] = hh; ol[base + (size_t)(lane + 32) * 1024] = ll;
}

__global__ void rmsT_f32(const float* __restrict__ in, int ld, int off,
                         const float* __restrict__ g, float* __restrict__ outT)
{
    int token = blockIdx.x;
    int b = token >> 10, n = token & 1023;
    int w = threadIdx.x >> 5, lane = threadIdx.x & 31;
    const float* src = in + (size_t)token * ld + off + w*64;
    float v0 = src[lane], v1 = src[lane + 32];
    if (g) {
        float ss = v0*v0 + v1*v1;
#pragma unroll
        for (int o = 16; o; o >>= 1) ss += __shfl_xor_sync(0xffffffffu, ss, o);
        float inv = 8.0f / fmaxf(sqrtf(ss), 1e-12f);
        v0 *= inv * g[w*64 + lane];
        v1 *= inv * g[w*64 + lane + 32];
    }
    float* dst = outT + ((size_t)(b*12 + w) * 1024 + n) * 64;
    dst[lane] = v0; dst[lane + 32] = v1;
}

// ---------------------------------------------------------------------------
// Attention pooling (192 blocks), fp32 path.
// ---------------------------------------------------------------------------
__global__ void pool_attn_kernel(const float* __restrict__ pqn, const float* __restrict__ kT,
                                 const float* __restrict__ vT, const int* __restrict__ image_ids,
                                 const int* __restrict__ lengths, float* __restrict__ out)
{
    int idx = blockIdx.x;
    int h = idx % 12, img = (idx / 12) % 4, b = idx / 48;
    int tid = threadIdx.x;
    __shared__ float q[64];
    __shared__ float p[1024];
    __shared__ float sh[8];
    __shared__ float bs[2];
    __shared__ float sred[256];
    if (tid < 64) q[tid] = pqn[h*64 + tid];
    __syncthreads();

    const float* K = kT + (size_t)(b*12 + h) * 1024 * 64;
    int len = lengths[b];
    float loc[4]; float mx = -FLT_MAX;
#pragma unroll
    for (int t = 0; t < 4; t++) {
        int j = tid + t*256;
        const float* kr = K + (size_t)j * 64;
        float dot = 0.f;
#pragma unroll
        for (int d = 0; d < 64; d++) dot += q[d] * kr[d];
        bool ok = (image_ids[b*1024 + j] == img) && (j < len);
        loc[t] = ok ? dot : -FLT_MAX;
        mx = fmaxf(mx, loc[t]);
    }
#pragma unroll
    for (int o = 16; o; o >>= 1) mx = fmaxf(mx, __shfl_xor_sync(0xffffffffu, mx, o));
    int w = tid >> 5;
    if ((tid & 31) == 0) sh[w] = mx;
    __syncthreads();
    if (tid == 0) { float mm = sh[0]; for (int i = 1; i < 8; i++) mm = fmaxf(mm, sh[i]); bs[0] = mm; }
    __syncthreads();
    mx = bs[0];
    float s = 0.f;
#pragma unroll
    for (int t = 0; t < 4; t++) {
        float e = __expf(loc[t] - mx);
        p[tid + t*256] = e;
        s += e;
    }
#pragma unroll
    for (int o = 16; o; o >>= 1) s += __shfl_xor_sync(0xffffffffu, s, o);
    if ((tid & 31) == 0) sh[w] = s;
    __syncthreads();
    if (tid == 0) { float ss = 0.f; for (int i = 0; i < 8; i++) ss += sh[i]; bs[1] = 1.f / ss; }
    __syncthreads();
    float inv = bs[1];

    const float* V = vT + (size_t)(b*12 + h) * 1024 * 64;
    int d = tid & 63, grp = tid >> 6;
    float acc = 0.f;
    for (int j = grp; j < 1024; j += 4) acc += p[j] * V[(size_t)j*64 + d];
    sred[tid] = acc;
    __syncthreads();
    if (grp == 0) {
        float r = (sred[d] + sred[d + 64]) + (sred[d + 128] + sred[d + 192]);
        out[(size_t)(b*4 + img) * 768 + h*64 + d] = r * inv;
    }
}

__global__ void rms_vec_kernel(const float* __restrict__ in, const float* __restrict__ g,
                               float* __restrict__ out)
{
    int w = threadIdx.x >> 5, lane = threadIdx.x & 31;
    float v0 = in[w*64 + lane], v1 = in[w*64 + lane + 32];
    float ss = v0*v0 + v1*v1;
#pragma unroll
    for (int o = 16; o; o >>= 1) ss += __shfl_xor_sync(0xffffffffu, ss, o);
    float inv = 8.0f / fmaxf(sqrtf(ss), 1e-12f);
    out[w*64 + lane]      = v0 * inv * g[w*64 + lane];
    out[w*64 + lane + 32] = v1 * inv * g[w*64 + lane + 32];
}

__global__ void small_gemm_kernel(const float* __restrict__ A, const float* __restrict__ W,
                                  const float* __restrict__ addvec, float* __restrict__ C,
                                  int N, int K)
{
    __shared__ float a[768];
    int row = blockIdx.y;
    for (int i = threadIdx.x; i < K; i += 256) a[i] = A[(size_t)row*K + i];
    __syncthreads();
    int n = blockIdx.x * 256 + threadIdx.x;
    if (n >= N) return;
    float acc = addvec ? addvec[n] : 0.f;
#pragma unroll 4
    for (int k = 0; k < K; k++) acc += a[k] * W[(size_t)k*N + n];
    C[(size_t)row*N + n] = acc;
}

// ---------------------------------------------------------------------------
// Host side
// ---------------------------------------------------------------------------
extern "C" void kernel_launch(void* const* d_in, const int* in_sizes, int n_in,
                              void* d_out, int out_size)
{
    (void)in_sizes; (void)n_in; (void)out_size;
    const float* patches    = (const float*)d_in[0];
    const int*   ppos       = (const int*)  d_in[1];
    const int*   image_ids  = (const int*)  d_in[2];
    const int*   lengths    = (const int*)  d_in[3];
    const float* emb_ln_g   = (const float*)d_in[4];
    const float* W_emb      = (const float*)d_in[5];
    const float* b_emb      = (const float*)d_in[6];
    const float* emb_ln2_g  = (const float*)d_in[7];
    const float* pos_h      = (const float*)d_in[8];
    const float* pos_w      = (const float*)d_in[9];
    const float* ln_attn_g  = (const float*)d_in[10];
    const float* Wq         = (const float*)d_in[11];
    const float* Wkv        = (const float*)d_in[12];
    const float* qn_g       = (const float*)d_in[13];
    const float* kn_g       = (const float*)d_in[14];
    const float* Wo         = (const float*)d_in[15];
    const float* ln_ff_g    = (const float*)d_in[16];
    const float* W1         = (const float*)d_in[17];
    const float* b1         = (const float*)d_in[18];
    const float* W2         = (const float*)d_in[19];
    const float* b2         = (const float*)d_in[20];
    const float* final_ln_g = (const float*)d_in[21];
    const float* pool_q     = (const float*)d_in[22];
    const float* pool_ln_g  = (const float*)d_in[23];
    const float* pWq        = (const float*)d_in[24];
    const float* pWkv       = (const float*)d_in[25];
    const float* p_qn_g     = (const float*)d_in[26];
    const float* p_kn_g     = (const float*)d_in[27];
    const float* pWo        = (const float*)d_in[28];
    const float* head_ln_g  = (const float*)d_in[29];
    const float* W_head     = (const float*)d_in[30];

    float *x, *qkv, *kTf, *vTf, *sm, *pattn, *pool, *pln;
    __nv_bfloat16 *xnh, *xnl, *tmph, *tmpl, *qTh, *qTl, *kTh, *kTl, *vTth, *vTtl;
    __nv_bfloat16 *aoh, *aol, *whi, *wlo;
    cudaGetSymbolAddress((void**)&x,    g_x);
    cudaGetSymbolAddress((void**)&qkv,  g_qkv);
    cudaGetSymbolAddress((void**)&kTf,  g_kTf);
    cudaGetSymbolAddress((void**)&vTf,  g_vTf);
    cudaGetSymbolAddress((void**)&sm,   g_sm);
    cudaGetSymbolAddress((void**)&pattn,g_pattn);
    cudaGetSymbolAddress((void**)&pool, g_pool);
    cudaGetSymbolAddress((void**)&pln,  g_pln);
    cudaGetSymbolAddress((void**)&xnh,  g_xnh);
    cudaGetSymbolAddress((void**)&xnl,  g_xnl);
    cudaGetSymbolAddress((void**)&tmph, g_tmph);
    cudaGetSymbolAddress((void**)&tmpl, g_tmpl);
    cudaGetSymbolAddress((void**)&qTh,  g_qTh);
    cudaGetSymbolAddress((void**)&qTl,  g_qTl);
    cudaGetSymbolAddress((void**)&kTh,  g_kTh);
    cudaGetSymbolAddress((void**)&kTl,  g_kTl);
    cudaGetSymbolAddress((void**)&vTth, g_vTth);
    cudaGetSymbolAddress((void**)&vTtl, g_vTtl);
    cudaGetSymbolAddress((void**)&aoh,  g_aoh);
    cudaGetSymbolAddress((void**)&aol,  g_aol);
    cudaGetSymbolAddress((void**)&whi,  g_whi);
    cudaGetSymbolAddress((void**)&wlo,  g_wlo);

    constexpr int SMEM128 = 131072;
    cudaFuncSetAttribute(mma_gemm,   cudaFuncAttributeMaxDynamicSharedMemorySize, SMEM128);
    cudaFuncSetAttribute(flash_attn, cudaFuncAttributeMaxDynamicSharedMemorySize, FA_SMEM);

    // ---- Convert + transpose weights ----
    dim3 wb(32, 8);
    wconv_kernel<<<dim3(DIM/32,  DIM/32),  wb>>>(W_emb, whi + WOFF_EMB, wlo + WOFF_EMB, DIM, DIM);
    for (int l = 0; l < 4; l++) {
        wconv_kernel<<<dim3(DIM/32,    DIM/32),  wb>>>(Wq  + (size_t)l*DIM*DIM,    whi + WOFF_Q(l),  wlo + WOFF_Q(l),  DIM,  DIM);
        wconv_kernel<<<dim3(2*DIM/32,  DIM/32),  wb>>>(Wkv + (size_t)l*DIM*2*DIM,  whi + WOFF_Q(l) + 589824ULL, wlo + WOFF_Q(l) + 589824ULL, DIM, 2*DIM);
        wconv_kernel<<<dim3(DIM/32,    DIM/32),  wb>>>(Wo  + (size_t)l*DIM*DIM,    whi + WOFF_O(l),  wlo + WOFF_O(l),  DIM,  DIM);
        wconv_kernel<<<dim3(MLPD/32,   DIM/32),  wb>>>(W1  + (size_t)l*DIM*MLPD,   whi + WOFF_W1(l), wlo + WOFF_W1(l), DIM,  MLPD);
        wconv_kernel<<<dim3(DIM/32,    MLPD/32), wb>>>(W2  + (size_t)l*MLPD*DIM,   whi + WOFF_W2(l), wlo + WOFF_W2(l), MLPD, DIM);
    }
    wconv_kernel<<<dim3(2*DIM/32, DIM/32), wb>>>(pWkv, whi + WOFF_PKV, wlo + WOFF_PKV, DIM, 2*DIM);

    auto G = [&](const __nv_bfloat16* ah, const __nv_bfloat16* al,
                 const __nv_bfloat16* bh, const __nv_bfloat16* bl,
                 const float* bias, const float* res,
                 float* C, __nv_bfloat16* Chi, __nv_bfloat16* Clo,
                 int M, int N, int K, int flags) {
        dim3 g(N/128, M/128, 1);
        mma_gemm<<<g, 256, SMEM128>>>(ah, al, bh, bl, bias, res, C, Chi, Clo, M, N, K, flags);
    };

    // ---- Embedding ----
    ln_kernel<<<TOKS, 256>>>(patches, emb_ln_g, nullptr, xnh, xnl, nullptr, nullptr, nullptr);
    G(xnh, xnl, whi + WOFF_EMB, wlo + WOFF_EMB, b_emb, nullptr, x, nullptr, nullptr, TOKS, DIM, DIM, FBIAS);
    ln_kernel<<<TOKS, 256>>>(x, emb_ln2_g, x, nullptr, nullptr, pos_h, pos_w, ppos);

    // ---- Transformer layers ----
    for (int l = 0; l < 4; l++) {
        ln_kernel<<<TOKS, 256>>>(x, ln_attn_g + l*DIM, nullptr, xnh, xnl, nullptr, nullptr, nullptr);
        G(xnh, xnl, whi + WOFF_Q(l), wlo + WOFF_Q(l), nullptr, nullptr, qkv, nullptr, nullptr,
          TOKS, 2304, DIM, 0);
        rmsT_split<<<TOKS, 384>>>(qkv, 2304, 0,    qn_g + l*DIM, qTh, qTl);
        rmsT_split<<<TOKS, 384>>>(qkv, 2304, 768,  kn_g + l*DIM, kTh, kTl);
        rmsTv_split<<<TOKS, 384>>>(qkv, 2304, 1536, vTth, vTtl);
        flash_attn<<<dim3(8, BH), 256, FA_SMEM>>>(qTh, qTl, kTh, kTl, vTth, vTtl,
                                                  image_ids, lengths, aoh, aol);
        G(aoh, aol, whi + WOFF_O(l), wlo + WOFF_O(l), nullptr, x, x, nullptr, nullptr,
          TOKS, DIM, DIM, FRES);
        ln_kernel<<<TOKS, 256>>>(x, ln_ff_g + l*DIM, nullptr, xnh, xnl, nullptr, nullptr, nullptr);
        G(xnh, xnl, whi + WOFF_W1(l), wlo + WOFF_W1(l), b1 + l*MLPD, nullptr,
          nullptr, tmph, tmpl, TOKS, MLPD, DIM, FBIAS|FGELU);
        G(tmph, tmpl, whi + WOFF_W2(l), wlo + WOFF_W2(l), b2 + l*DIM, x,
          x, nullptr, nullptr, TOKS, DIM, MLPD, FBIAS|FRES);
    }

    // ---- Final LN ----
    ln_kernel<<<TOKS, 256>>>(x, final_ln_g, nullptr, xnh, xnl, nullptr, nullptr, nullptr);

    // ---- Attention pooling ----
    ln_kernel<<<1, 256>>>(pool_q, pool_ln_g, sm, nullptr, nullptr, nullptr, nullptr, nullptr);
    small_gemm_kernel<<<dim3(3, 1), 256>>>(sm, pWq, nullptr, sm + 768, DIM, DIM);
    rms_vec_kernel<<<1, 384>>>(sm + 768, p_qn_g, sm + 1536);
    G(xnh, xnl, whi + WOFF_PKV, wlo + WOFF_PKV, nullptr, nullptr, qkv, nullptr, nullptr,
      TOKS, 1536, DIM, 0);
    rmsT_f32<<<TOKS, 384>>>(qkv, 1536, 0,   p_kn_g, kTf);
    rmsT_f32<<<TOKS, 384>>>(qkv, 1536, 768, nullptr, vTf);
    pool_attn_kernel<<<NB*IMGS*NHEAD, 256>>>(sm + 1536, kTf, vTf, image_ids, lengths, pattn);
    small_gemm_kernel<<<dim3(3, 16), 256>>>(pattn, pWo, pool_q, pool, DIM, DIM);
    ln_kernel<<<16, 256>>>(pool, head_ln_g, pln, nullptr, nullptr, nullptr, nullptr, nullptr);
    small_gemm_kernel<<<dim3(4, 16), 256>>>(pln, W_head, nullptr, (float*)d_out, NCLS, DIM);
}

// round 6
// speedup vs baseline: 2.7686x; 1.0139x over previous
#include <cuda_runtime.h>
#include <cuda_bf16.h>
#include <math.h>
#include <float.h>
#include <stdint.h>

// ---------------------------------------------------------------------------
// Problem constants
// ---------------------------------------------------------------------------
#define NB      4
#define NTOK    1024
#define DIM     768
#define NHEAD   12
#define DHEAD   64
#define MLPD    3072
#define IMGS    4
#define NCLS    1000
#define TOKS    (NB*NTOK)
#define BH      (NB*NHEAD)

#define FBIAS 1
#define FGELU 2
#define FRES  4

#define WOFF_EMB 0ULL
#define WPERL    7077888ULL
#define WOFF_L(l)   (589824ULL + (unsigned long long)(l)*WPERL)
#define WOFF_Q(l)   (WOFF_L(l) + 0ULL)
#define WOFF_O(l)   (WOFF_L(l) + 1769472ULL)
#define WOFF_W1(l)  (WOFF_L(l) + 2359296ULL)
#define WOFF_W2(l)  (WOFF_L(l) + 4718592ULL)
#define WOFF_PKV    (589824ULL + 4ULL*WPERL)
#define WTOTAL      30081024ULL

// ---------------------------------------------------------------------------
// Device scratch
// ---------------------------------------------------------------------------
__device__ float g_x   [TOKS*DIM];
__device__ float g_qkv [TOKS*2304];
__device__ __nv_bfloat16 g_xnh[TOKS*DIM],  g_xnl[TOKS*DIM];
__device__ __nv_bfloat16 g_tmph[TOKS*MLPD], g_tmpl[TOKS*MLPD];
__device__ __nv_bfloat16 g_qTh[BH*NTOK*DHEAD], g_qTl[BH*NTOK*DHEAD];
__device__ __nv_bfloat16 g_kTh[BH*NTOK*DHEAD], g_kTl[BH*NTOK*DHEAD];
__device__ __nv_bfloat16 g_vTth[BH*DHEAD*NTOK], g_vTtl[BH*DHEAD*NTOK];
__device__ __nv_bfloat16 g_aoh[TOKS*DIM], g_aol[TOKS*DIM];
__device__ float g_kTf[BH*NTOK*DHEAD], g_vTf[BH*NTOK*DHEAD];
__device__ float g_sm  [4096];
__device__ float g_pattn[16*DIM];
__device__ float g_pool [16*DIM];
__device__ float g_pln  [16*DIM];
__device__ __nv_bfloat16 g_whi[WTOTAL];
__device__ __nv_bfloat16 g_wlo[WTOTAL];

// ---------------------------------------------------------------------------
// Helpers
// ---------------------------------------------------------------------------
__device__ __forceinline__ uint32_t smem_u32(const void* p) {
    uint32_t a;
    asm("{ .reg .u64 t; cvta.to.shared.u64 t, %1; cvt.u32.u64 %0, t; }" : "=r"(a) : "l"(p));
    return a;
}

#define LDSM4(r, addr) \
    asm volatile("ldmatrix.sync.aligned.m8n8.x4.shared.b16 {%0,%1,%2,%3}, [%4];" \
        : "=r"((r)[0]), "=r"((r)[1]), "=r"((r)[2]), "=r"((r)[3]) : "r"(addr))

#define MMA16816(d, a, b) \
    asm volatile("mma.sync.aligned.m16n8k16.row.col.f32.bf16.bf16.f32 " \
        "{%0,%1,%2,%3}, {%4,%5,%6,%7}, {%8,%9}, {%0,%1,%2,%3};" \
        : "+f"((d)[0]), "+f"((d)[1]), "+f"((d)[2]), "+f"((d)[3]) \
        : "r"((a)[0]), "r"((a)[1]), "r"((a)[2]), "r"((a)[3]), "r"((b)[0]), "r"((b)[1]))

#define CPA16(dst, src) \
    asm volatile("cp.async.cg.shared.global [%0], [%1], 16;" :: "r"(dst), "l"(src))
#define CP_COMMIT() asm volatile("cp.async.commit_group;" ::: "memory")
#define CP_WAIT0()  asm volatile("cp.async.wait_group 0;" ::: "memory")
#define CP_WAIT1()  asm volatile("cp.async.wait_group 1;" ::: "memory")

__device__ __forceinline__ void split2(float v, __nv_bfloat16& h, __nv_bfloat16& l) {
    h = __float2bfloat16(v);
    l = __float2bfloat16(v - __bfloat162float(h));
}
__device__ __forceinline__ uint32_t bfu(__nv_bfloat16 b) { return (uint32_t)__bfloat16_as_ushort(b); }

__device__ __forceinline__ void cpa_tile(uint32_t smbase, const __nv_bfloat16* __restrict__ g,
                                         int ldk, int chunks, int tid)
{
    for (int i = tid; i < chunks; i += 256) {
        int r = i >> 3, c = i & 7;
        uint32_t off = r * 128 + c * 16;
        uint32_t sw = off ^ ((off >> 3) & 0x70);
        CPA16(smbase + sw, g + (size_t)r * ldk + c * 8);
    }
}

// ---------------------------------------------------------------------------
// Weight convert+transpose: W[K,N] fp32 -> hi/lo [N,K] bf16
// ---------------------------------------------------------------------------
__global__ void wconv_kernel(const float* __restrict__ W, __nv_bfloat16* __restrict__ hi,
                             __nv_bfloat16* __restrict__ lo, int K, int N)
{
    __shared__ float t[32][33];
    int n0 = blockIdx.x * 32, k0 = blockIdx.y * 32;
    int tx = threadIdx.x, ty = threadIdx.y;
#pragma unroll
    for (int r = 0; r < 4; r++)
        t[ty + r*8][tx] = W[(size_t)(k0 + ty + r*8) * N + n0 + tx];
    __syncthreads();
#pragma unroll
    for (int r = 0; r < 4; r++) {
        int n = n0 + ty + r*8, k = k0 + tx;
        float v = t[tx][ty + r*8];
        __nv_bfloat16 h, l; split2(v, h, l);
        hi[(size_t)n * K + k] = h;
        lo[(size_t)n * K + k] = l;
    }
}

// ---------------------------------------------------------------------------
// Pipelined mma.sync GEMM, templated on M-tile (128 or 256) x 128 N-tile.
// MT=128: 8 warps 2Mx4N (warp 64x32). MT=256: 8 warps 4Mx2N (warp 64x64).
// ---------------------------------------------------------------------------
template<int MT>
__global__ void __launch_bounds__(256, 1) mma_gemm(
    const __nv_bfloat16* __restrict__ Ahi, const __nv_bfloat16* __restrict__ Alo,
    const __nv_bfloat16* __restrict__ Bhi, const __nv_bfloat16* __restrict__ Blo,
    const float* __restrict__ bias, const float* __restrict__ res,
    float* __restrict__ C, __nv_bfloat16* __restrict__ Chi, __nv_bfloat16* __restrict__ Clo,
    int M, int N, int K, int flags)
{
    constexpr int WM   = MT / 64;          // warps in M (2 or 4)
    constexpr int NQ   = (WM == 2) ? 2 : 4; // B ldmatrix.x4 per warp per ks
    constexpr int NTL  = 2 * NQ;           // 8-wide n tiles per warp (4 or 8)
    constexpr int NCOL = NQ * 16;          // warp n-span (32 or 64)
    constexpr int A_SZ = MT * 128;         // bytes per A buffer
    constexpr int STG  = 2 * A_SZ + 32768; // stage size

    extern __shared__ char smem[];
    uint32_t uS = smem_u32(smem);

    const int tid = threadIdx.x;
    const int wid = tid >> 5, lane = tid & 31;
    const int m0 = blockIdx.y * MT, n0 = blockIdx.x * 128;
    const int wm = wid & (WM - 1), wn = wid / WM;

    const __nv_bfloat16* Azh = Ahi + (size_t)m0 * K;
    const __nv_bfloat16* Azl = Alo + (size_t)m0 * K;
    const __nv_bfloat16* Bzh = Bhi + (size_t)n0 * K;
    const __nv_bfloat16* Bzl = Blo + (size_t)n0 * K;

    float acc[4][NTL][4] = {};

    const int a_row = wm * 64 + (lane & 15);
    const int a_cb  = (lane >> 4) * 16;
    const int b_row = wn * NCOL + (lane & 7) + ((lane >> 4) << 3);
    const int b_cb  = ((lane >> 3) & 1) * 16;

    const int KT = K >> 6;
    {
        cpa_tile(uS,                  Azh, K, MT * 8, tid);
        cpa_tile(uS + A_SZ,           Azl, K, MT * 8, tid);
        cpa_tile(uS + 2 * A_SZ,       Bzh, K, 1024,   tid);
        cpa_tile(uS + 2 * A_SZ + 16384, Bzl, K, 1024, tid);
        CP_COMMIT();
    }

    for (int kt = 0; kt < KT; kt++) {
        if (kt + 1 < KT) {
            uint32_t base = uS + ((kt + 1) & 1) * STG;
            cpa_tile(base,                  Azh + (kt + 1) * 64, K, MT * 8, tid);
            cpa_tile(base + A_SZ,           Azl + (kt + 1) * 64, K, MT * 8, tid);
            cpa_tile(base + 2 * A_SZ,       Bzh + (kt + 1) * 64, K, 1024,   tid);
            cpa_tile(base + 2 * A_SZ + 16384, Bzl + (kt + 1) * 64, K, 1024, tid);
            CP_COMMIT();
            CP_WAIT1();
        } else {
            CP_WAIT0();
        }
        __syncthreads();

        uint32_t bAh = uS + (kt & 1) * STG;
        uint32_t bAl = bAh + A_SZ;
        uint32_t bBh = bAh + 2 * A_SZ;
        uint32_t bBl = bBh + 16384;

#pragma unroll
        for (int ks = 0; ks < 4; ks++) {
            uint32_t ah[4][4], al[4][4], bh[NQ][4], bl[NQ][4];
#pragma unroll
            for (int mt = 0; mt < 4; mt++) {
                int row = a_row + mt * 16;
                uint32_t off = row * 128 + ((a_cb + ks * 32) ^ ((row & 7) << 4));
                LDSM4(ah[mt], bAh + off);
                LDSM4(al[mt], bAl + off);
            }
#pragma unroll
            for (int q = 0; q < NQ; q++) {
                int row = b_row + q * 16;
                uint32_t off = row * 128 + ((b_cb + ks * 32) ^ ((row & 7) << 4));
                LDSM4(bh[q], bBh + off);
                LDSM4(bl[q], bBl + off);
            }
#pragma unroll
            for (int mt = 0; mt < 4; mt++)
#pragma unroll
                for (int nt = 0; nt < NTL; nt++)
                    MMA16816(acc[mt][nt], ah[mt], &bh[nt >> 1][(nt & 1) * 2]);
#pragma unroll
            for (int mt = 0; mt < 4; mt++)
#pragma unroll
                for (int nt = 0; nt < NTL; nt++)
                    MMA16816(acc[mt][nt], ah[mt], &bl[nt >> 1][(nt & 1) * 2]);
#pragma unroll
            for (int mt = 0; mt < 4; mt++)
#pragma unroll
                for (int nt = 0; nt < NTL; nt++)
                    MMA16816(acc[mt][nt], al[mt], &bh[nt >> 1][(nt & 1) * 2]);
        }
        __syncthreads();
    }

    const int rbase = m0 + wm * 64;
#pragma unroll
    for (int mt = 0; mt < 4; mt++) {
#pragma unroll
        for (int nt = 0; nt < NTL; nt++) {
            int c = n0 + wn * NCOL + nt * 8 + (lane & 3) * 2;
            float bv0 = 0.f, bv1 = 0.f;
            if (flags & FBIAS) { bv0 = bias[c]; bv1 = bias[c + 1]; }
#pragma unroll
            for (int half = 0; half < 2; half++) {
                int r = rbase + mt * 16 + (lane >> 2) + half * 8;
                float v0 = acc[mt][nt][half * 2 + 0];
                float v1 = acc[mt][nt][half * 2 + 1];
                if (flags & FBIAS) { v0 += bv0; v1 += bv1; }
                if (flags & FGELU) {
                    v0 = 0.5f * v0 * (1.f + erff(v0 * 0.70710678118654752f));
                    v1 = 0.5f * v1 * (1.f + erff(v1 * 0.70710678118654752f));
                }
                long idx = (long)r * N + c;
                if (flags & FRES) { v0 += res[idx]; v1 += res[idx + 1]; }
                if (C) *(float2*)(C + idx) = make_float2(v0, v1);
                if (Chi) {
                    __nv_bfloat16 h0, l0, h1, l1;
                    split2(v0, h0, l0); split2(v1, h1, l1);
                    ushort2 hh; hh.x = (ushort)bfu(h0); hh.y = (ushort)bfu(h1);
                    ushort2 ll; ll.x = (ushort)bfu(l0); ll.y = (ushort)bfu(l1);
                    *(ushort2*)(Chi + idx) = hh;
                    *(ushort2*)(Clo + idx) = ll;
                }
            }
        }
    }
}

// ---------------------------------------------------------------------------
// Fused flash attention (unchanged from R5).
// ---------------------------------------------------------------------------
#define FA_SMEM 165504

__global__ void __launch_bounds__(256, 1) flash_attn(
    const __nv_bfloat16* __restrict__ Qh_, const __nv_bfloat16* __restrict__ Ql_,
    const __nv_bfloat16* __restrict__ Kh_, const __nv_bfloat16* __restrict__ Kl_,
    const __nv_bfloat16* __restrict__ Vh_, const __nv_bfloat16* __restrict__ Vl_,
    const int* __restrict__ image_ids, const int* __restrict__ lengths,
    __nv_bfloat16* __restrict__ Oh_, __nv_bfloat16* __restrict__ Ol_)
{
    extern __shared__ char smem[];
    uint32_t uS = smem_u32(smem);
    const int tid = threadIdx.x, wid = tid >> 5, lane = tid & 31;
    const int z = blockIdx.y, b = z / 12, h = z % 12;
    const int m0 = blockIdx.x * 128;

    int* s_cmin   = (int*)(smem + 163840);
    int* s_cmax   = s_cmin + 8;
    int* s_jlist  = s_cmax + 8;
    int* s_meta   = s_jlist + 8;
    int* s_imgRow = s_meta + 8;
    int* s_imgCol = s_imgRow + 128;

    const int len = lengths[b];

    {
        int4 v = *(const int4*)(image_ids + b*1024 + wid*128 + lane*4);
        int mn = min(min(v.x, v.y), min(v.z, v.w));
        int mx = max(max(v.x, v.y), max(v.z, v.w));
#pragma unroll
        for (int o = 16; o; o >>= 1) {
            mn = min(mn, __shfl_xor_sync(0xffffffffu, mn, o));
            mx = max(mx, __shfl_xor_sync(0xffffffffu, mx, o));
        }
        if (lane == 0) { s_cmin[wid] = mn; s_cmax[wid] = mx; }
    }
    if (tid < 128) s_imgRow[tid] = image_ids[b*1024 + m0 + tid];
    __syncthreads();
    if (tid == 0) {
        int rmin = s_cmin[blockIdx.x], rmax = s_cmax[blockIdx.x];
        int nj = 0;
        for (int jb = 0; jb < 8; jb++)
            if (jb * 128 < len && s_cmax[jb] >= rmin && s_cmin[jb] <= rmax)
                s_jlist[nj++] = jb;
        s_meta[0] = nj;
    }
    __syncthreads();
    const int nj = s_meta[0];

    const size_t qoff = ((size_t)z * 1024 + m0) * 64;
    cpa_tile(uS,         Qh_ + qoff, 64, 1024, tid);
    cpa_tile(uS + 16384, Ql_ + qoff, 64, 1024, tid);

    auto prefetch = [&](int t) {
        int jb = s_jlist[t];
        int st = t & 1;
        uint32_t base = uS + 32768 + st * 65536;
        size_t koff = ((size_t)z * 1024 + jb * 128) * 64;
        cpa_tile(base,         Kh_ + koff, 64, 1024, tid);
        cpa_tile(base + 16384, Kl_ + koff, 64, 1024, tid);
        const __nv_bfloat16* vh = Vh_ + (size_t)z * 64 * 1024 + jb * 128;
        const __nv_bfloat16* vl = Vl_ + (size_t)z * 64 * 1024 + jb * 128;
        for (int i = tid; i < 1024; i += 256) {
            int r = i >> 4, c = i & 15;
            int kc = c >> 3, cc = c & 7;
            uint32_t off = r * 128 + cc * 16;
            uint32_t sw = off ^ ((off >> 3) & 0x70);
            CPA16(base + 32768 + kc * 8192 + sw, vh + (size_t)r * 1024 + c * 8);
            CPA16(base + 49152 + kc * 8192 + sw, vl + (size_t)r * 1024 + c * 8);
        }
        if (tid < 128) s_imgCol[st * 128 + tid] = image_ids[b*1024 + jb*128 + tid];
    };
    prefetch(0);
    CP_COMMIT();

    float O[8][4] = {};
    float mA = -FLT_MAX, mB = -FLT_MAX, lA = 0.f, lB = 0.f;
    uint32_t qh[4][4], ql[4][4];
    bool qloaded = false;

    const int rA = lane >> 2;
    const int imgA = s_imgRow[wid * 16 + rA];
    const int imgB = s_imgRow[wid * 16 + rA + 8];

    const int a_row = wid * 16 + (lane & 15);
    const int a_cb  = (lane >> 4) * 16;
    const int b_row_base = (lane & 7) + ((lane >> 4) << 3);
    const int b_cb  = ((lane >> 3) & 1) * 16;

    for (int t = 0; t < nj; t++) {
        if (t + 1 < nj) { prefetch(t + 1); CP_COMMIT(); CP_WAIT1(); }
        else CP_WAIT0();
        __syncthreads();

        if (!qloaded) {
            qloaded = true;
#pragma unroll
            for (int ks = 0; ks < 4; ks++) {
                uint32_t off = a_row * 128 + ((a_cb + ks * 32) ^ ((a_row & 7) << 4));
                LDSM4(qh[ks], uS + off);
                LDSM4(ql[ks], uS + 16384 + off);
            }
        }

        int st = t & 1;
        uint32_t bK  = uS + 32768 + st * 65536;
        uint32_t bKl = bK + 16384;
        uint32_t bV  = bK + 32768;
        uint32_t bVl = bK + 49152;
        int jb = s_jlist[t];
        int j0 = jb * 128;
        const int* imgC = s_imgCol + st * 128;

        float S[16][4] = {};
#pragma unroll
        for (int ks = 0; ks < 4; ks++) {
#pragma unroll
            for (int nb = 0; nb < 8; nb++) {
                uint32_t bh4[4], bl4[4];
                int row = nb * 16 + b_row_base;
                uint32_t off = row * 128 + ((b_cb + ks * 32) ^ ((row & 7) << 4));
                LDSM4(bh4, bK + off);
                LDSM4(bl4, bKl + off);
                MMA16816(S[2*nb],   qh[ks], bh4);
                MMA16816(S[2*nb+1], qh[ks], bh4 + 2);
                MMA16816(S[2*nb],   qh[ks], bl4);
                MMA16816(S[2*nb+1], qh[ks], bl4 + 2);
                MMA16816(S[2*nb],   ql[ks], bh4);
                MMA16816(S[2*nb+1], ql[ks], bh4 + 2);
            }
        }

        float mnA = mA, mnB = mB;
#pragma unroll
        for (int nt = 0; nt < 16; nt++) {
            int c0 = nt * 8 + (lane & 3) * 2;
            int i0 = imgC[c0], i1 = imgC[c0 + 1];
            bool v0 = (j0 + c0) < len, v1 = (j0 + c0 + 1) < len;
            if (i0 == imgA && v0) mnA = fmaxf(mnA, S[nt][0]);
            if (i1 == imgA && v1) mnA = fmaxf(mnA, S[nt][1]);
            if (i0 == imgB && v0) mnB = fmaxf(mnB, S[nt][2]);
            if (i1 == imgB && v1) mnB = fmaxf(mnB, S[nt][3]);
        }
#pragma unroll
        for (int o = 1; o <= 2; o <<= 1) {
            mnA = fmaxf(mnA, __shfl_xor_sync(0xffffffffu, mnA, o));
            mnB = fmaxf(mnB, __shfl_xor_sync(0xffffffffu, mnB, o));
        }
        float scA = __expf(mA - mnA), scB = __expf(mB - mnB);
        mA = mnA; mB = mnB;
        lA *= scA; lB *= scB;
#pragma unroll
        for (int nt = 0; nt < 16; nt++) {
            int c0 = nt * 8 + (lane & 3) * 2;
            int i0 = imgC[c0], i1 = imgC[c0 + 1];
            bool v0 = (j0 + c0) < len, v1 = (j0 + c0 + 1) < len;
            float p0 = (i0 == imgA && v0) ? __expf(S[nt][0] - mnA) : 0.f;
            float p1 = (i1 == imgA && v1) ? __expf(S[nt][1] - mnA) : 0.f;
            float p2 = (i0 == imgB && v0) ? __expf(S[nt][2] - mnB) : 0.f;
            float p3 = (i1 == imgB && v1) ? __expf(S[nt][3] - mnB) : 0.f;
            lA += p0 + p1; lB += p2 + p3;
            S[nt][0] = p0; S[nt][1] = p1; S[nt][2] = p2; S[nt][3] = p3;
        }
#pragma unroll
        for (int nt = 0; nt < 8; nt++) {
            O[nt][0] *= scA; O[nt][1] *= scA; O[nt][2] *= scB; O[nt][3] *= scB;
        }

#pragma unroll
        for (int kt = 0; kt < 8; kt++) {
            uint32_t ah4[4], al4[4];
            {
                __nv_bfloat16 h0, l0, h1, l1;
                split2(S[2*kt][0], h0, l0);   split2(S[2*kt][1], h1, l1);
                ah4[0] = bfu(h0) | (bfu(h1) << 16);  al4[0] = bfu(l0) | (bfu(l1) << 16);
                split2(S[2*kt][2], h0, l0);   split2(S[2*kt][3], h1, l1);
                ah4[1] = bfu(h0) | (bfu(h1) << 16);  al4[1] = bfu(l0) | (bfu(l1) << 16);
                split2(S[2*kt+1][0], h0, l0); split2(S[2*kt+1][1], h1, l1);
                ah4[2] = bfu(h0) | (bfu(h1) << 16);  al4[2] = bfu(l0) | (bfu(l1) << 16);
                split2(S[2*kt+1][2], h0, l0); split2(S[2*kt+1][3], h1, l1);
                ah4[3] = bfu(h0) | (bfu(h1) << 16);  al4[3] = bfu(l0) | (bfu(l1) << 16);
            }
            uint32_t tb  = bV  + (kt >> 2) * 8192;
            uint32_t tbl = bVl + (kt >> 2) * 8192;
#pragma unroll
            for (int nb = 0; nb < 4; nb++) {
                uint32_t vh4[4], vl4[4];
                int row = nb * 16 + b_row_base;
                uint32_t off = row * 128 + ((b_cb + (kt & 3) * 32) ^ ((row & 7) << 4));
                LDSM4(vh4, tb + off);
                LDSM4(vl4, tbl + off);
                MMA16816(O[2*nb],   ah4, vh4);
                MMA16816(O[2*nb+1], ah4, vh4 + 2);
                MMA16816(O[2*nb],   ah4, vl4);
                MMA16816(O[2*nb+1], ah4, vl4 + 2);
                MMA16816(O[2*nb],   al4, vh4);
                MMA16816(O[2*nb+1], al4, vh4 + 2);
            }
        }
        __syncthreads();
    }

#pragma unroll
    for (int o = 1; o <= 2; o <<= 1) {
        lA += __shfl_xor_sync(0xffffffffu, lA, o);
        lB += __shfl_xor_sync(0xffffffffu, lB, o);
    }
    float iA = lA > 0.f ? 1.f / lA : 0.f;
    float iB = lB > 0.f ? 1.f / lB : 0.f;
    size_t rowA = (size_t)(b * 1024 + m0 + wid * 16 + rA);
#pragma unroll
    for (int nt = 0; nt < 8; nt++) {
        int c = nt * 8 + (lane & 3) * 2;
        __nv_bfloat16 h0, l0, h1, l1;
        float v0 = O[nt][0] * iA, v1 = O[nt][1] * iA;
        split2(v0, h0, l0); split2(v1, h1, l1);
        size_t idx = rowA * 768 + h * 64 + c;
        ushort2 hh; hh.x = (ushort)bfu(h0); hh.y = (ushort)bfu(h1);
        ushort2 ll; ll.x = (ushort)bfu(l0); ll.y = (ushort)bfu(l1);
        *(ushort2*)(Oh_ + idx) = hh;
        *(ushort2*)(Ol_ + idx) = ll;
        v0 = O[nt][2] * iB; v1 = O[nt][3] * iB;
        split2(v0, h0, l0); split2(v1, h1, l1);
        idx = (rowA + 8) * 768 + h * 64 + c;
        hh.x = (ushort)bfu(h0); hh.y = (ushort)bfu(h1);
        ll.x = (ushort)bfu(l0); ll.y = (ushort)bfu(l1);
        *(ushort2*)(Oh_ + idx) = hh;
        *(ushort2*)(Ol_ + idx) = ll;
    }
}

// ---------------------------------------------------------------------------
// LayerNorm over width 768. fp32 and/or bf16 hi/lo outputs. Optional pos add.
// ---------------------------------------------------------------------------
__global__ void ln_kernel(const float* __restrict__ in, const float* __restrict__ g,
                          float* __restrict__ outf,
                          __nv_bfloat16* __restrict__ outhi, __nv_bfloat16* __restrict__ outlo,
                          const float* __restrict__ pos_h, const float* __restrict__ pos_w,
                          const int* __restrict__ ppos)
{
    int row = blockIdx.x;
    int tid = threadIdx.x;
    const float* xr = in + (size_t)row * 768;
    float v[3]; float s = 0.f, q = 0.f;
#pragma unroll
    for (int i = 0; i < 3; i++) { float t = xr[tid + i*256]; v[i] = t; s += t; q += t*t; }
#pragma unroll
    for (int o = 16; o; o >>= 1) {
        s += __shfl_xor_sync(0xffffffffu, s, o);
        q += __shfl_xor_sync(0xffffffffu, q, o);
    }
    __shared__ float shs[8], shq[8], st[2];
    int w = tid >> 5;
    if ((tid & 31) == 0) { shs[w] = s; shq[w] = q; }
    __syncthreads();
    if (tid == 0) {
        float S = 0.f, Q = 0.f;
#pragma unroll
        for (int i = 0; i < 8; i++) { S += shs[i]; Q += shq[i]; }
        float mu = S * (1.f/768.f);
        st[0] = mu;
        st[1] = rsqrtf(Q * (1.f/768.f) - mu*mu + 1e-5f);
    }
    __syncthreads();
    float mu = st[0], rs = st[1];
    int p0 = 0, p1 = 0;
    if (ppos) { p0 = ppos[row*2]; p1 = ppos[row*2 + 1]; }
#pragma unroll
    for (int i = 0; i < 3; i++) {
        int c = tid + i*256;
        float y = (v[i] - mu) * rs * g[c];
        if (ppos) y += pos_h[p0*768 + c] + pos_w[p1*768 + c];
        size_t idx = (size_t)row*768 + c;
        if (outf) outf[idx] = y;
        if (outhi) {
            __nv_bfloat16 hh, ll; split2(y, hh, ll);
            outhi[idx] = hh; outlo[idx] = ll;
        }
    }
}

// ---------------------------------------------------------------------------
// Fused QKV postprocess: one launch does q-rms, k-rms, v transpose.
// block = token, 384 threads (12 warps = 12 heads).
// ---------------------------------------------------------------------------
__global__ void rmsT_all(const float* __restrict__ qkv,
                         const float* __restrict__ qg, const float* __restrict__ kg,
                         __nv_bfloat16* __restrict__ qh, __nv_bfloat16* __restrict__ ql,
                         __nv_bfloat16* __restrict__ kh, __nv_bfloat16* __restrict__ kl,
                         __nv_bfloat16* __restrict__ vh, __nv_bfloat16* __restrict__ vl)
{
    int token = blockIdx.x;
    int b = token >> 10, n = token & 1023;
    int w = threadIdx.x >> 5, lane = threadIdx.x & 31;
    const float* base = qkv + (size_t)token * 2304 + w * 64;
    __nv_bfloat16 hh, ll;

    // Q
    {
        float v0 = base[lane], v1 = base[lane + 32];
        float ss = v0*v0 + v1*v1;
#pragma unroll
        for (int o = 16; o; o >>= 1) ss += __shfl_xor_sync(0xffffffffu, ss, o);
        float inv = 8.0f / fmaxf(sqrtf(ss), 1e-12f);
        v0 *= inv * qg[w*64 + lane];
        v1 *= inv * qg[w*64 + lane + 32];
        size_t dst = ((size_t)(b*12 + w) * 1024 + n) * 64;
        split2(v0, hh, ll); qh[dst + lane] = hh;      ql[dst + lane] = ll;
        split2(v1, hh, ll); qh[dst + lane + 32] = hh; ql[dst + lane + 32] = ll;
    }
    // K
    {
        float v0 = base[768 + lane], v1 = base[768 + lane + 32];
        float ss = v0*v0 + v1*v1;
#pragma unroll
        for (int o = 16; o; o >>= 1) ss += __shfl_xor_sync(0xffffffffu, ss, o);
        float inv = 8.0f / fmaxf(sqrtf(ss), 1e-12f);
        v0 *= inv * kg[w*64 + lane];
        v1 *= inv * kg[w*64 + lane + 32];
        size_t dst = ((size_t)(b*12 + w) * 1024 + n) * 64;
        split2(v0, hh, ll); kh[dst + lane] = hh;      kl[dst + lane] = ll;
        split2(v1, hh, ll); kh[dst + lane + 32] = hh; kl[dst + lane + 32] = ll;
    }
    // V (transposed [z][d][n])
    {
        float v0 = base[1536 + lane], v1 = base[1536 + lane + 32];
        size_t vb = ((size_t)(b*12 + w) * 64) * 1024 + n;
        split2(v0, hh, ll); vh[vb + (size_t)lane * 1024] = hh;        vl[vb + (size_t)lane * 1024] = ll;
        split2(v1, hh, ll); vh[vb + (size_t)(lane + 32) * 1024] = hh; vl[vb + (size_t)(lane + 32) * 1024] = ll;
    }
}

__global__ void rmsT_f32(const float* __restrict__ in, int ld, int off,
                         const float* __restrict__ g, float* __restrict__ outT)
{
    int token = blockIdx.x;
    int b = token >> 10, n = token & 1023;
    int w = threadIdx.x >> 5, lane = threadIdx.x & 31;
    const float* src = in + (size_t)token * ld + off + w*64;
    float v0 = src[lane], v1 = src[lane + 32];
    if (g) {
        float ss = v0*v0 + v1*v1;
#pragma unroll
        for (int o = 16; o; o >>= 1) ss += __shfl_xor_sync(0xffffffffu, ss, o);
        float inv = 8.0f / fmaxf(sqrtf(ss), 1e-12f);
        v0 *= inv * g[w*64 + lane];
        v1 *= inv * g[w*64 + lane + 32];
    }
    float* dst = outT + ((size_t)(b*12 + w) * 1024 + n) * 64;
    dst[lane] = v0; dst[lane + 32] = v1;
}

// ---------------------------------------------------------------------------
// Attention pooling (192 blocks), fp32 path.
// ---------------------------------------------------------------------------
__global__ void pool_attn_kernel(const float* __restrict__ pqn, const float* __restrict__ kT,
                                 const float* __restrict__ vT, const int* __restrict__ image_ids,
                                 const int* __restrict__ lengths, float* __restrict__ out)
{
    int idx = blockIdx.x;
    int h = idx % 12, img = (idx / 12) % 4, b = idx / 48;
    int tid = threadIdx.x;
    __shared__ float q[64];
    __shared__ float p[1024];
    __shared__ float sh[8];
    __shared__ float bs[2];
    __shared__ float sred[256];
    if (tid < 64) q[tid] = pqn[h*64 + tid];
    __syncthreads();

    const float* K = kT + (size_t)(b*12 + h) * 1024 * 64;
    int len = lengths[b];
    float loc[4]; float mx = -FLT_MAX;
#pragma unroll
    for (int t = 0; t < 4; t++) {
        int j = tid + t*256;
        const float* kr = K + (size_t)j * 64;
        float dot = 0.f;
#pragma unroll
        for (int d = 0; d < 64; d++) dot += q[d] * kr[d];
        bool ok = (image_ids[b*1024 + j] == img) && (j < len);
        loc[t] = ok ? dot : -FLT_MAX;
        mx = fmaxf(mx, loc[t]);
    }
#pragma unroll
    for (int o = 16; o; o >>= 1) mx = fmaxf(mx, __shfl_xor_sync(0xffffffffu, mx, o));
    int w = tid >> 5;
    if ((tid & 31) == 0) sh[w] = mx;
    __syncthreads();
    if (tid == 0) { float mm = sh[0]; for (int i = 1; i < 8; i++) mm = fmaxf(mm, sh[i]); bs[0] = mm; }
    __syncthreads();
    mx = bs[0];
    float s = 0.f;
#pragma unroll
    for (int t = 0; t < 4; t++) {
        float e = __expf(loc[t] - mx);
        p[tid + t*256] = e;
        s += e;
    }
#pragma unroll
    for (int o = 16; o; o >>= 1) s += __shfl_xor_sync(0xffffffffu, s, o);
    if ((tid & 31) == 0) sh[w] = s;
    __syncthreads();
    if (tid == 0) { float ss = 0.f; for (int i = 0; i < 8; i++) ss += sh[i]; bs[1] = 1.f / ss; }
    __syncthreads();
    float inv = bs[1];

    const float* V = vT + (size_t)(b*12 + h) * 1024 * 64;
    int d = tid & 63, grp = tid >> 6;
    float acc = 0.f;
    for (int j = grp; j < 1024; j += 4) acc += p[j] * V[(size_t)j*64 + d];
    sred[tid] = acc;
    __syncthreads();
    if (grp == 0) {
        float r = (sred[d] + sred[d + 64]) + (sred[d + 128] + sred[d + 192]);
        out[(size_t)(b*4 + img) * 768 + h*64 + d] = r * inv;
    }
}

__global__ void rms_vec_kernel(const float* __restrict__ in, const float* __restrict__ g,
                               float* __restrict__ out)
{
    int w = threadIdx.x >> 5, lane = threadIdx.x & 31;
    float v0 = in[w*64 + lane], v1 = in[w*64 + lane + 32];
    float ss = v0*v0 + v1*v1;
#pragma unroll
    for (int o = 16; o; o >>= 1) ss += __shfl_xor_sync(0xffffffffu, ss, o);
    float inv = 8.0f / fmaxf(sqrtf(ss), 1e-12f);
    out[w*64 + lane]      = v0 * inv * g[w*64 + lane];
    out[w*64 + lane + 32] = v1 * inv * g[w*64 + lane + 32];
}

__global__ void small_gemm_kernel(const float* __restrict__ A, const float* __restrict__ W,
                                  const float* __restrict__ addvec, float* __restrict__ C,
                                  int N, int K)
{
    __shared__ float a[768];
    int row = blockIdx.y;
    for (int i = threadIdx.x; i < K; i += 256) a[i] = A[(size_t)row*K + i];
    __syncthreads();
    int n = blockIdx.x * 256 + threadIdx.x;
    if (n >= N) return;
    float acc = addvec ? addvec[n] : 0.f;
#pragma unroll 4
    for (int k = 0; k < K; k++) acc += a[k] * W[(size_t)k*N + n];
    C[(size_t)row*N + n] = acc;
}

// ---------------------------------------------------------------------------
// Host side
// ---------------------------------------------------------------------------
extern "C" void kernel_launch(void* const* d_in, const int* in_sizes, int n_in,
                              void* d_out, int out_size)
{
    (void)in_sizes; (void)n_in; (void)out_size;
    const float* patches    = (const float*)d_in[0];
    const int*   ppos       = (const int*)  d_in[1];
    const int*   image_ids  = (const int*)  d_in[2];
    const int*   lengths    = (const int*)  d_in[3];
    const float* emb_ln_g   = (const float*)d_in[4];
    const float* W_emb      = (const float*)d_in[5];
    const float* b_emb      = (const float*)d_in[6];
    const float* emb_ln2_g  = (const float*)d_in[7];
    const float* pos_h      = (const float*)d_in[8];
    const float* pos_w      = (const float*)d_in[9];
    const float* ln_attn_g  = (const float*)d_in[10];
    const float* Wq         = (const float*)d_in[11];
    const float* Wkv        = (const float*)d_in[12];
    const float* qn_g       = (const float*)d_in[13];
    const float* kn_g       = (const float*)d_in[14];
    const float* Wo         = (const float*)d_in[15];
    const float* ln_ff_g    = (const float*)d_in[16];
    const float* W1         = (const float*)d_in[17];
    const float* b1         = (const float*)d_in[18];
    const float* W2         = (const float*)d_in[19];
    const float* b2         = (const float*)d_in[20];
    const float* final_ln_g = (const float*)d_in[21];
    const float* pool_q     = (const float*)d_in[22];
    const float* pool_ln_g  = (const float*)d_in[23];
    const float* pWq        = (const float*)d_in[24];
    const float* pWkv       = (const float*)d_in[25];
    const float* p_qn_g     = (const float*)d_in[26];
    const float* p_kn_g     = (const float*)d_in[27];
    const float* pWo        = (const float*)d_in[28];
    const float* head_ln_g  = (const float*)d_in[29];
    const float* W_head     = (const float*)d_in[30];

    float *x, *qkv, *kTf, *vTf, *sm, *pattn, *pool, *pln;
    __nv_bfloat16 *xnh, *xnl, *tmph, *tmpl, *qTh, *qTl, *kTh, *kTl, *vTth, *vTtl;
    __nv_bfloat16 *aoh, *aol, *whi, *wlo;
    cudaGetSymbolAddress((void**)&x,    g_x);
    cudaGetSymbolAddress((void**)&qkv,  g_qkv);
    cudaGetSymbolAddress((void**)&kTf,  g_kTf);
    cudaGetSymbolAddress((void**)&vTf,  g_vTf);
    cudaGetSymbolAddress((void**)&sm,   g_sm);
    cudaGetSymbolAddress((void**)&pattn,g_pattn);
    cudaGetSymbolAddress((void**)&pool, g_pool);
    cudaGetSymbolAddress((void**)&pln,  g_pln);
    cudaGetSymbolAddress((void**)&xnh,  g_xnh);
    cudaGetSymbolAddress((void**)&xnl,  g_xnl);
    cudaGetSymbolAddress((void**)&tmph, g_tmph);
    cudaGetSymbolAddress((void**)&tmpl, g_tmpl);
    cudaGetSymbolAddress((void**)&qTh,  g_qTh);
    cudaGetSymbolAddress((void**)&qTl,  g_qTl);
    cudaGetSymbolAddress((void**)&kTh,  g_kTh);
    cudaGetSymbolAddress((void**)&kTl,  g_kTl);
    cudaGetSymbolAddress((void**)&vTth, g_vTth);
    cudaGetSymbolAddress((void**)&vTtl, g_vTtl);
    cudaGetSymbolAddress((void**)&aoh,  g_aoh);
    cudaGetSymbolAddress((void**)&aol,  g_aol);
    cudaGetSymbolAddress((void**)&whi,  g_whi);
    cudaGetSymbolAddress((void**)&wlo,  g_wlo);

    constexpr int SMEM128 = 131072;
    constexpr int SMEM256 = 196608;
    cudaFuncSetAttribute(mma_gemm<128>, cudaFuncAttributeMaxDynamicSharedMemorySize, SMEM128);
    cudaFuncSetAttribute(mma_gemm<256>, cudaFuncAttributeMaxDynamicSharedMemorySize, SMEM256);
    cudaFuncSetAttribute(flash_attn,    cudaFuncAttributeMaxDynamicSharedMemorySize, FA_SMEM);

    // ---- Convert + transpose weights ----
    dim3 wb(32, 8);
    wconv_kernel<<<dim3(DIM/32,  DIM/32),  wb>>>(W_emb, whi + WOFF_EMB, wlo + WOFF_EMB, DIM, DIM);
    for (int l = 0; l < 4; l++) {
        wconv_kernel<<<dim3(DIM/32,    DIM/32),  wb>>>(Wq  + (size_t)l*DIM*DIM,    whi + WOFF_Q(l),  wlo + WOFF_Q(l),  DIM,  DIM);
        wconv_kernel<<<dim3(2*DIM/32,  DIM/32),  wb>>>(Wkv + (size_t)l*DIM*2*DIM,  whi + WOFF_Q(l) + 589824ULL, wlo + WOFF_Q(l) + 589824ULL, DIM, 2*DIM);
        wconv_kernel<<<dim3(DIM/32,    DIM/32),  wb>>>(Wo  + (size_t)l*DIM*DIM,    whi + WOFF_O(l),  wlo + WOFF_O(l),  DIM,  DIM);
        wconv_kernel<<<dim3(MLPD/32,   DIM/32),  wb>>>(W1  + (size_t)l*DIM*MLPD,   whi + WOFF_W1(l), wlo + WOFF_W1(l), DIM,  MLPD);
        wconv_kernel<<<dim3(DIM/32,    MLPD/32), wb>>>(W2  + (size_t)l*MLPD*DIM,   whi + WOFF_W2(l), wlo + WOFF_W2(l), MLPD, DIM);
    }
    wconv_kernel<<<dim3(2*DIM/32, DIM/32), wb>>>(pWkv, whi + WOFF_PKV, wlo + WOFF_PKV, DIM, 2*DIM);

    auto G128 = [&](const __nv_bfloat16* ah, const __nv_bfloat16* al,
                    const __nv_bfloat16* bh, const __nv_bfloat16* bl,
                    const float* bias, const float* res,
                    float* C, __nv_bfloat16* Chi, __nv_bfloat16* Clo,
                    int M, int N, int K, int flags) {
        mma_gemm<128><<<dim3(N/128, M/128), 256, SMEM128>>>(ah, al, bh, bl, bias, res, C, Chi, Clo, M, N, K, flags);
    };
    auto G256 = [&](const __nv_bfloat16* ah, const __nv_bfloat16* al,
                    const __nv_bfloat16* bh, const __nv_bfloat16* bl,
                    const float* bias, const float* res,
                    float* C, __nv_bfloat16* Chi, __nv_bfloat16* Clo,
                    int M, int N, int K, int flags) {
        mma_gemm<256><<<dim3(N/128, M/256), 256, SMEM256>>>(ah, al, bh, bl, bias, res, C, Chi, Clo, M, N, K, flags);
    };

    // ---- Embedding ----
    ln_kernel<<<TOKS, 256>>>(patches, emb_ln_g, nullptr, xnh, xnl, nullptr, nullptr, nullptr);
    G128(xnh, xnl, whi + WOFF_EMB, wlo + WOFF_EMB, b_emb, nullptr, x, nullptr, nullptr, TOKS, DIM, DIM, FBIAS);
    ln_kernel<<<TOKS, 256>>>(x, emb_ln2_g, x, nullptr, nullptr, pos_h, pos_w, ppos);

    // ---- Transformer layers ----
    for (int l = 0; l < 4; l++) {
        ln_kernel<<<TOKS, 256>>>(x, ln_attn_g + l*DIM, nullptr, xnh, xnl, nullptr, nullptr, nullptr);
        G256(xnh, xnl, whi + WOFF_Q(l), wlo + WOFF_Q(l), nullptr, nullptr, qkv, nullptr, nullptr,
             TOKS, 2304, DIM, 0);
        rmsT_all<<<TOKS, 384>>>(qkv, qn_g + l*DIM, kn_g + l*DIM, qTh, qTl, kTh, kTl, vTth, vTtl);
        flash_attn<<<dim3(8, BH), 256, FA_SMEM>>>(qTh, qTl, kTh, kTl, vTth, vTtl,
                                                  image_ids, lengths, aoh, aol);
        G128(aoh, aol, whi + WOFF_O(l), wlo + WOFF_O(l), nullptr, x, x, nullptr, nullptr,
             TOKS, DIM, DIM, FRES);
        ln_kernel<<<TOKS, 256>>>(x, ln_ff_g + l*DIM, nullptr, xnh, xnl, nullptr, nullptr, nullptr);
        G256(xnh, xnl, whi + WOFF_W1(l), wlo + WOFF_W1(l), b1 + l*MLPD, nullptr,
             nullptr, tmph, tmpl, TOKS, MLPD, DIM, FBIAS|FGELU);
        G128(tmph, tmpl, whi + WOFF_W2(l), wlo + WOFF_W2(l), b2 + l*DIM, x,
             x, nullptr, nullptr, TOKS, DIM, MLPD, FBIAS|FRES);
    }

    // ---- Final LN ----
    ln_kernel<<<TOKS, 256>>>(x, final_ln_g, nullptr, xnh, xnl, nullptr, nullptr, nullptr);

    // ---- Attention pooling ----
    ln_kernel<<<1, 256>>>(pool_q, pool_ln_g, sm, nullptr, nullptr, nullptr, nullptr, nullptr);
    small_gemm_kernel<<<dim3(3, 1), 256>>>(sm, pWq, nullptr, sm + 768, DIM, DIM);
    rms_vec_kernel<<<1, 384>>>(sm + 768, p_qn_g, sm + 1536);
    G256(xnh, xnl, whi + WOFF_PKV, wlo + WOFF_PKV, nullptr, nullptr, qkv, nullptr, nullptr,
         TOKS, 1536, DIM, 0);
    rmsT_f32<<<TOKS, 384>>>(qkv, 1536, 0,   p_kn_g, kTf);
    rmsT_f32<<<TOKS, 384>>>(qkv, 1536, 768, nullptr, vTf);
    pool_attn_kernel<<<NB*IMGS*NHEAD, 256>>>(sm + 1536, kTf, vTf, image_ids, lengths, pattn);
    small_gemm_kernel<<<dim3(3, 16), 256>>>(pattn, pWo, pool_q, pool, DIM, DIM);
    ln_kernel<<<16, 256>>>(pool, head_ln_g, pln, nullptr, nullptr, nullptr, nullptr, nullptr);
    small_gemm_kernel<<<dim3(4, 16), 256>>>(pln, W_head, nullptr, (float*)d_out, NCLS, DIM);
}

// round 7
// speedup vs baseline: 3.4534x; 1.2474x over previous
#include <cuda_runtime.h>
#include <cuda_bf16.h>
#include <cuda_fp16.h>
#include <math.h>
#include <float.h>
#include <stdint.h>

// ---------------------------------------------------------------------------
// Problem constants
// ---------------------------------------------------------------------------
#define NB      4
#define NTOK    1024
#define DIM     768
#define NHEAD   12
#define DHEAD   64
#define MLPD    3072
#define IMGS    4
#define NCLS    1000
#define TOKS    (NB*NTOK)
#define BH      (NB*NHEAD)

#define FBIAS 1
#define FGELU 2
#define FRES  4

#define WOFF_EMB 0ULL
#define WPERL    7077888ULL
#define WOFF_L(l)   (589824ULL + (unsigned long long)(l)*WPERL)
#define WOFF_Q(l)   (WOFF_L(l) + 0ULL)
#define WOFF_O(l)   (WOFF_L(l) + 1769472ULL)
#define WOFF_W1(l)  (WOFF_L(l) + 2359296ULL)
#define WOFF_W2(l)  (WOFF_L(l) + 4718592ULL)
#define WOFF_PKV    (589824ULL + 4ULL*WPERL)
#define WTOTAL      30081024ULL

// ---------------------------------------------------------------------------
// Device scratch
// ---------------------------------------------------------------------------
__device__ float g_x   [TOKS*DIM];
__device__ float g_qkv [TOKS*2304];
__device__ __half g_xnh[TOKS*DIM],  g_xnl[TOKS*DIM];
__device__ __half g_tmph[TOKS*MLPD], g_tmpl[TOKS*MLPD];
__device__ __half g_aoh[TOKS*DIM], g_aol[TOKS*DIM];
__device__ __nv_bfloat16 g_qTh[BH*NTOK*DHEAD], g_qTl[BH*NTOK*DHEAD];
__device__ __nv_bfloat16 g_kTh[BH*NTOK*DHEAD], g_kTl[BH*NTOK*DHEAD];
__device__ __nv_bfloat16 g_vTth[BH*DHEAD*NTOK], g_vTtl[BH*DHEAD*NTOK];
__device__ float g_kTf[BH*NTOK*DHEAD], g_vTf[BH*NTOK*DHEAD];
__device__ float g_sm  [4096];
__device__ float g_pattn[16*DIM];
__device__ float g_pool [16*DIM];
__device__ float g_pln  [16*DIM];
__device__ __half g_w[WTOTAL];

// ---------------------------------------------------------------------------
// Helpers
// ---------------------------------------------------------------------------
__device__ __forceinline__ uint32_t smem_u32(const void* p) {
    uint32_t a;
    asm("{ .reg .u64 t; cvta.to.shared.u64 t, %1; cvt.u32.u64 %0, t; }" : "=r"(a) : "l"(p));
    return a;
}

#define LDSM4(r, addr) \
    asm volatile("ldmatrix.sync.aligned.m8n8.x4.shared.b16 {%0,%1,%2,%3}, [%4];" \
        : "=r"((r)[0]), "=r"((r)[1]), "=r"((r)[2]), "=r"((r)[3]) : "r"(addr))

#define MMA16816(d, a, b) \
    asm volatile("mma.sync.aligned.m16n8k16.row.col.f32.bf16.bf16.f32 " \
        "{%0,%1,%2,%3}, {%4,%5,%6,%7}, {%8,%9}, {%0,%1,%2,%3};" \
        : "+f"((d)[0]), "+f"((d)[1]), "+f"((d)[2]), "+f"((d)[3]) \
        : "r"((a)[0]), "r"((a)[1]), "r"((a)[2]), "r"((a)[3]), "r"((b)[0]), "r"((b)[1]))

#define MMAH16816(d, a, b) \
    asm volatile("mma.sync.aligned.m16n8k16.row.col.f32.f16.f16.f32 " \
        "{%0,%1,%2,%3}, {%4,%5,%6,%7}, {%8,%9}, {%0,%1,%2,%3};" \
        : "+f"((d)[0]), "+f"((d)[1]), "+f"((d)[2]), "+f"((d)[3]) \
        : "r"((a)[0]), "r"((a)[1]), "r"((a)[2]), "r"((a)[3]), "r"((b)[0]), "r"((b)[1]))

#define CPA16(dst, src) \
    asm volatile("cp.async.cg.shared.global [%0], [%1], 16;" :: "r"(dst), "l"(src))
#define CP_COMMIT() asm volatile("cp.async.commit_group;" ::: "memory")
#define CP_WAIT0()  asm volatile("cp.async.wait_group 0;" ::: "memory")
#define CP_WAIT1()  asm volatile("cp.async.wait_group 1;" ::: "memory")

__device__ __forceinline__ void split2(float v, __nv_bfloat16& h, __nv_bfloat16& l) {
    h = __float2bfloat16(v);
    l = __float2bfloat16(v - __bfloat162float(h));
}
__device__ __forceinline__ void split2h(float v, __half& h, __half& l) {
    h = __float2half(v);
    l = __float2half(v - __half2float(h));
}
__device__ __forceinline__ uint32_t bfu(__nv_bfloat16 b) { return (uint32_t)__bfloat16_as_ushort(b); }
__device__ __forceinline__ uint32_t hfu(__half b) { return (uint32_t)__half_as_ushort(b); }

template<typename T>
__device__ __forceinline__ void cpa_tile(uint32_t smbase, const T* __restrict__ g,
                                         int ldk, int chunks, int tid)
{
    for (int i = tid; i < chunks; i += 256) {
        int r = i >> 3, c = i & 7;
        uint32_t off = r * 128 + c * 16;
        uint32_t sw = off ^ ((off >> 3) & 0x70);
        CPA16(smbase + sw, g + (size_t)r * ldk + c * 8);
    }
}

// ---------------------------------------------------------------------------
// Weight convert+transpose: W[K,N] fp32 -> fp16 [N,K]
// ---------------------------------------------------------------------------
__global__ void wconv_kernel(const float* __restrict__ W, __half* __restrict__ out,
                             int K, int N)
{
    __shared__ float t[32][33];
    int n0 = blockIdx.x * 32, k0 = blockIdx.y * 32;
    int tx = threadIdx.x, ty = threadIdx.y;
#pragma unroll
    for (int r = 0; r < 4; r++)
        t[ty + r*8][tx] = W[(size_t)(k0 + ty + r*8) * N + n0 + tx];
    __syncthreads();
#pragma unroll
    for (int r = 0; r < 4; r++) {
        int n = n0 + ty + r*8, k = k0 + tx;
        out[(size_t)n * K + k] = __float2half(t[tx][ty + r*8]);
    }
}

// ---------------------------------------------------------------------------
// Pipelined mma.sync fp16 GEMM, 2-pass (A fp16 hi/lo, B fp16 weights).
// MT=128: 8 warps 2Mx4N. MT=256: 8 warps 4Mx2N.
// ---------------------------------------------------------------------------
template<int MT>
__global__ void __launch_bounds__(256, 1) mma_gemm(
    const __half* __restrict__ Ahi, const __half* __restrict__ Alo,
    const __half* __restrict__ B,
    const float* __restrict__ bias, const float* __restrict__ res,
    float* __restrict__ C, __half* __restrict__ Chi, __half* __restrict__ Clo,
    int M, int N, int K, int flags)
{
    constexpr int WM   = MT / 64;
    constexpr int NQ   = (WM == 2) ? 2 : 4;
    constexpr int NTL  = 2 * NQ;
    constexpr int NCOL = NQ * 16;
    constexpr int A_SZ = MT * 128;
    constexpr int STG  = 2 * A_SZ + 16384;

    extern __shared__ char smem[];
    uint32_t uS = smem_u32(smem);

    const int tid = threadIdx.x;
    const int wid = tid >> 5, lane = tid & 31;
    const int m0 = blockIdx.y * MT, n0 = blockIdx.x * 128;
    const int wm = wid & (WM - 1), wn = wid / WM;

    const __half* Azh = Ahi + (size_t)m0 * K;
    const __half* Azl = Alo + (size_t)m0 * K;
    const __half* Bz  = B   + (size_t)n0 * K;

    float acc[4][NTL][4] = {};

    const int a_row = wm * 64 + (lane & 15);
    const int a_cb  = (lane >> 4) * 16;
    const int b_row = wn * NCOL + (lane & 7) + ((lane >> 4) << 3);
    const int b_cb  = ((lane >> 3) & 1) * 16;

    const int KT = K >> 6;
    {
        cpa_tile(uS,              Azh, K, MT * 8, tid);
        cpa_tile(uS + A_SZ,       Azl, K, MT * 8, tid);
        cpa_tile(uS + 2 * A_SZ,   Bz,  K, 1024,   tid);
        CP_COMMIT();
    }

    for (int kt = 0; kt < KT; kt++) {
        if (kt + 1 < KT) {
            uint32_t base = uS + ((kt + 1) & 1) * STG;
            cpa_tile(base,            Azh + (kt + 1) * 64, K, MT * 8, tid);
            cpa_tile(base + A_SZ,     Azl + (kt + 1) * 64, K, MT * 8, tid);
            cpa_tile(base + 2 * A_SZ, Bz  + (kt + 1) * 64, K, 1024,   tid);
            CP_COMMIT();
            CP_WAIT1();
        } else {
            CP_WAIT0();
        }
        __syncthreads();

        uint32_t bAh = uS + (kt & 1) * STG;
        uint32_t bAl = bAh + A_SZ;
        uint32_t bB  = bAh + 2 * A_SZ;

#pragma unroll
        for (int ks = 0; ks < 4; ks++) {
            uint32_t ah[4][4], al[4][4], bh[NQ][4];
#pragma unroll
            for (int mt = 0; mt < 4; mt++) {
                int row = a_row + mt * 16;
                uint32_t off = row * 128 + ((a_cb + ks * 32) ^ ((row & 7) << 4));
                LDSM4(ah[mt], bAh + off);
                LDSM4(al[mt], bAl + off);
            }
#pragma unroll
            for (int q = 0; q < NQ; q++) {
                int row = b_row + q * 16;
                uint32_t off = row * 128 + ((b_cb + ks * 32) ^ ((row & 7) << 4));
                LDSM4(bh[q], bB + off);
            }
#pragma unroll
            for (int mt = 0; mt < 4; mt++)
#pragma unroll
                for (int nt = 0; nt < NTL; nt++)
                    MMAH16816(acc[mt][nt], ah[mt], &bh[nt >> 1][(nt & 1) * 2]);
#pragma unroll
            for (int mt = 0; mt < 4; mt++)
#pragma unroll
                for (int nt = 0; nt < NTL; nt++)
                    MMAH16816(acc[mt][nt], al[mt], &bh[nt >> 1][(nt & 1) * 2]);
        }
        __syncthreads();
    }

    const int rbase = m0 + wm * 64;
#pragma unroll
    for (int mt = 0; mt < 4; mt++) {
#pragma unroll
        for (int nt = 0; nt < NTL; nt++) {
            int c = n0 + wn * NCOL + nt * 8 + (lane & 3) * 2;
            float bv0 = 0.f, bv1 = 0.f;
            if (flags & FBIAS) { bv0 = bias[c]; bv1 = bias[c + 1]; }
#pragma unroll
            for (int half = 0; half < 2; half++) {
                int r = rbase + mt * 16 + (lane >> 2) + half * 8;
                float v0 = acc[mt][nt][half * 2 + 0];
                float v1 = acc[mt][nt][half * 2 + 1];
                if (flags & FBIAS) { v0 += bv0; v1 += bv1; }
                if (flags & FGELU) {
                    v0 = 0.5f * v0 * (1.f + erff(v0 * 0.70710678118654752f));
                    v1 = 0.5f * v1 * (1.f + erff(v1 * 0.70710678118654752f));
                }
                long idx = (long)r * N + c;
                if (flags & FRES) { v0 += res[idx]; v1 += res[idx + 1]; }
                if (C) *(float2*)(C + idx) = make_float2(v0, v1);
                if (Chi) {
                    __half h0, l0, h1, l1;
                    split2h(v0, h0, l0); split2h(v1, h1, l1);
                    ushort2 hh; hh.x = (ushort)hfu(h0); hh.y = (ushort)hfu(h1);
                    ushort2 ll; ll.x = (ushort)hfu(l0); ll.y = (ushort)hfu(l1);
                    *(ushort2*)(Chi + idx) = hh;
                    *(ushort2*)(Clo + idx) = ll;
                }
            }
        }
    }
}

// ---------------------------------------------------------------------------
// Fused flash attention (bf16 3-pass, unchanged core; fp16 hi/lo output).
// ---------------------------------------------------------------------------
#define FA_SMEM 165504

__global__ void __launch_bounds__(256, 1) flash_attn(
    const __nv_bfloat16* __restrict__ Qh_, const __nv_bfloat16* __restrict__ Ql_,
    const __nv_bfloat16* __restrict__ Kh_, const __nv_bfloat16* __restrict__ Kl_,
    const __nv_bfloat16* __restrict__ Vh_, const __nv_bfloat16* __restrict__ Vl_,
    const int* __restrict__ image_ids, const int* __restrict__ lengths,
    __half* __restrict__ Oh_, __half* __restrict__ Ol_)
{
    extern __shared__ char smem[];
    uint32_t uS = smem_u32(smem);
    const int tid = threadIdx.x, wid = tid >> 5, lane = tid & 31;
    const int z = blockIdx.y, b = z / 12, h = z % 12;
    const int m0 = blockIdx.x * 128;

    int* s_cmin   = (int*)(smem + 163840);
    int* s_cmax   = s_cmin + 8;
    int* s_jlist  = s_cmax + 8;
    int* s_meta   = s_jlist + 8;
    int* s_imgRow = s_meta + 8;
    int* s_imgCol = s_imgRow + 128;

    const int len = lengths[b];

    {
        int4 v = *(const int4*)(image_ids + b*1024 + wid*128 + lane*4);
        int mn = min(min(v.x, v.y), min(v.z, v.w));
        int mx = max(max(v.x, v.y), max(v.z, v.w));
#pragma unroll
        for (int o = 16; o; o >>= 1) {
            mn = min(mn, __shfl_xor_sync(0xffffffffu, mn, o));
            mx = max(mx, __shfl_xor_sync(0xffffffffu, mx, o));
        }
        if (lane == 0) { s_cmin[wid] = mn; s_cmax[wid] = mx; }
    }
    if (tid < 128) s_imgRow[tid] = image_ids[b*1024 + m0 + tid];
    __syncthreads();
    if (tid == 0) {
        int rmin = s_cmin[blockIdx.x], rmax = s_cmax[blockIdx.x];
        int nj = 0;
        for (int jb = 0; jb < 8; jb++)
            if (jb * 128 < len && s_cmax[jb] >= rmin && s_cmin[jb] <= rmax)
                s_jlist[nj++] = jb;
        s_meta[0] = nj;
    }
    __syncthreads();
    const int nj = s_meta[0];

    const size_t qoff = ((size_t)z * 1024 + m0) * 64;
    cpa_tile(uS,         Qh_ + qoff, 64, 1024, tid);
    cpa_tile(uS + 16384, Ql_ + qoff, 64, 1024, tid);

    auto prefetch = [&](int t) {
        int jb = s_jlist[t];
        int st = t & 1;
        uint32_t base = uS + 32768 + st * 65536;
        size_t koff = ((size_t)z * 1024 + jb * 128) * 64;
        cpa_tile(base,         Kh_ + koff, 64, 1024, tid);
        cpa_tile(base + 16384, Kl_ + koff, 64, 1024, tid);
        const __nv_bfloat16* vh = Vh_ + (size_t)z * 64 * 1024 + jb * 128;
        const __nv_bfloat16* vl = Vl_ + (size_t)z * 64 * 1024 + jb * 128;
        for (int i = tid; i < 1024; i += 256) {
            int r = i >> 4, c = i & 15;
            int kc = c >> 3, cc = c & 7;
            uint32_t off = r * 128 + cc * 16;
            uint32_t sw = off ^ ((off >> 3) & 0x70);
            CPA16(base + 32768 + kc * 8192 + sw, vh + (size_t)r * 1024 + c * 8);
            CPA16(base + 49152 + kc * 8192 + sw, vl + (size_t)r * 1024 + c * 8);
        }
        if (tid < 128) s_imgCol[st * 128 + tid] = image_ids[b*1024 + jb*128 + tid];
    };
    prefetch(0);
    CP_COMMIT();

    float O[8][4] = {};
    float mA = -FLT_MAX, mB = -FLT_MAX, lA = 0.f, lB = 0.f;
    uint32_t qh[4][4], ql[4][4];
    bool qloaded = false;

    const int rA = lane >> 2;
    const int imgA = s_imgRow[wid * 16 + rA];
    const int imgB = s_imgRow[wid * 16 + rA + 8];

    const int a_row = wid * 16 + (lane & 15);
    const int a_cb  = (lane >> 4) * 16;
    const int b_row_base = (lane & 7) + ((lane >> 4) << 3);
    const int b_cb  = ((lane >> 3) & 1) * 16;

    for (int t = 0; t < nj; t++) {
        if (t + 1 < nj) { prefetch(t + 1); CP_COMMIT(); CP_WAIT1(); }
        else CP_WAIT0();
        __syncthreads();

        if (!qloaded) {
            qloaded = true;
#pragma unroll
            for (int ks = 0; ks < 4; ks++) {
                uint32_t off = a_row * 128 + ((a_cb + ks * 32) ^ ((a_row & 7) << 4));
                LDSM4(qh[ks], uS + off);
                LDSM4(ql[ks], uS + 16384 + off);
            }
        }

        int st = t & 1;
        uint32_t bK  = uS + 32768 + st * 65536;
        uint32_t bKl = bK + 16384;
        uint32_t bV  = bK + 32768;
        uint32_t bVl = bK + 49152;
        int jb = s_jlist[t];
        int j0 = jb * 128;
        const int* imgC = s_imgCol + st * 128;

        float S[16][4] = {};
#pragma unroll
        for (int ks = 0; ks < 4; ks++) {
#pragma unroll
            for (int nb = 0; nb < 8; nb++) {
                uint32_t bh4[4], bl4[4];
                int row = nb * 16 + b_row_base;
                uint32_t off = row * 128 + ((b_cb + ks * 32) ^ ((row & 7) << 4));
                LDSM4(bh4, bK + off);
                LDSM4(bl4, bKl + off);
                MMA16816(S[2*nb],   qh[ks], bh4);
                MMA16816(S[2*nb+1], qh[ks], bh4 + 2);
                MMA16816(S[2*nb],   qh[ks], bl4);
                MMA16816(S[2*nb+1], qh[ks], bl4 + 2);
                MMA16816(S[2*nb],   ql[ks], bh4);
                MMA16816(S[2*nb+1], ql[ks], bh4 + 2);
            }
        }

        float mnA = mA, mnB = mB;
#pragma unroll
        for (int nt = 0; nt < 16; nt++) {
            int c0 = nt * 8 + (lane & 3) * 2;
            int i0 = imgC[c0], i1 = imgC[c0 + 1];
            bool v0 = (j0 + c0) < len, v1 = (j0 + c0 + 1) < len;
            if (i0 == imgA && v0) mnA = fmaxf(mnA, S[nt][0]);
            if (i1 == imgA && v1) mnA = fmaxf(mnA, S[nt][1]);
            if (i0 == imgB && v0) mnB = fmaxf(mnB, S[nt][2]);
            if (i1 == imgB && v1) mnB = fmaxf(mnB, S[nt][3]);
        }
#pragma unroll
        for (int o = 1; o <= 2; o <<= 1) {
            mnA = fmaxf(mnA, __shfl_xor_sync(0xffffffffu, mnA, o));
            mnB = fmaxf(mnB, __shfl_xor_sync(0xffffffffu, mnB, o));
        }
        float scA = __expf(mA - mnA), scB = __expf(mB - mnB);
        mA = mnA; mB = mnB;
        lA *= scA; lB *= scB;
#pragma unroll
        for (int nt = 0; nt < 16; nt++) {
            int c0 = nt * 8 + (lane & 3) * 2;
            int i0 = imgC[c0], i1 = imgC[c0 + 1];
            bool v0 = (j0 + c0) < len, v1 = (j0 + c0 + 1) < len;
            float p0 = (i0 == imgA && v0) ? __expf(S[nt][0] - mnA) : 0.f;
            float p1 = (i1 == imgA && v1) ? __expf(S[nt][1] - mnA) : 0.f;
            float p2 = (i0 == imgB && v0) ? __expf(S[nt][2] - mnB) : 0.f;
            float p3 = (i1 == imgB && v1) ? __expf(S[nt][3] - mnB) : 0.f;
            lA += p0 + p1; lB += p2 + p3;
            S[nt][0] = p0; S[nt][1] = p1; S[nt][2] = p2; S[nt][3] = p3;
        }
#pragma unroll
        for (int nt = 0; nt < 8; nt++) {
            O[nt][0] *= scA; O[nt][1] *= scA; O[nt][2] *= scB; O[nt][3] *= scB;
        }

#pragma unroll
        for (int kt = 0; kt < 8; kt++) {
            uint32_t ah4[4], al4[4];
            {
                __nv_bfloat16 h0, l0, h1, l1;
                split2(S[2*kt][0], h0, l0);   split2(S[2*kt][1], h1, l1);
                ah4[0] = bfu(h0) | (bfu(h1) << 16);  al4[0] = bfu(l0) | (bfu(l1) << 16);
                split2(S[2*kt][2], h0, l0);   split2(S[2*kt][3], h1, l1);
                ah4[1] = bfu(h0) | (bfu(h1) << 16);  al4[1] = bfu(l0) | (bfu(l1) << 16);
                split2(S[2*kt+1][0], h0, l0); split2(S[2*kt+1][1], h1, l1);
                ah4[2] = bfu(h0) | (bfu(h1) << 16);  al4[2] = bfu(l0) | (bfu(l1) << 16);
                split2(S[2*kt+1][2], h0, l0); split2(S[2*kt+1][3], h1, l1);
                ah4[3] = bfu(h0) | (bfu(h1) << 16);  al4[3] = bfu(l0) | (bfu(l1) << 16);
            }
            uint32_t tb  = bV  + (kt >> 2) * 8192;
            uint32_t tbl = bVl + (kt >> 2) * 8192;
#pragma unroll
            for (int nb = 0; nb < 4; nb++) {
                uint32_t vh4[4], vl4[4];
                int row = nb * 16 + b_row_base;
                uint32_t off = row * 128 + ((b_cb + (kt & 3) * 32) ^ ((row & 7) << 4));
                LDSM4(vh4, tb + off);
                LDSM4(vl4, tbl + off);
                MMA16816(O[2*nb],   ah4, vh4);
                MMA16816(O[2*nb+1], ah4, vh4 + 2);
                MMA16816(O[2*nb],   ah4, vl4);
                MMA16816(O[2*nb+1], ah4, vl4 + 2);
                MMA16816(O[2*nb],   al4, vh4);
                MMA16816(O[2*nb+1], al4, vh4 + 2);
            }
        }
        __syncthreads();
    }

#pragma unroll
    for (int o = 1; o <= 2; o <<= 1) {
        lA += __shfl_xor_sync(0xffffffffu, lA, o);
        lB += __shfl_xor_sync(0xffffffffu, lB, o);
    }
    float iA = lA > 0.f ? 1.f / lA : 0.f;
    float iB = lB > 0.f ? 1.f / lB : 0.f;
    size_t rowA = (size_t)(b * 1024 + m0 + wid * 16 + rA);
#pragma unroll
    for (int nt = 0; nt < 8; nt++) {
        int c = nt * 8 + (lane & 3) * 2;
        __half h0, l0, h1, l1;
        float v0 = O[nt][0] * iA, v1 = O[nt][1] * iA;
        split2h(v0, h0, l0); split2h(v1, h1, l1);
        size_t idx = rowA * 768 + h * 64 + c;
        ushort2 hh; hh.x = (ushort)hfu(h0); hh.y = (ushort)hfu(h1);
        ushort2 ll; ll.x = (ushort)hfu(l0); ll.y = (ushort)hfu(l1);
        *(ushort2*)(Oh_ + idx) = hh;
        *(ushort2*)(Ol_ + idx) = ll;
        v0 = O[nt][2] * iB; v1 = O[nt][3] * iB;
        split2h(v0, h0, l0); split2h(v1, h1, l1);
        idx = (rowA + 8) * 768 + h * 64 + c;
        hh.x = (ushort)hfu(h0); hh.y = (ushort)hfu(h1);
        ll.x = (ushort)hfu(l0); ll.y = (ushort)hfu(l1);
        *(ushort2*)(Oh_ + idx) = hh;
        *(ushort2*)(Ol_ + idx) = ll;
    }
}

// ---------------------------------------------------------------------------
// LayerNorm over width 768. fp32 and/or fp16 hi/lo outputs. Optional pos add.
// ---------------------------------------------------------------------------
__global__ void ln_kernel(const float* __restrict__ in, const float* __restrict__ g,
                          float* __restrict__ outf,
                          __half* __restrict__ outhi, __half* __restrict__ outlo,
                          const float* __restrict__ pos_h, const float* __restrict__ pos_w,
                          const int* __restrict__ ppos)
{
    int row = blockIdx.x;
    int tid = threadIdx.x;
    const float* xr = in + (size_t)row * 768;
    float v[3]; float s = 0.f, q = 0.f;
#pragma unroll
    for (int i = 0; i < 3; i++) { float t = xr[tid + i*256]; v[i] = t; s += t; q += t*t; }
#pragma unroll
    for (int o = 16; o; o >>= 1) {
        s += __shfl_xor_sync(0xffffffffu, s, o);
        q += __shfl_xor_sync(0xffffffffu, q, o);
    }
    __shared__ float shs[8], shq[8], st[2];
    int w = tid >> 5;
    if ((tid & 31) == 0) { shs[w] = s; shq[w] = q; }
    __syncthreads();
    if (tid == 0) {
        float S = 0.f, Q = 0.f;
#pragma unroll
        for (int i = 0; i < 8; i++) { S += shs[i]; Q += shq[i]; }
        float mu = S * (1.f/768.f);
        st[0] = mu;
        st[1] = rsqrtf(Q * (1.f/768.f) - mu*mu + 1e-5f);
    }
    __syncthreads();
    float mu = st[0], rs = st[1];
    int p0 = 0, p1 = 0;
    if (ppos) { p0 = ppos[row*2]; p1 = ppos[row*2 + 1]; }
#pragma unroll
    for (int i = 0; i < 3; i++) {
        int c = tid + i*256;
        float y = (v[i] - mu) * rs * g[c];
        if (ppos) y += pos_h[p0*768 + c] + pos_w[p1*768 + c];
        size_t idx = (size_t)row*768 + c;
        if (outf) outf[idx] = y;
        if (outhi) {
            __half hh, ll; split2h(y, hh, ll);
            outhi[idx] = hh; outlo[idx] = ll;
        }
    }
}

// ---------------------------------------------------------------------------
// Fused QKV postprocess (bf16 outputs for flash).
// ---------------------------------------------------------------------------
__global__ void rmsT_all(const float* __restrict__ qkv,
                         const float* __restrict__ qg, const float* __restrict__ kg,
                         __nv_bfloat16* __restrict__ qh, __nv_bfloat16* __restrict__ ql,
                         __nv_bfloat16* __restrict__ kh, __nv_bfloat16* __restrict__ kl,
                         __nv_bfloat16* __restrict__ vh, __nv_bfloat16* __restrict__ vl)
{
    int token = blockIdx.x;
    int b = token >> 10, n = token & 1023;
    int w = threadIdx.x >> 5, lane = threadIdx.x & 31;
    const float* base = qkv + (size_t)token * 2304 + w * 64;
    __nv_bfloat16 hh, ll;

    {
        float v0 = base[lane], v1 = base[lane + 32];
        float ss = v0*v0 + v1*v1;
#pragma unroll
        for (int o = 16; o; o >>= 1) ss += __shfl_xor_sync(0xffffffffu, ss, o);
        float inv = 8.0f / fmaxf(sqrtf(ss), 1e-12f);
        v0 *= inv * qg[w*64 + lane];
        v1 *= inv * qg[w*64 + lane + 32];
        size_t dst = ((size_t)(b*12 + w) * 1024 + n) * 64;
        split2(v0, hh, ll); qh[dst + lane] = hh;      ql[dst + lane] = ll;
        split2(v1, hh, ll); qh[dst + lane + 32] = hh; ql[dst + lane + 32] = ll;
    }
    {
        float v0 = base[768 + lane], v1 = base[768 + lane + 32];
        float ss = v0*v0 + v1*v1;
#pragma unroll
        for (int o = 16; o; o >>= 1) ss += __shfl_xor_sync(0xffffffffu, ss, o);
        float inv = 8.0f / fmaxf(sqrtf(ss), 1e-12f);
        v0 *= inv * kg[w*64 + lane];
        v1 *= inv * kg[w*64 + lane + 32];
        size_t dst = ((size_t)(b*12 + w) * 1024 + n) * 64;
        split2(v0, hh, ll); kh[dst + lane] = hh;      kl[dst + lane] = ll;
        split2(v1, hh, ll); kh[dst + lane + 32] = hh; kl[dst + lane + 32] = ll;
    }
    {
        float v0 = base[1536 + lane], v1 = base[1536 + lane + 32];
        size_t vb = ((size_t)(b*12 + w) * 64) * 1024 + n;
        split2(v0, hh, ll); vh[vb + (size_t)lane * 1024] = hh;        vl[vb + (size_t)lane * 1024] = ll;
        split2(v1, hh, ll); vh[vb + (size_t)(lane + 32) * 1024] = hh; vl[vb + (size_t)(lane + 32) * 1024] = ll;
    }
}

__global__ void rmsT_f32(const float* __restrict__ in, int ld, int off,
                         const float* __restrict__ g, float* __restrict__ outT)
{
    int token = blockIdx.x;
    int b = token >> 10, n = token & 1023;
    int w = threadIdx.x >> 5, lane = threadIdx.x & 31;
    const float* src = in + (size_t)token * ld + off + w*64;
    float v0 = src[lane], v1 = src[lane + 32];
    if (g) {
        float ss = v0*v0 + v1*v1;
#pragma unroll
        for (int o = 16; o; o >>= 1) ss += __shfl_xor_sync(0xffffffffu, ss, o);
        float inv = 8.0f / fmaxf(sqrtf(ss), 1e-12f);
        v0 *= inv * g[w*64 + lane];
        v1 *= inv * g[w*64 + lane + 32];
    }
    float* dst = outT + ((size_t)(b*12 + w) * 1024 + n) * 64;
    dst[lane] = v0; dst[lane + 32] = v1;
}

// ---------------------------------------------------------------------------
// Attention pooling (192 blocks), fp32 path.
// ---------------------------------------------------------------------------
__global__ void pool_attn_kernel(const float* __restrict__ pqn, const float* __restrict__ kT,
                                 const float* __restrict__ vT, const int* __restrict__ image_ids,
                                 const int* __restrict__ lengths, float* __restrict__ out)
{
    int idx = blockIdx.x;
    int h = idx % 12, img = (idx / 12) % 4, b = idx / 48;
    int tid = threadIdx.x;
    __shared__ float q[64];
    __shared__ float p[1024];
    __shared__ float sh[8];
    __shared__ float bs[2];
    __shared__ float sred[256];
    if (tid < 64) q[tid] = pqn[h*64 + tid];
    __syncthreads();

    const float* K = kT + (size_t)(b*12 + h) * 1024 * 64;
    int len = lengths[b];
    float loc[4]; float mx = -FLT_MAX;
#pragma unroll
    for (int t = 0; t < 4; t++) {
        int j = tid + t*256;
        const float* kr = K + (size_t)j * 64;
        float dot = 0.f;
#pragma unroll
        for (int d = 0; d < 64; d++) dot += q[d] * kr[d];
        bool ok = (image_ids[b*1024 + j] == img) && (j < len);
        loc[t] = ok ? dot : -FLT_MAX;
        mx = fmaxf(mx, loc[t]);
    }
#pragma unroll
    for (int o = 16; o; o >>= 1) mx = fmaxf(mx, __shfl_xor_sync(0xffffffffu, mx, o));
    int w = tid >> 5;
    if ((tid & 31) == 0) sh[w] = mx;
    __syncthreads();
    if (tid == 0) { float mm = sh[0]; for (int i = 1; i < 8; i++) mm = fmaxf(mm, sh[i]); bs[0] = mm; }
    __syncthreads();
    mx = bs[0];
    float s = 0.f;
#pragma unroll
    for (int t = 0; t < 4; t++) {
        float e = __expf(loc[t] - mx);
        p[tid + t*256] = e;
        s += e;
    }
#pragma unroll
    for (int o = 16; o; o >>= 1) s += __shfl_xor_sync(0xffffffffu, s, o);
    if ((tid & 31) == 0) sh[w] = s;
    __syncthreads();
    if (tid == 0) { float ss = 0.f; for (int i = 0; i < 8; i++) ss += sh[i]; bs[1] = 1.f / ss; }
    __syncthreads();
    float inv = bs[1];

    const float* V = vT + (size_t)(b*12 + h) * 1024 * 64;
    int d = tid & 63, grp = tid >> 6;
    float acc = 0.f;
    for (int j = grp; j < 1024; j += 4) acc += p[j] * V[(size_t)j*64 + d];
    sred[tid] = acc;
    __syncthreads();
    if (grp == 0) {
        float r = (sred[d] + sred[d + 64]) + (sred[d + 128] + sred[d + 192]);
        out[(size_t)(b*4 + img) * 768 + h*64 + d] = r * inv;
    }
}

__global__ void rms_vec_kernel(const float* __restrict__ in, const float* __restrict__ g,
                               float* __restrict__ out)
{
    int w = threadIdx.x >> 5, lane = threadIdx.x & 31;
    float v0 = in[w*64 + lane], v1 = in[w*64 + lane + 32];
    float ss = v0*v0 + v1*v1;
#pragma unroll
    for (int o = 16; o; o >>= 1) ss += __shfl_xor_sync(0xffffffffu, ss, o);
    float inv = 8.0f / fmaxf(sqrtf(ss), 1e-12f);
    out[w*64 + lane]      = v0 * inv * g[w*64 + lane];
    out[w*64 + lane + 32] = v1 * inv * g[w*64 + lane + 32];
}

__global__ void small_gemm_kernel(const float* __restrict__ A, const float* __restrict__ W,
                                  const float* __restrict__ addvec, float* __restrict__ C,
                                  int N, int K)
{
    __shared__ float a[768];
    int row = blockIdx.y;
    for (int i = threadIdx.x; i < K; i += 256) a[i] = A[(size_t)row*K + i];
    __syncthreads();
    int n = blockIdx.x * 256 + threadIdx.x;
    if (n >= N) return;
    float acc = addvec ? addvec[n] : 0.f;
#pragma unroll 4
    for (int k = 0; k < K; k++) acc += a[k] * W[(size_t)k*N + n];
    C[(size_t)row*N + n] = acc;
}

// ---------------------------------------------------------------------------
// Host side
// ---------------------------------------------------------------------------
extern "C" void kernel_launch(void* const* d_in, const int* in_sizes, int n_in,
                              void* d_out, int out_size)
{
    (void)in_sizes; (void)n_in; (void)out_size;
    const float* patches    = (const float*)d_in[0];
    const int*   ppos       = (const int*)  d_in[1];
    const int*   image_ids  = (const int*)  d_in[2];
    const int*   lengths    = (const int*)  d_in[3];
    const float* emb_ln_g   = (const float*)d_in[4];
    const float* W_emb      = (const float*)d_in[5];
    const float* b_emb      = (const float*)d_in[6];
    const float* emb_ln2_g  = (const float*)d_in[7];
    const float* pos_h      = (const float*)d_in[8];
    const float* pos_w      = (const float*)d_in[9];
    const float* ln_attn_g  = (const float*)d_in[10];
    const float* Wq         = (const float*)d_in[11];
    const float* Wkv        = (const float*)d_in[12];
    const float* qn_g       = (const float*)d_in[13];
    const float* kn_g       = (const float*)d_in[14];
    const float* Wo         = (const float*)d_in[15];
    const float* ln_ff_g    = (const float*)d_in[16];
    const float* W1         = (const float*)d_in[17];
    const float* b1         = (const float*)d_in[18];
    const float* W2         = (const float*)d_in[19];
    const float* b2         = (const float*)d_in[20];
    const float* final_ln_g = (const float*)d_in[21];
    const float* pool_q     = (const float*)d_in[22];
    const float* pool_ln_g  = (const float*)d_in[23];
    const float* pWq        = (const float*)d_in[24];
    const float* pWkv       = (const float*)d_in[25];
    const float* p_qn_g     = (const float*)d_in[26];
    const float* p_kn_g     = (const float*)d_in[27];
    const float* pWo        = (const float*)d_in[28];
    const float* head_ln_g  = (const float*)d_in[29];
    const float* W_head     = (const float*)d_in[30];

    float *x, *qkv, *kTf, *vTf, *sm, *pattn, *pool, *pln;
    __half *xnh, *xnl, *tmph, *tmpl, *aoh, *aol, *w;
    __nv_bfloat16 *qTh, *qTl, *kTh, *kTl, *vTth, *vTtl;
    cudaGetSymbolAddress((void**)&x,    g_x);
    cudaGetSymbolAddress((void**)&qkv,  g_qkv);
    cudaGetSymbolAddress((void**)&kTf,  g_kTf);
    cudaGetSymbolAddress((void**)&vTf,  g_vTf);
    cudaGetSymbolAddress((void**)&sm,   g_sm);
    cudaGetSymbolAddress((void**)&pattn,g_pattn);
    cudaGetSymbolAddress((void**)&pool, g_pool);
    cudaGetSymbolAddress((void**)&pln,  g_pln);
    cudaGetSymbolAddress((void**)&xnh,  g_xnh);
    cudaGetSymbolAddress((void**)&xnl,  g_xnl);
    cudaGetSymbolAddress((void**)&tmph, g_tmph);
    cudaGetSymbolAddress((void**)&tmpl, g_tmpl);
    cudaGetSymbolAddress((void**)&qTh,  g_qTh);
    cudaGetSymbolAddress((void**)&qTl,  g_qTl);
    cudaGetSymbolAddress((void**)&kTh,  g_kTh);
    cudaGetSymbolAddress((void**)&kTl,  g_kTl);
    cudaGetSymbolAddress((void**)&vTth, g_vTth);
    cudaGetSymbolAddress((void**)&vTtl, g_vTtl);
    cudaGetSymbolAddress((void**)&aoh,  g_aoh);
    cudaGetSymbolAddress((void**)&aol,  g_aol);
    cudaGetSymbolAddress((void**)&w,    g_w);

    constexpr int SMEM128 = 98304;     // 2*(2*16384+16384)
    constexpr int SMEM256 = 163840;    // 2*(2*32768+16384)
    cudaFuncSetAttribute(mma_gemm<128>, cudaFuncAttributeMaxDynamicSharedMemorySize, SMEM128);
    cudaFuncSetAttribute(mma_gemm<256>, cudaFuncAttributeMaxDynamicSharedMemorySize, SMEM256);
    cudaFuncSetAttribute(flash_attn,    cudaFuncAttributeMaxDynamicSharedMemorySize, FA_SMEM);

    // ---- Convert + transpose weights to fp16 [N,K] ----
    dim3 wb(32, 8);
    wconv_kernel<<<dim3(DIM/32,  DIM/32),  wb>>>(W_emb, w + WOFF_EMB, DIM, DIM);
    for (int l = 0; l < 4; l++) {
        wconv_kernel<<<dim3(DIM/32,    DIM/32),  wb>>>(Wq  + (size_t)l*DIM*DIM,   w + WOFF_Q(l),  DIM,  DIM);
        wconv_kernel<<<dim3(2*DIM/32,  DIM/32),  wb>>>(Wkv + (size_t)l*DIM*2*DIM, w + WOFF_Q(l) + 589824ULL, DIM, 2*DIM);
        wconv_kernel<<<dim3(DIM/32,    DIM/32),  wb>>>(Wo  + (size_t)l*DIM*DIM,   w + WOFF_O(l),  DIM,  DIM);
        wconv_kernel<<<dim3(MLPD/32,   DIM/32),  wb>>>(W1  + (size_t)l*DIM*MLPD,  w + WOFF_W1(l), DIM,  MLPD);
        wconv_kernel<<<dim3(DIM/32,    MLPD/32), wb>>>(W2  + (size_t)l*MLPD*DIM,  w + WOFF_W2(l), MLPD, DIM);
    }
    wconv_kernel<<<dim3(2*DIM/32, DIM/32), wb>>>(pWkv, w + WOFF_PKV, DIM, 2*DIM);

    auto G128 = [&](const __half* ah, const __half* al, const __half* bw,
                    const float* bias, const float* res,
                    float* C, __half* Chi, __half* Clo,
                    int M, int N, int K, int flags) {
        mma_gemm<128><<<dim3(N/128, M/128), 256, SMEM128>>>(ah, al, bw, bias, res, C, Chi, Clo, M, N, K, flags);
    };
    auto G256 = [&](const __half* ah, const __half* al, const __half* bw,
                    const float* bias, const float* res,
                    float* C, __half* Chi, __half* Clo,
                    int M, int N, int K, int flags) {
        mma_gemm<256><<<dim3(N/128, M/256), 256, SMEM256>>>(ah, al, bw, bias, res, C, Chi, Clo, M, N, K, flags);
    };

    // ---- Embedding ----
    ln_kernel<<<TOKS, 256>>>(patches, emb_ln_g, nullptr, xnh, xnl, nullptr, nullptr, nullptr);
    G128(xnh, xnl, w + WOFF_EMB, b_emb, nullptr, x, nullptr, nullptr, TOKS, DIM, DIM, FBIAS);
    ln_kernel<<<TOKS, 256>>>(x, emb_ln2_g, x, nullptr, nullptr, pos_h, pos_w, ppos);

    // ---- Transformer layers ----
    for (int l = 0; l < 4; l++) {
        ln_kernel<<<TOKS, 256>>>(x, ln_attn_g + l*DIM, nullptr, xnh, xnl, nullptr, nullptr, nullptr);
        G256(xnh, xnl, w + WOFF_Q(l), nullptr, nullptr, qkv, nullptr, nullptr, TOKS, 2304, DIM, 0);
        rmsT_all<<<TOKS, 384>>>(qkv, qn_g + l*DIM, kn_g + l*DIM, qTh, qTl, kTh, kTl, vTth, vTtl);
        flash_attn<<<dim3(8, BH), 256, FA_SMEM>>>(qTh, qTl, kTh, kTl, vTth, vTtl,
                                                  image_ids, lengths, aoh, aol);
        G128(aoh, aol, w + WOFF_O(l), nullptr, x, x, nullptr, nullptr, TOKS, DIM, DIM, FRES);
        ln_kernel<<<TOKS, 256>>>(x, ln_ff_g + l*DIM, nullptr, xnh, xnl, nullptr, nullptr, nullptr);
        G256(xnh, xnl, w + WOFF_W1(l), b1 + l*MLPD, nullptr, nullptr, tmph, tmpl,
             TOKS, MLPD, DIM, FBIAS|FGELU);
        G128(tmph, tmpl, w + WOFF_W2(l), b2 + l*DIM, x, x, nullptr, nullptr,
             TOKS, DIM, MLPD, FBIAS|FRES);
    }

    // ---- Final LN ----
    ln_kernel<<<TOKS, 256>>>(x, final_ln_g, nullptr, xnh, xnl, nullptr, nullptr, nullptr);

    // ---- Attention pooling ----
    ln_kernel<<<1, 256>>>(pool_q, pool_ln_g, sm, nullptr, nullptr, nullptr, nullptr, nullptr);
    small_gemm_kernel<<<dim3(3, 1), 256>>>(sm, pWq, nullptr, sm + 768, DIM, DIM);
    rms_vec_kernel<<<1, 384>>>(sm + 768, p_qn_g, sm + 1536);
    G256(xnh, xnl, w + WOFF_PKV, nullptr, nullptr, qkv, nullptr, nullptr, TOKS, 1536, DIM, 0);
    rmsT_f32<<<TOKS, 384>>>(qkv, 1536, 0,   p_kn_g, kTf);
    rmsT_f32<<<TOKS, 384>>>(qkv, 1536, 768, nullptr, vTf);
    pool_attn_kernel<<<NB*IMGS*NHEAD, 256>>>(sm + 1536, kTf, vTf, image_ids, lengths, pattn);
    small_gemm_kernel<<<dim3(3, 16), 256>>>(pattn, pWo, pool_q, pool, DIM, DIM);
    ln_kernel<<<16, 256>>>(pool, head_ln_g, pln, nullptr, nullptr, nullptr, nullptr, nullptr);
    small_gemm_kernel<<<dim3(4, 16), 256>>>(pln, W_head, nullptr, (float*)d_out, NCLS, DIM);
}

// round 8
// speedup vs baseline: 4.6256x; 1.3394x over previous
#include <cuda_runtime.h>
#include <cuda_bf16.h>
#include <cuda_fp16.h>
#include <math.h>
#include <float.h>
#include <stdint.h>

// ---------------------------------------------------------------------------
// Problem constants
// ---------------------------------------------------------------------------
#define NB      4
#define NTOK    1024
#define DIM     768
#define NHEAD   12
#define DHEAD   64
#define MLPD    3072
#define IMGS    4
#define NCLS    1000
#define TOKS    (NB*NTOK)
#define BH      (NB*NHEAD)

#define FBIAS 1
#define FGELU 2
#define FRES  4

#define WOFF_EMB 0ULL
#define WPERL    7077888ULL
#define WOFF_L(l)   (589824ULL + (unsigned long long)(l)*WPERL)
#define WOFF_Q(l)   (WOFF_L(l) + 0ULL)
#define WOFF_O(l)   (WOFF_L(l) + 1769472ULL)
#define WOFF_W1(l)  (WOFF_L(l) + 2359296ULL)
#define WOFF_W2(l)  (WOFF_L(l) + 4718592ULL)
#define WOFF_PKV    (589824ULL + 4ULL*WPERL)
#define WTOTAL      30081024ULL

// ---------------------------------------------------------------------------
// Device scratch
// ---------------------------------------------------------------------------
__device__ float g_x   [TOKS*DIM];
__device__ float g_qkv [TOKS*2304];
__device__ __half g_xn  [TOKS*DIM];
__device__ __half g_tmp [TOKS*MLPD];
__device__ __half g_ao  [TOKS*DIM];
__device__ __nv_bfloat16 g_qTh[BH*NTOK*DHEAD], g_qTl[BH*NTOK*DHEAD];
__device__ __nv_bfloat16 g_kTh[BH*NTOK*DHEAD], g_kTl[BH*NTOK*DHEAD];
__device__ __nv_bfloat16 g_vTth[BH*DHEAD*NTOK], g_vTtl[BH*DHEAD*NTOK];
__device__ float g_kTf[BH*NTOK*DHEAD], g_vTf[BH*NTOK*DHEAD];
__device__ float g_sm  [4096];
__device__ float g_pattn[16*DIM];
__device__ float g_pool [16*DIM];
__device__ float g_pln  [16*DIM];
__device__ __half g_w[WTOTAL];

// ---------------------------------------------------------------------------
// Helpers
// ---------------------------------------------------------------------------
__device__ __forceinline__ uint32_t smem_u32(const void* p) {
    uint32_t a;
    asm("{ .reg .u64 t; cvta.to.shared.u64 t, %1; cvt.u32.u64 %0, t; }" : "=r"(a) : "l"(p));
    return a;
}

#define LDSM4(r, addr) \
    asm volatile("ldmatrix.sync.aligned.m8n8.x4.shared.b16 {%0,%1,%2,%3}, [%4];" \
        : "=r"((r)[0]), "=r"((r)[1]), "=r"((r)[2]), "=r"((r)[3]) : "r"(addr))

#define MMA16816(d, a, b) \
    asm volatile("mma.sync.aligned.m16n8k16.row.col.f32.bf16.bf16.f32 " \
        "{%0,%1,%2,%3}, {%4,%5,%6,%7}, {%8,%9}, {%0,%1,%2,%3};" \
        : "+f"((d)[0]), "+f"((d)[1]), "+f"((d)[2]), "+f"((d)[3]) \
        : "r"((a)[0]), "r"((a)[1]), "r"((a)[2]), "r"((a)[3]), "r"((b)[0]), "r"((b)[1]))

#define MMAH16816(d, a, b) \
    asm volatile("mma.sync.aligned.m16n8k16.row.col.f32.f16.f16.f32 " \
        "{%0,%1,%2,%3}, {%4,%5,%6,%7}, {%8,%9}, {%0,%1,%2,%3};" \
        : "+f"((d)[0]), "+f"((d)[1]), "+f"((d)[2]), "+f"((d)[3]) \
        : "r"((a)[0]), "r"((a)[1]), "r"((a)[2]), "r"((a)[3]), "r"((b)[0]), "r"((b)[1]))

#define CPA16(dst, src) \
    asm volatile("cp.async.cg.shared.global [%0], [%1], 16;" :: "r"(dst), "l"(src))
#define CP_COMMIT() asm volatile("cp.async.commit_group;" ::: "memory")
#define CP_WAIT0()  asm volatile("cp.async.wait_group 0;" ::: "memory")
#define CP_WAIT1()  asm volatile("cp.async.wait_group 1;" ::: "memory")

__device__ __forceinline__ void split2(float v, __nv_bfloat16& h, __nv_bfloat16& l) {
    h = __float2bfloat16(v);
    l = __float2bfloat16(v - __bfloat162float(h));
}
__device__ __forceinline__ uint32_t bfu(__nv_bfloat16 b) { return (uint32_t)__bfloat16_as_ushort(b); }

template<typename T>
__device__ __forceinline__ void cpa_tile(uint32_t smbase, const T* __restrict__ g,
                                         int ldk, int chunks, int tid)
{
    for (int i = tid; i < chunks; i += 256) {
        int r = i >> 3, c = i & 7;
        uint32_t off = r * 128 + c * 16;
        uint32_t sw = off ^ ((off >> 3) & 0x70);
        CPA16(smbase + sw, g + (size_t)r * ldk + c * 8);
    }
}

// ---------------------------------------------------------------------------
// Weight convert+transpose: W[K,N] fp32 -> fp16 [N,K]
// ---------------------------------------------------------------------------
__global__ void wconv_kernel(const float* __restrict__ W, __half* __restrict__ out,
                             int K, int N)
{
    __shared__ float t[32][33];
    int n0 = blockIdx.x * 32, k0 = blockIdx.y * 32;
    int tx = threadIdx.x, ty = threadIdx.y;
#pragma unroll
    for (int r = 0; r < 4; r++)
        t[ty + r*8][tx] = W[(size_t)(k0 + ty + r*8) * N + n0 + tx];
    __syncthreads();
#pragma unroll
    for (int r = 0; r < 4; r++) {
        int n = n0 + ty + r*8, k = k0 + tx;
        out[(size_t)n * K + k] = __float2half(t[tx][ty + r*8]);
    }
}

// ---------------------------------------------------------------------------
// Pipelined mma.sync fp16 GEMM, single pass (A fp16, B fp16 weights).
// MT=128: 8 warps 2Mx4N. MT=256: 8 warps 4Mx2N.
// ---------------------------------------------------------------------------
template<int MT>
__global__ void __launch_bounds__(256, 1) mma_gemm(
    const __half* __restrict__ A, const __half* __restrict__ B,
    const float* __restrict__ bias, const float* __restrict__ res,
    float* __restrict__ C, __half* __restrict__ Ch,
    int M, int N, int K, int flags)
{
    constexpr int WM   = MT / 64;
    constexpr int NQ   = (WM == 2) ? 2 : 4;
    constexpr int NTL  = 2 * NQ;
    constexpr int NCOL = NQ * 16;
    constexpr int A_SZ = MT * 128;
    constexpr int STG  = A_SZ + 16384;

    extern __shared__ char smem[];
    uint32_t uS = smem_u32(smem);

    const int tid = threadIdx.x;
    const int wid = tid >> 5, lane = tid & 31;
    const int m0 = blockIdx.y * MT, n0 = blockIdx.x * 128;
    const int wm = wid & (WM - 1), wn = wid / WM;

    const __half* Az = A + (size_t)m0 * K;
    const __half* Bz = B + (size_t)n0 * K;

    float acc[4][NTL][4] = {};

    const int a_row = wm * 64 + (lane & 15);
    const int a_cb  = (lane >> 4) * 16;
    const int b_row = wn * NCOL + (lane & 7) + ((lane >> 4) << 3);
    const int b_cb  = ((lane >> 3) & 1) * 16;

    const int KT = K >> 6;
    {
        cpa_tile(uS,        Az, K, MT * 8, tid);
        cpa_tile(uS + A_SZ, Bz, K, 1024,   tid);
        CP_COMMIT();
    }

    for (int kt = 0; kt < KT; kt++) {
        if (kt + 1 < KT) {
            uint32_t base = uS + ((kt + 1) & 1) * STG;
            cpa_tile(base,        Az + (kt + 1) * 64, K, MT * 8, tid);
            cpa_tile(base + A_SZ, Bz + (kt + 1) * 64, K, 1024,   tid);
            CP_COMMIT();
            CP_WAIT1();
        } else {
            CP_WAIT0();
        }
        __syncthreads();

        uint32_t bA = uS + (kt & 1) * STG;
        uint32_t bB = bA + A_SZ;

#pragma unroll
        for (int ks = 0; ks < 4; ks++) {
            uint32_t ah[4][4], bh[NQ][4];
#pragma unroll
            for (int mt = 0; mt < 4; mt++) {
                int row = a_row + mt * 16;
                uint32_t off = row * 128 + ((a_cb + ks * 32) ^ ((row & 7) << 4));
                LDSM4(ah[mt], bA + off);
            }
#pragma unroll
            for (int q = 0; q < NQ; q++) {
                int row = b_row + q * 16;
                uint32_t off = row * 128 + ((b_cb + ks * 32) ^ ((row & 7) << 4));
                LDSM4(bh[q], bB + off);
            }
#pragma unroll
            for (int mt = 0; mt < 4; mt++)
#pragma unroll
                for (int nt = 0; nt < NTL; nt++)
                    MMAH16816(acc[mt][nt], ah[mt], &bh[nt >> 1][(nt & 1) * 2]);
        }
        __syncthreads();
    }

    const int rbase = m0 + wm * 64;
#pragma unroll
    for (int mt = 0; mt < 4; mt++) {
#pragma unroll
        for (int nt = 0; nt < NTL; nt++) {
            int c = n0 + wn * NCOL + nt * 8 + (lane & 3) * 2;
            float bv0 = 0.f, bv1 = 0.f;
            if (flags & FBIAS) { bv0 = bias[c]; bv1 = bias[c + 1]; }
#pragma unroll
            for (int half = 0; half < 2; half++) {
                int r = rbase + mt * 16 + (lane >> 2) + half * 8;
                float v0 = acc[mt][nt][half * 2 + 0];
                float v1 = acc[mt][nt][half * 2 + 1];
                if (flags & FBIAS) { v0 += bv0; v1 += bv1; }
                if (flags & FGELU) {
                    v0 = 0.5f * v0 * (1.f + erff(v0 * 0.70710678118654752f));
                    v1 = 0.5f * v1 * (1.f + erff(v1 * 0.70710678118654752f));
                }
                long idx = (long)r * N + c;
                if (flags & FRES) { v0 += res[idx]; v1 += res[idx + 1]; }
                if (C) *(float2*)(C + idx) = make_float2(v0, v1);
                if (Ch) {
                    __half2 hv = __floats2half2_rn(v0, v1);
                    *(__half2*)(Ch + idx) = hv;
                }
            }
        }
    }
}

// ---------------------------------------------------------------------------
// Fused flash attention (bf16 3-pass; fp16 output).
// ---------------------------------------------------------------------------
#define FA_SMEM 165504

__global__ void __launch_bounds__(256, 1) flash_attn(
    const __nv_bfloat16* __restrict__ Qh_, const __nv_bfloat16* __restrict__ Ql_,
    const __nv_bfloat16* __restrict__ Kh_, const __nv_bfloat16* __restrict__ Kl_,
    const __nv_bfloat16* __restrict__ Vh_, const __nv_bfloat16* __restrict__ Vl_,
    const int* __restrict__ image_ids, const int* __restrict__ lengths,
    __half* __restrict__ O_)
{
    extern __shared__ char smem[];
    uint32_t uS = smem_u32(smem);
    const int tid = threadIdx.x, wid = tid >> 5, lane = tid & 31;
    const int z = blockIdx.y, b = z / 12, h = z % 12;
    const int m0 = blockIdx.x * 128;

    int* s_cmin   = (int*)(smem + 163840);
    int* s_cmax   = s_cmin + 8;
    int* s_jlist  = s_cmax + 8;
    int* s_meta   = s_jlist + 8;
    int* s_imgRow = s_meta + 8;
    int* s_imgCol = s_imgRow + 128;

    const int len = lengths[b];

    {
        int4 v = *(const int4*)(image_ids + b*1024 + wid*128 + lane*4);
        int mn = min(min(v.x, v.y), min(v.z, v.w));
        int mx = max(max(v.x, v.y), max(v.z, v.w));
#pragma unroll
        for (int o = 16; o; o >>= 1) {
            mn = min(mn, __shfl_xor_sync(0xffffffffu, mn, o));
            mx = max(mx, __shfl_xor_sync(0xffffffffu, mx, o));
        }
        if (lane == 0) { s_cmin[wid] = mn; s_cmax[wid] = mx; }
    }
    if (tid < 128) s_imgRow[tid] = image_ids[b*1024 + m0 + tid];
    __syncthreads();
    if (tid == 0) {
        int rmin = s_cmin[blockIdx.x], rmax = s_cmax[blockIdx.x];
        int nj = 0;
        for (int jb = 0; jb < 8; jb++)
            if (jb * 128 < len && s_cmax[jb] >= rmin && s_cmin[jb] <= rmax)
                s_jlist[nj++] = jb;
        s_meta[0] = nj;
    }
    __syncthreads();
    const int nj = s_meta[0];

    const size_t qoff = ((size_t)z * 1024 + m0) * 64;
    cpa_tile(uS,         Qh_ + qoff, 64, 1024, tid);
    cpa_tile(uS + 16384, Ql_ + qoff, 64, 1024, tid);

    auto prefetch = [&](int t) {
        int jb = s_jlist[t];
        int st = t & 1;
        uint32_t base = uS + 32768 + st * 65536;
        size_t koff = ((size_t)z * 1024 + jb * 128) * 64;
        cpa_tile(base,         Kh_ + koff, 64, 1024, tid);
        cpa_tile(base + 16384, Kl_ + koff, 64, 1024, tid);
        const __nv_bfloat16* vh = Vh_ + (size_t)z * 64 * 1024 + jb * 128;
        const __nv_bfloat16* vl = Vl_ + (size_t)z * 64 * 1024 + jb * 128;
        for (int i = tid; i < 1024; i += 256) {
            int r = i >> 4, c = i & 15;
            int kc = c >> 3, cc = c & 7;
            uint32_t off = r * 128 + cc * 16;
            uint32_t sw = off ^ ((off >> 3) & 0x70);
            CPA16(base + 32768 + kc * 8192 + sw, vh + (size_t)r * 1024 + c * 8);
            CPA16(base + 49152 + kc * 8192 + sw, vl + (size_t)r * 1024 + c * 8);
        }
        if (tid < 128) s_imgCol[st * 128 + tid] = image_ids[b*1024 + jb*128 + tid];
    };
    prefetch(0);
    CP_COMMIT();

    float O[8][4] = {};
    float mA = -FLT_MAX, mB = -FLT_MAX, lA = 0.f, lB = 0.f;
    uint32_t qh[4][4], ql[4][4];
    bool qloaded = false;

    const int rA = lane >> 2;
    const int imgA = s_imgRow[wid * 16 + rA];
    const int imgB = s_imgRow[wid * 16 + rA + 8];

    const int a_row = wid * 16 + (lane & 15);
    const int a_cb  = (lane >> 4) * 16;
    const int b_row_base = (lane & 7) + ((lane >> 4) << 3);
    const int b_cb  = ((lane >> 3) & 1) * 16;

    for (int t = 0; t < nj; t++) {
        if (t + 1 < nj) { prefetch(t + 1); CP_COMMIT(); CP_WAIT1(); }
        else CP_WAIT0();
        __syncthreads();

        if (!qloaded) {
            qloaded = true;
#pragma unroll
            for (int ks = 0; ks < 4; ks++) {
                uint32_t off = a_row * 128 + ((a_cb + ks * 32) ^ ((a_row & 7) << 4));
                LDSM4(qh[ks], uS + off);
                LDSM4(ql[ks], uS + 16384 + off);
            }
        }

        int st = t & 1;
        uint32_t bK  = uS + 32768 + st * 65536;
        uint32_t bKl = bK + 16384;
        uint32_t bV  = bK + 32768;
        uint32_t bVl = bK + 49152;
        int jb = s_jlist[t];
        int j0 = jb * 128;
        const int* imgC = s_imgCol + st * 128;

        float S[16][4] = {};
#pragma unroll
        for (int ks = 0; ks < 4; ks++) {
#pragma unroll
            for (int nb = 0; nb < 8; nb++) {
                uint32_t bh4[4], bl4[4];
                int row = nb * 16 + b_row_base;
                uint32_t off = row * 128 + ((b_cb + ks * 32) ^ ((row & 7) << 4));
                LDSM4(bh4, bK + off);
                LDSM4(bl4, bKl + off);
                MMA16816(S[2*nb],   qh[ks], bh4);
                MMA16816(S[2*nb+1], qh[ks], bh4 + 2);
                MMA16816(S[2*nb],   qh[ks], bl4);
                MMA16816(S[2*nb+1], qh[ks], bl4 + 2);
                MMA16816(S[2*nb],   ql[ks], bh4);
                MMA16816(S[2*nb+1], ql[ks], bh4 + 2);
            }
        }

        float mnA = mA, mnB = mB;
#pragma unroll
        for (int nt = 0; nt < 16; nt++) {
            int c0 = nt * 8 + (lane & 3) * 2;
            int i0 = imgC[c0], i1 = imgC[c0 + 1];
            bool v0 = (j0 + c0) < len, v1 = (j0 + c0 + 1) < len;
            if (i0 == imgA && v0) mnA = fmaxf(mnA, S[nt][0]);
            if (i1 == imgA && v1) mnA = fmaxf(mnA, S[nt][1]);
            if (i0 == imgB && v0) mnB = fmaxf(mnB, S[nt][2]);
            if (i1 == imgB && v1) mnB = fmaxf(mnB, S[nt][3]);
        }
#pragma unroll
        for (int o = 1; o <= 2; o <<= 1) {
            mnA = fmaxf(mnA, __shfl_xor_sync(0xffffffffu, mnA, o));
            mnB = fmaxf(mnB, __shfl_xor_sync(0xffffffffu, mnB, o));
        }
        float scA = __expf(mA - mnA), scB = __expf(mB - mnB);
        mA = mnA; mB = mnB;
        lA *= scA; lB *= scB;
#pragma unroll
        for (int nt = 0; nt < 16; nt++) {
            int c0 = nt * 8 + (lane & 3) * 2;
            int i0 = imgC[c0], i1 = imgC[c0 + 1];
            bool v0 = (j0 + c0) < len, v1 = (j0 + c0 + 1) < len;
            float p0 = (i0 == imgA && v0) ? __expf(S[nt][0] - mnA) : 0.f;
            float p1 = (i1 == imgA && v1) ? __expf(S[nt][1] - mnA) : 0.f;
            float p2 = (i0 == imgB && v0) ? __expf(S[nt][2] - mnB) : 0.f;
            float p3 = (i1 == imgB && v1) ? __expf(S[nt][3] - mnB) : 0.f;
            lA += p0 + p1; lB += p2 + p3;
            S[nt][0] = p0; S[nt][1] = p1; S[nt][2] = p2; S[nt][3] = p3;
        }
#pragma unroll
        for (int nt = 0; nt < 8; nt++) {
            O[nt][0] *= scA; O[nt][1] *= scA; O[nt][2] *= scB; O[nt][3] *= scB;
        }

#pragma unroll
        for (int kt = 0; kt < 8; kt++) {
            uint32_t ah4[4], al4[4];
            {
                __nv_bfloat16 h0, l0, h1, l1;
                split2(S[2*kt][0], h0, l0);   split2(S[2*kt][1], h1, l1);
                ah4[0] = bfu(h0) | (bfu(h1) << 16);  al4[0] = bfu(l0) | (bfu(l1) << 16);
                split2(S[2*kt][2], h0, l0);   split2(S[2*kt][3], h1, l1);
                ah4[1] = bfu(h0) | (bfu(h1) << 16);  al4[1] = bfu(l0) | (bfu(l1) << 16);
                split2(S[2*kt+1][0], h0, l0); split2(S[2*kt+1][1], h1, l1);
                ah4[2] = bfu(h0) | (bfu(h1) << 16);  al4[2] = bfu(l0) | (bfu(l1) << 16);
                split2(S[2*kt+1][2], h0, l0); split2(S[2*kt+1][3], h1, l1);
                ah4[3] = bfu(h0) | (bfu(h1) << 16);  al4[3] = bfu(l0) | (bfu(l1) << 16);
            }
            uint32_t tb  = bV  + (kt >> 2) * 8192;
            uint32_t tbl = bVl + (kt >> 2) * 8192;
#pragma unroll
            for (int nb = 0; nb < 4; nb++) {
                uint32_t vh4[4], vl4[4];
                int row = nb * 16 + b_row_base;
                uint32_t off = row * 128 + ((b_cb + (kt & 3) * 32) ^ ((row & 7) << 4));
                LDSM4(vh4, tb + off);
                LDSM4(vl4, tbl + off);
                MMA16816(O[2*nb],   ah4, vh4);
                MMA16816(O[2*nb+1], ah4, vh4 + 2);
                MMA16816(O[2*nb],   ah4, vl4);
                MMA16816(O[2*nb+1], ah4, vl4 + 2);
                MMA16816(O[2*nb],   al4, vh4);
                MMA16816(O[2*nb+1], al4, vh4 + 2);
            }
        }
        __syncthreads();
    }

#pragma unroll
    for (int o = 1; o <= 2; o <<= 1) {
        lA += __shfl_xor_sync(0xffffffffu, lA, o);
        lB += __shfl_xor_sync(0xffffffffu, lB, o);
    }
    float iA = lA > 0.f ? 1.f / lA : 0.f;
    float iB = lB > 0.f ? 1.f / lB : 0.f;
    size_t rowA = (size_t)(b * 1024 + m0 + wid * 16 + rA);
#pragma unroll
    for (int nt = 0; nt < 8; nt++) {
        int c = nt * 8 + (lane & 3) * 2;
        size_t idx = rowA * 768 + h * 64 + c;
        *(__half2*)(O_ + idx) = __floats2half2_rn(O[nt][0] * iA, O[nt][1] * iA);
        idx = (rowA + 8) * 768 + h * 64 + c;
        *(__half2*)(O_ + idx) = __floats2half2_rn(O[nt][2] * iB, O[nt][3] * iB);
    }
}

// ---------------------------------------------------------------------------
// LayerNorm over width 768. fp32 and/or fp16 outputs. Optional pos add.
// ---------------------------------------------------------------------------
__global__ void ln_kernel(const float* __restrict__ in, const float* __restrict__ g,
                          float* __restrict__ outf, __half* __restrict__ outh,
                          const float* __restrict__ pos_h, const float* __restrict__ pos_w,
                          const int* __restrict__ ppos)
{
    int row = blockIdx.x;
    int tid = threadIdx.x;
    const float* xr = in + (size_t)row * 768;
    float v[3]; float s = 0.f, q = 0.f;
#pragma unroll
    for (int i = 0; i < 3; i++) { float t = xr[tid + i*256]; v[i] = t; s += t; q += t*t; }
#pragma unroll
    for (int o = 16; o; o >>= 1) {
        s += __shfl_xor_sync(0xffffffffu, s, o);
        q += __shfl_xor_sync(0xffffffffu, q, o);
    }
    __shared__ float shs[8], shq[8], st[2];
    int w = tid >> 5;
    if ((tid & 31) == 0) { shs[w] = s; shq[w] = q; }
    __syncthreads();
    if (tid == 0) {
        float S = 0.f, Q = 0.f;
#pragma unroll
        for (int i = 0; i < 8; i++) { S += shs[i]; Q += shq[i]; }
        float mu = S * (1.f/768.f);
        st[0] = mu;
        st[1] = rsqrtf(Q * (1.f/768.f) - mu*mu + 1e-5f);
    }
    __syncthreads();
    float mu = st[0], rs = st[1];
    int p0 = 0, p1 = 0;
    if (ppos) { p0 = ppos[row*2]; p1 = ppos[row*2 + 1]; }
#pragma unroll
    for (int i = 0; i < 3; i++) {
        int c = tid + i*256;
        float y = (v[i] - mu) * rs * g[c];
        if (ppos) y += pos_h[p0*768 + c] + pos_w[p1*768 + c];
        size_t idx = (size_t)row*768 + c;
        if (outf) outf[idx] = y;
        if (outh) outh[idx] = __float2half(y);
    }
}

// ---------------------------------------------------------------------------
// Fused QKV postprocess (bf16 hi/lo outputs for flash).
// ---------------------------------------------------------------------------
__global__ void rmsT_all(const float* __restrict__ qkv,
                         const float* __restrict__ qg, const float* __restrict__ kg,
                         __nv_bfloat16* __restrict__ qh, __nv_bfloat16* __restrict__ ql,
                         __nv_bfloat16* __restrict__ kh, __nv_bfloat16* __restrict__ kl,
                         __nv_bfloat16* __restrict__ vh, __nv_bfloat16* __restrict__ vl)
{
    int token = blockIdx.x;
    int b = token >> 10, n = token & 1023;
    int w = threadIdx.x >> 5, lane = threadIdx.x & 31;
    const float* base = qkv + (size_t)token * 2304 + w * 64;
    __nv_bfloat16 hh, ll;

    {
        float v0 = base[lane], v1 = base[lane + 32];
        float ss = v0*v0 + v1*v1;
#pragma unroll
        for (int o = 16; o; o >>= 1) ss += __shfl_xor_sync(0xffffffffu, ss, o);
        float inv = 8.0f / fmaxf(sqrtf(ss), 1e-12f);
        v0 *= inv * qg[w*64 + lane];
        v1 *= inv * qg[w*64 + lane + 32];
        size_t dst = ((size_t)(b*12 + w) * 1024 + n) * 64;
        split2(v0, hh, ll); qh[dst + lane] = hh;      ql[dst + lane] = ll;
        split2(v1, hh, ll); qh[dst + lane + 32] = hh; ql[dst + lane + 32] = ll;
    }
    {
        float v0 = base[768 + lane], v1 = base[768 + lane + 32];
        float ss = v0*v0 + v1*v1;
#pragma unroll
        for (int o = 16; o; o >>= 1) ss += __shfl_xor_sync(0xffffffffu, ss, o);
        float inv = 8.0f / fmaxf(sqrtf(ss), 1e-12f);
        v0 *= inv * kg[w*64 + lane];
        v1 *= inv * kg[w*64 + lane + 32];
        size_t dst = ((size_t)(b*12 + w) * 1024 + n) * 64;
        split2(v0, hh, ll); kh[dst + lane] = hh;      kl[dst + lane] = ll;
        split2(v1, hh, ll); kh[dst + lane + 32] = hh; kl[dst + lane + 32] = ll;
    }
    {
        float v0 = base[1536 + lane], v1 = base[1536 + lane + 32];
        size_t vb = ((size_t)(b*12 + w) * 64) * 1024 + n;
        split2(v0, hh, ll); vh[vb + (size_t)lane * 1024] = hh;        vl[vb + (size_t)lane * 1024] = ll;
        split2(v1, hh, ll); vh[vb + (size_t)(lane + 32) * 1024] = hh; vl[vb + (size_t)(lane + 32) * 1024] = ll;
    }
}

__global__ void rmsT_f32(const float* __restrict__ in, int ld, int off,
                         const float* __restrict__ g, float* __restrict__ outT)
{
    int token = blockIdx.x;
    int b = token >> 10, n = token & 1023;
    int w = threadIdx.x >> 5, lane = threadIdx.x & 31;
    const float* src = in + (size_t)token * ld + off + w*64;
    float v0 = src[lane], v1 = src[lane + 32];
    if (g) {
        float ss = v0*v0 + v1*v1;
#pragma unroll
        for (int o = 16; o; o >>= 1) ss += __shfl_xor_sync(0xffffffffu, ss, o);
        float inv = 8.0f / fmaxf(sqrtf(ss), 1e-12f);
        v0 *= inv * g[w*64 + lane];
        v1 *= inv * g[w*64 + lane + 32];
    }
    float* dst = outT + ((size_t)(b*12 + w) * 1024 + n) * 64;
    dst[lane] = v0; dst[lane + 32] = v1;
}

// ---------------------------------------------------------------------------
// Attention pooling (192 blocks), fp32 path.
// ---------------------------------------------------------------------------
__global__ void pool_attn_kernel(const float* __restrict__ pqn, const float* __restrict__ kT,
                                 const float* __restrict__ vT, const int* __restrict__ image_ids,
                                 const int* __restrict__ lengths, float* __restrict__ out)
{
    int idx = blockIdx.x;
    int h = idx % 12, img = (idx / 12) % 4, b = idx / 48;
    int tid = threadIdx.x;
    __shared__ float q[64];
    __shared__ float p[1024];
    __shared__ float sh[8];
    __shared__ float bs[2];
    __shared__ float sred[256];
    if (tid < 64) q[tid] = pqn[h*64 + tid];
    __syncthreads();

    const float* K = kT + (size_t)(b*12 + h) * 1024 * 64;
    int len = lengths[b];
    float loc[4]; float mx = -FLT_MAX;
#pragma unroll
    for (int t = 0; t < 4; t++) {
        int j = tid + t*256;
        const float* kr = K + (size_t)j * 64;
        float dot = 0.f;
#pragma unroll
        for (int d = 0; d < 64; d++) dot += q[d] * kr[d];
        bool ok = (image_ids[b*1024 + j] == img) && (j < len);
        loc[t] = ok ? dot : -FLT_MAX;
        mx = fmaxf(mx, loc[t]);
    }
#pragma unroll
    for (int o = 16; o; o >>= 1) mx = fmaxf(mx, __shfl_xor_sync(0xffffffffu, mx, o));
    int w = tid >> 5;
    if ((tid & 31) == 0) sh[w] = mx;
    __syncthreads();
    if (tid == 0) { float mm = sh[0]; for (int i = 1; i < 8; i++) mm = fmaxf(mm, sh[i]); bs[0] = mm; }
    __syncthreads();
    mx = bs[0];
    float s = 0.f;
#pragma unroll
    for (int t = 0; t < 4; t++) {
        float e = __expf(loc[t] - mx);
        p[tid + t*256] = e;
        s += e;
    }
#pragma unroll
    for (int o = 16; o; o >>= 1) s += __shfl_xor_sync(0xffffffffu, s, o);
    if ((tid & 31) == 0) sh[w] = s;
    __syncthreads();
    if (tid == 0) { float ss = 0.f; for (int i = 0; i < 8; i++) ss += sh[i]; bs[1] = 1.f / ss; }
    __syncthreads();
    float inv = bs[1];

    const float* V = vT + (size_t)(b*12 + h) * 1024 * 64;
    int d = tid & 63, grp = tid >> 6;
    float acc = 0.f;
    for (int j = grp; j < 1024; j += 4) acc += p[j] * V[(size_t)j*64 + d];
    sred[tid] = acc;
    __syncthreads();
    if (grp == 0) {
        float r = (sred[d] + sred[d + 64]) + (sred[d + 128] + sred[d + 192]);
        out[(size_t)(b*4 + img) * 768 + h*64 + d] = r * inv;
    }
}

__global__ void rms_vec_kernel(const float* __restrict__ in, const float* __restrict__ g,
                               float* __restrict__ out)
{
    int w = threadIdx.x >> 5, lane = threadIdx.x & 31;
    float v0 = in[w*64 + lane], v1 = in[w*64 + lane + 32];
    float ss = v0*v0 + v1*v1;
#pragma unroll
    for (int o = 16; o; o >>= 1) ss += __shfl_xor_sync(0xffffffffu, ss, o);
    float inv = 8.0f / fmaxf(sqrtf(ss), 1e-12f);
    out[w*64 + lane]      = v0 * inv * g[w*64 + lane];
    out[w*64 + lane + 32] = v1 * inv * g[w*64 + lane + 32];
}

__global__ void small_gemm_kernel(const float* __restrict__ A, const float* __restrict__ W,
                                  const float* __restrict__ addvec, float* __restrict__ C,
                                  int N, int K)
{
    __shared__ float a[768];
    int row = blockIdx.y;
    for (int i = threadIdx.x; i < K; i += 256) a[i] = A[(size_t)row*K + i];
    __syncthreads();
    int n = blockIdx.x * 256 + threadIdx.x;
    if (n >= N) return;
    float acc = addvec ? addvec[n] : 0.f;
#pragma unroll 4
    for (int k = 0; k < K; k++) acc += a[k] * W[(size_t)k*N + n];
    C[(size_t)row*N + n] = acc;
}

// ---------------------------------------------------------------------------
// Host side
// ---------------------------------------------------------------------------
extern "C" void kernel_launch(void* const* d_in, const int* in_sizes, int n_in,
                              void* d_out, int out_size)
{
    (void)in_sizes; (void)n_in; (void)out_size;
    const float* patches    = (const float*)d_in[0];
    const int*   ppos       = (const int*)  d_in[1];
    const int*   image_ids  = (const int*)  d_in[2];
    const int*   lengths    = (const int*)  d_in[3];
    const float* emb_ln_g   = (const float*)d_in[4];
    const float* W_emb      = (const float*)d_in[5];
    const float* b_emb      = (const float*)d_in[6];
    const float* emb_ln2_g  = (const float*)d_in[7];
    const float* pos_h      = (const float*)d_in[8];
    const float* pos_w      = (const float*)d_in[9];
    const float* ln_attn_g  = (const float*)d_in[10];
    const float* Wq         = (const float*)d_in[11];
    const float* Wkv        = (const float*)d_in[12];
    const float* qn_g       = (const float*)d_in[13];
    const float* kn_g       = (const float*)d_in[14];
    const float* Wo         = (const float*)d_in[15];
    const float* ln_ff_g    = (const float*)d_in[16];
    const float* W1         = (const float*)d_in[17];
    const float* b1         = (const float*)d_in[18];
    const float* W2         = (const float*)d_in[19];
    const float* b2         = (const float*)d_in[20];
    const float* final_ln_g = (const float*)d_in[21];
    const float* pool_q     = (const float*)d_in[22];
    const float* pool_ln_g  = (const float*)d_in[23];
    const float* pWq        = (const float*)d_in[24];
    const float* pWkv       = (const float*)d_in[25];
    const float* p_qn_g     = (const float*)d_in[26];
    const float* p_kn_g     = (const float*)d_in[27];
    const float* pWo        = (const float*)d_in[28];
    const float* head_ln_g  = (const float*)d_in[29];
    const float* W_head     = (const float*)d_in[30];

    float *x, *qkv, *kTf, *vTf, *sm, *pattn, *pool, *pln;
    __half *xn, *tmp, *ao, *w;
    __nv_bfloat16 *qTh, *qTl, *kTh, *kTl, *vTth, *vTtl;
    cudaGetSymbolAddress((void**)&x,    g_x);
    cudaGetSymbolAddress((void**)&qkv,  g_qkv);
    cudaGetSymbolAddress((void**)&kTf,  g_kTf);
    cudaGetSymbolAddress((void**)&vTf,  g_vTf);
    cudaGetSymbolAddress((void**)&sm,   g_sm);
    cudaGetSymbolAddress((void**)&pattn,g_pattn);
    cudaGetSymbolAddress((void**)&pool, g_pool);
    cudaGetSymbolAddress((void**)&pln,  g_pln);
    cudaGetSymbolAddress((void**)&xn,   g_xn);
    cudaGetSymbolAddress((void**)&tmp,  g_tmp);
    cudaGetSymbolAddress((void**)&ao,   g_ao);
    cudaGetSymbolAddress((void**)&qTh,  g_qTh);
    cudaGetSymbolAddress((void**)&qTl,  g_qTl);
    cudaGetSymbolAddress((void**)&kTh,  g_kTh);
    cudaGetSymbolAddress((void**)&kTl,  g_kTl);
    cudaGetSymbolAddress((void**)&vTth, g_vTth);
    cudaGetSymbolAddress((void**)&vTtl, g_vTtl);
    cudaGetSymbolAddress((void**)&w,    g_w);

    constexpr int SMEM128 = 65536;     // 2*(16384+16384)
    constexpr int SMEM256 = 98304;     // 2*(32768+16384)
    cudaFuncSetAttribute(mma_gemm<128>, cudaFuncAttributeMaxDynamicSharedMemorySize, SMEM128);
    cudaFuncSetAttribute(mma_gemm<256>, cudaFuncAttributeMaxDynamicSharedMemorySize, SMEM256);
    cudaFuncSetAttribute(flash_attn,    cudaFuncAttributeMaxDynamicSharedMemorySize, FA_SMEM);

    // ---- Convert + transpose weights to fp16 [N,K] ----
    dim3 wb(32, 8);
    wconv_kernel<<<dim3(DIM/32,  DIM/32),  wb>>>(W_emb, w + WOFF_EMB, DIM, DIM);
    for (int l = 0; l < 4; l++) {
        wconv_kernel<<<dim3(DIM/32,    DIM/32),  wb>>>(Wq  + (size_t)l*DIM*DIM,   w + WOFF_Q(l),  DIM,  DIM);
        wconv_kernel<<<dim3(2*DIM/32,  DIM/32),  wb>>>(Wkv + (size_t)l*DIM*2*DIM, w + WOFF_Q(l) + 589824ULL, DIM, 2*DIM);
        wconv_kernel<<<dim3(DIM/32,    DIM/32),  wb>>>(Wo  + (size_t)l*DIM*DIM,   w + WOFF_O(l),  DIM,  DIM);
        wconv_kernel<<<dim3(MLPD/32,   DIM/32),  wb>>>(W1  + (size_t)l*DIM*MLPD,  w + WOFF_W1(l), DIM,  MLPD);
        wconv_kernel<<<dim3(DIM/32,    MLPD/32), wb>>>(W2  + (size_t)l*MLPD*DIM,  w + WOFF_W2(l), MLPD, DIM);
    }
    wconv_kernel<<<dim3(2*DIM/32, DIM/32), wb>>>(pWkv, w + WOFF_PKV, DIM, 2*DIM);

    auto G128 = [&](const __half* a, const __half* bw,
                    const float* bias, const float* res,
                    float* C, __half* Ch, int M, int N, int K, int flags) {
        mma_gemm<128><<<dim3(N/128, M/128), 256, SMEM128>>>(a, bw, bias, res, C, Ch, M, N, K, flags);
    };
    auto G256 = [&](const __half* a, const __half* bw,
                    const float* bias, const float* res,
                    float* C, __half* Ch, int M, int N, int K, int flags) {
        mma_gemm<256><<<dim3(N/128, M/256), 256, SMEM256>>>(a, bw, bias, res, C, Ch, M, N, K, flags);
    };

    // ---- Embedding ----
    ln_kernel<<<TOKS, 256>>>(patches, emb_ln_g, nullptr, xn, nullptr, nullptr, nullptr);
    G128(xn, w + WOFF_EMB, b_emb, nullptr, x, nullptr, TOKS, DIM, DIM, FBIAS);
    ln_kernel<<<TOKS, 256>>>(x, emb_ln2_g, x, nullptr, pos_h, pos_w, ppos);

    // ---- Transformer layers ----
    for (int l = 0; l < 4; l++) {
        ln_kernel<<<TOKS, 256>>>(x, ln_attn_g + l*DIM, nullptr, xn, nullptr, nullptr, nullptr);
        G256(xn, w + WOFF_Q(l), nullptr, nullptr, qkv, nullptr, TOKS, 2304, DIM, 0);
        rmsT_all<<<TOKS, 384>>>(qkv, qn_g + l*DIM, kn_g + l*DIM, qTh, qTl, kTh, kTl, vTth, vTtl);
        flash_attn<<<dim3(8, BH), 256, FA_SMEM>>>(qTh, qTl, kTh, kTl, vTth, vTtl,
                                                  image_ids, lengths, ao);
        G128(ao, w + WOFF_O(l), nullptr, x, x, nullptr, TOKS, DIM, DIM, FRES);
        ln_kernel<<<TOKS, 256>>>(x, ln_ff_g + l*DIM, nullptr, xn, nullptr, nullptr, nullptr);
        G256(xn, w + WOFF_W1(l), b1 + l*MLPD, nullptr, nullptr, tmp, TOKS, MLPD, DIM, FBIAS|FGELU);
        G128(tmp, w + WOFF_W2(l), b2 + l*DIM, x, x, nullptr, TOKS, DIM, MLPD, FBIAS|FRES);
    }

    // ---- Final LN ----
    ln_kernel<<<TOKS, 256>>>(x, final_ln_g, nullptr, xn, nullptr, nullptr, nullptr);

    // ---- Attention pooling ----
    ln_kernel<<<1, 256>>>(pool_q, pool_ln_g, sm, nullptr, nullptr, nullptr, nullptr);
    small_gemm_kernel<<<dim3(3, 1), 256>>>(sm, pWq, nullptr, sm + 768, DIM, DIM);
    rms_vec_kernel<<<1, 384>>>(sm + 768, p_qn_g, sm + 1536);
    G256(xn, w + WOFF_PKV, nullptr, nullptr, qkv, nullptr, TOKS, 1536, DIM, 0);
    rmsT_f32<<<TOKS, 384>>>(qkv, 1536, 0,   p_kn_g, kTf);
    rmsT_f32<<<TOKS, 384>>>(qkv, 1536, 768, nullptr, vTf);
    pool_attn_kernel<<<NB*IMGS*NHEAD, 256>>>(sm + 1536, kTf, vTf, image_ids, lengths, pattn);
    small_gemm_kernel<<<dim3(3, 16), 256>>>(pattn, pWo, pool_q, pool, DIM, DIM);
    ln_kernel<<<16, 256>>>(pool, head_ln_g, pln, nullptr, nullptr, nullptr, nullptr);
    small_gemm_kernel<<<dim3(4, 16), 256>>>(pln, W_head, nullptr, (float*)d_out, NCLS, DIM);
}

// round 9
// speedup vs baseline: 4.6273x; 1.0004x over previous
#include <cuda_runtime.h>
#include <cuda_bf16.h>
#include <cuda_fp16.h>
#include <math.h>
#include <float.h>
#include <stdint.h>

// ---------------------------------------------------------------------------
// Problem constants
// ---------------------------------------------------------------------------
#define NB      4
#define NTOK    1024
#define DIM     768
#define NHEAD   12
#define DHEAD   64
#define MLPD    3072
#define IMGS    4
#define NCLS    1000
#define TOKS    (NB*NTOK)
#define BH      (NB*NHEAD)

#define FBIAS 1
#define FGELU 2
#define FRES  4

#define WOFF_EMB 0ULL
#define WPERL    7077888ULL
#define WOFF_L(l)   (589824ULL + (unsigned long long)(l)*WPERL)
#define WOFF_Q(l)   (WOFF_L(l) + 0ULL)
#define WOFF_O(l)   (WOFF_L(l) + 1769472ULL)
#define WOFF_W1(l)  (WOFF_L(l) + 2359296ULL)
#define WOFF_W2(l)  (WOFF_L(l) + 4718592ULL)
#define WOFF_PKV    (589824ULL + 4ULL*WPERL)
#define WTOTAL      30081024ULL

// ---------------------------------------------------------------------------
// Device scratch
// ---------------------------------------------------------------------------
__device__ float g_x   [TOKS*DIM];
__device__ float g_qkv [TOKS*2304];
__device__ __half g_xn  [TOKS*DIM];
__device__ __half g_tmp [TOKS*MLPD];
__device__ __half g_ao  [TOKS*DIM];
__device__ __nv_bfloat16 g_qTh[BH*NTOK*DHEAD], g_qTl[BH*NTOK*DHEAD];
__device__ __nv_bfloat16 g_kTh[BH*NTOK*DHEAD], g_kTl[BH*NTOK*DHEAD];
__device__ __nv_bfloat16 g_vTth[BH*DHEAD*NTOK], g_vTtl[BH*DHEAD*NTOK];
__device__ float g_kTf[BH*NTOK*DHEAD], g_vTf[BH*NTOK*DHEAD];
__device__ float g_sm  [4096];
__device__ float g_pattn[16*DIM];
__device__ float g_pool [16*DIM];
__device__ float g_pln  [16*DIM];
__device__ __half g_w[WTOTAL];

// ---------------------------------------------------------------------------
// Helpers
// ---------------------------------------------------------------------------
__device__ __forceinline__ uint32_t smem_u32(const void* p) {
    uint32_t a;
    asm("{ .reg .u64 t; cvta.to.shared.u64 t, %1; cvt.u32.u64 %0, t; }" : "=r"(a) : "l"(p));
    return a;
}

#define LDSM4(r, addr) \
    asm volatile("ldmatrix.sync.aligned.m8n8.x4.shared.b16 {%0,%1,%2,%3}, [%4];" \
        : "=r"((r)[0]), "=r"((r)[1]), "=r"((r)[2]), "=r"((r)[3]) : "r"(addr))

#define MMA16816(d, a, b) \
    asm volatile("mma.sync.aligned.m16n8k16.row.col.f32.bf16.bf16.f32 " \
        "{%0,%1,%2,%3}, {%4,%5,%6,%7}, {%8,%9}, {%0,%1,%2,%3};" \
        : "+f"((d)[0]), "+f"((d)[1]), "+f"((d)[2]), "+f"((d)[3]) \
        : "r"((a)[0]), "r"((a)[1]), "r"((a)[2]), "r"((a)[3]), "r"((b)[0]), "r"((b)[1]))

#define MMAH16816(d, a, b) \
    asm volatile("mma.sync.aligned.m16n8k16.row.col.f32.f16.f16.f32 " \
        "{%0,%1,%2,%3}, {%4,%5,%6,%7}, {%8,%9}, {%0,%1,%2,%3};" \
        : "+f"((d)[0]), "+f"((d)[1]), "+f"((d)[2]), "+f"((d)[3]) \
        : "r"((a)[0]), "r"((a)[1]), "r"((a)[2]), "r"((a)[3]), "r"((b)[0]), "r"((b)[1]))

#define CPA16(dst, src) \
    asm volatile("cp.async.cg.shared.global [%0], [%1], 16;" :: "r"(dst), "l"(src))
#define CP_COMMIT() asm volatile("cp.async.commit_group;" ::: "memory")
#define CP_WAIT0()  asm volatile("cp.async.wait_group 0;" ::: "memory")
#define CP_WAIT1()  asm volatile("cp.async.wait_group 1;" ::: "memory")
#define CP_WAIT2()  asm volatile("cp.async.wait_group 2;" ::: "memory")

__device__ __forceinline__ void split2(float v, __nv_bfloat16& h, __nv_bfloat16& l) {
    h = __float2bfloat16(v);
    l = __float2bfloat16(v - __bfloat162float(h));
}
__device__ __forceinline__ uint32_t bfu(__nv_bfloat16 b) { return (uint32_t)__bfloat16_as_ushort(b); }

template<typename T>
__device__ __forceinline__ void cpa_tile(uint32_t smbase, const T* __restrict__ g,
                                         int ldk, int chunks, int tid)
{
    for (int i = tid; i < chunks; i += 256) {
        int r = i >> 3, c = i & 7;
        uint32_t off = r * 128 + c * 16;
        uint32_t sw = off ^ ((off >> 3) & 0x70);
        CPA16(smbase + sw, g + (size_t)r * ldk + c * 8);
    }
}

// ---------------------------------------------------------------------------
// Weight convert+transpose: W[K,N] fp32 -> fp16 [N,K]
// ---------------------------------------------------------------------------
__global__ void wconv_kernel(const float* __restrict__ W, __half* __restrict__ out,
                             int K, int N)
{
    __shared__ float t[32][33];
    int n0 = blockIdx.x * 32, k0 = blockIdx.y * 32;
    int tx = threadIdx.x, ty = threadIdx.y;
#pragma unroll
    for (int r = 0; r < 4; r++)
        t[ty + r*8][tx] = W[(size_t)(k0 + ty + r*8) * N + n0 + tx];
    __syncthreads();
#pragma unroll
    for (int r = 0; r < 4; r++) {
        int n = n0 + ty + r*8, k = k0 + tx;
        out[(size_t)n * K + k] = __float2half(t[tx][ty + r*8]);
    }
}

// ---------------------------------------------------------------------------
// Pipelined mma.sync fp16 GEMM, single pass, 3-stage cp.async pipeline.
// MT=128: 8 warps 2Mx4N. MT=256: 8 warps 4Mx2N.
// ---------------------------------------------------------------------------
template<int MT>
__global__ void __launch_bounds__(256, 1) mma_gemm(
    const __half* __restrict__ A, const __half* __restrict__ B,
    const float* __restrict__ bias, const float* __restrict__ res,
    float* __restrict__ C, __half* __restrict__ Ch,
    int M, int N, int K, int flags)
{
    constexpr int WM   = MT / 64;
    constexpr int NQ   = (WM == 2) ? 2 : 4;
    constexpr int NTL  = 2 * NQ;
    constexpr int NCOL = NQ * 16;
    constexpr int A_SZ = MT * 128;
    constexpr int STG  = A_SZ + 16384;

    extern __shared__ char smem[];
    uint32_t uS = smem_u32(smem);

    const int tid = threadIdx.x;
    const int wid = tid >> 5, lane = tid & 31;
    const int m0 = blockIdx.y * MT, n0 = blockIdx.x * 128;
    const int wm = wid & (WM - 1), wn = wid / WM;

    const __half* Az = A + (size_t)m0 * K;
    const __half* Bz = B + (size_t)n0 * K;

    float acc[4][NTL][4] = {};

    const int a_row = wm * 64 + (lane & 15);
    const int a_cb  = (lane >> 4) * 16;
    const int b_row = wn * NCOL + (lane & 7) + ((lane >> 4) << 3);
    const int b_cb  = ((lane >> 3) & 1) * 16;

    const int KT = K >> 6;

    auto prefetch = [&](int kt) {
        uint32_t base = uS + (kt % 3) * STG;
        cpa_tile(base,        Az + kt * 64, K, MT * 8, tid);
        cpa_tile(base + A_SZ, Bz + kt * 64, K, 1024,   tid);
        CP_COMMIT();
    };

    prefetch(0);
    if (KT > 1) prefetch(1);

    for (int kt = 0; kt < KT; kt++) {
        if (kt + 2 < KT)      { prefetch(kt + 2); CP_WAIT2(); }
        else if (kt + 1 < KT) { CP_WAIT1(); }
        else                  { CP_WAIT0(); }
        __syncthreads();

        uint32_t bA = uS + (kt % 3) * STG;
        uint32_t bB = bA + A_SZ;

#pragma unroll
        for (int ks = 0; ks < 4; ks++) {
            uint32_t ah[4][4], bh[NQ][4];
#pragma unroll
            for (int mt = 0; mt < 4; mt++) {
                int row = a_row + mt * 16;
                uint32_t off = row * 128 + ((a_cb + ks * 32) ^ ((row & 7) << 4));
                LDSM4(ah[mt], bA + off);
            }
#pragma unroll
            for (int q = 0; q < NQ; q++) {
                int row = b_row + q * 16;
                uint32_t off = row * 128 + ((b_cb + ks * 32) ^ ((row & 7) << 4));
                LDSM4(bh[q], bB + off);
            }
#pragma unroll
            for (int mt = 0; mt < 4; mt++)
#pragma unroll
                for (int nt = 0; nt < NTL; nt++)
                    MMAH16816(acc[mt][nt], ah[mt], &bh[nt >> 1][(nt & 1) * 2]);
        }
        __syncthreads();
    }

    const int rbase = m0 + wm * 64;
#pragma unroll
    for (int mt = 0; mt < 4; mt++) {
#pragma unroll
        for (int nt = 0; nt < NTL; nt++) {
            int c = n0 + wn * NCOL + nt * 8 + (lane & 3) * 2;
            float bv0 = 0.f, bv1 = 0.f;
            if (flags & FBIAS) { bv0 = bias[c]; bv1 = bias[c + 1]; }
#pragma unroll
            for (int half = 0; half < 2; half++) {
                int r = rbase + mt * 16 + (lane >> 2) + half * 8;
                float v0 = acc[mt][nt][half * 2 + 0];
                float v1 = acc[mt][nt][half * 2 + 1];
                if (flags & FBIAS) { v0 += bv0; v1 += bv1; }
                if (flags & FGELU) {
                    v0 = 0.5f * v0 * (1.f + erff(v0 * 0.70710678118654752f));
                    v1 = 0.5f * v1 * (1.f + erff(v1 * 0.70710678118654752f));
                }
                long idx = (long)r * N + c;
                if (flags & FRES) { v0 += res[idx]; v1 += res[idx + 1]; }
                if (C) *(float2*)(C + idx) = make_float2(v0, v1);
                if (Ch) {
                    __half2 hv = __floats2half2_rn(v0, v1);
                    *(__half2*)(Ch + idx) = hv;
                }
            }
        }
    }
}

// ---------------------------------------------------------------------------
// Fused flash attention (bf16 3-pass; fp16 output).
// ---------------------------------------------------------------------------
#define FA_SMEM 165504

__global__ void __launch_bounds__(256, 1) flash_attn(
    const __nv_bfloat16* __restrict__ Qh_, const __nv_bfloat16* __restrict__ Ql_,
    const __nv_bfloat16* __restrict__ Kh_, const __nv_bfloat16* __restrict__ Kl_,
    const __nv_bfloat16* __restrict__ Vh_, const __nv_bfloat16* __restrict__ Vl_,
    const int* __restrict__ image_ids, const int* __restrict__ lengths,
    __half* __restrict__ O_)
{
    extern __shared__ char smem[];
    uint32_t uS = smem_u32(smem);
    const int tid = threadIdx.x, wid = tid >> 5, lane = tid & 31;
    const int z = blockIdx.y, b = z / 12, h = z % 12;
    const int m0 = blockIdx.x * 128;

    int* s_cmin   = (int*)(smem + 163840);
    int* s_cmax   = s_cmin + 8;
    int* s_jlist  = s_cmax + 8;
    int* s_meta   = s_jlist + 8;
    int* s_imgRow = s_meta + 8;
    int* s_imgCol = s_imgRow + 128;

    const int len = lengths[b];

    {
        int4 v = *(const int4*)(image_ids + b*1024 + wid*128 + lane*4);
        int mn = min(min(v.x, v.y), min(v.z, v.w));
        int mx = max(max(v.x, v.y), max(v.z, v.w));
#pragma unroll
        for (int o = 16; o; o >>= 1) {
            mn = min(mn, __shfl_xor_sync(0xffffffffu, mn, o));
            mx = max(mx, __shfl_xor_sync(0xffffffffu, mx, o));
        }
        if (lane == 0) { s_cmin[wid] = mn; s_cmax[wid] = mx; }
    }
    if (tid < 128) s_imgRow[tid] = image_ids[b*1024 + m0 + tid];
    __syncthreads();
    if (tid == 0) {
        int rmin = s_cmin[blockIdx.x], rmax = s_cmax[blockIdx.x];
        int nj = 0;
        for (int jb = 0; jb < 8; jb++)
            if (jb * 128 < len && s_cmax[jb] >= rmin && s_cmin[jb] <= rmax)
                s_jlist[nj++] = jb;
        s_meta[0] = nj;
    }
    __syncthreads();
    const int nj = s_meta[0];

    const size_t qoff = ((size_t)z * 1024 + m0) * 64;
    cpa_tile(uS,         Qh_ + qoff, 64, 1024, tid);
    cpa_tile(uS + 16384, Ql_ + qoff, 64, 1024, tid);

    auto prefetch = [&](int t) {
        int jb = s_jlist[t];
        int st = t & 1;
        uint32_t base = uS + 32768 + st * 65536;
        size_t koff = ((size_t)z * 1024 + jb * 128) * 64;
        cpa_tile(base,         Kh_ + koff, 64, 1024, tid);
        cpa_tile(base + 16384, Kl_ + koff, 64, 1024, tid);
        const __nv_bfloat16* vh = Vh_ + (size_t)z * 64 * 1024 + jb * 128;
        const __nv_bfloat16* vl = Vl_ + (size_t)z * 64 * 1024 + jb * 128;
        for (int i = tid; i < 1024; i += 256) {
            int r = i >> 4, c = i & 15;
            int kc = c >> 3, cc = c & 7;
            uint32_t off = r * 128 + cc * 16;
            uint32_t sw = off ^ ((off >> 3) & 0x70);
            CPA16(base + 32768 + kc * 8192 + sw, vh + (size_t)r * 1024 + c * 8);
            CPA16(base + 49152 + kc * 8192 + sw, vl + (size_t)r * 1024 + c * 8);
        }
        if (tid < 128) s_imgCol[st * 128 + tid] = image_ids[b*1024 + jb*128 + tid];
    };
    prefetch(0);
    CP_COMMIT();

    float O[8][4] = {};
    float mA = -FLT_MAX, mB = -FLT_MAX, lA = 0.f, lB = 0.f;
    uint32_t qh[4][4], ql[4][4];
    bool qloaded = false;

    const int rA = lane >> 2;
    const int imgA = s_imgRow[wid * 16 + rA];
    const int imgB = s_imgRow[wid * 16 + rA + 8];

    const int a_row = wid * 16 + (lane & 15);
    const int a_cb  = (lane >> 4) * 16;
    const int b_row_base = (lane & 7) + ((lane >> 4) << 3);
    const int b_cb  = ((lane >> 3) & 1) * 16;

    for (int t = 0; t < nj; t++) {
        if (t + 1 < nj) { prefetch(t + 1); CP_COMMIT(); CP_WAIT1(); }
        else CP_WAIT0();
        __syncthreads();

        if (!qloaded) {
            qloaded = true;
#pragma unroll
            for (int ks = 0; ks < 4; ks++) {
                uint32_t off = a_row * 128 + ((a_cb + ks * 32) ^ ((a_row & 7) << 4));
                LDSM4(qh[ks], uS + off);
                LDSM4(ql[ks], uS + 16384 + off);
            }
        }

        int st = t & 1;
        uint32_t bK  = uS + 32768 + st * 65536;
        uint32_t bKl = bK + 16384;
        uint32_t bV  = bK + 32768;
        uint32_t bVl = bK + 49152;
        int jb = s_jlist[t];
        int j0 = jb * 128;
        const int* imgC = s_imgCol + st * 128;

        float S[16][4] = {};
#pragma unroll
        for (int ks = 0; ks < 4; ks++) {
#pragma unroll
            for (int nb = 0; nb < 8; nb++) {
                uint32_t bh4[4], bl4[4];
                int row = nb * 16 + b_row_base;
                uint32_t off = row * 128 + ((b_cb + ks * 32) ^ ((row & 7) << 4));
                LDSM4(bh4, bK + off);
                LDSM4(bl4, bKl + off);
                MMA16816(S[2*nb],   qh[ks], bh4);
                MMA16816(S[2*nb+1], qh[ks], bh4 + 2);
                MMA16816(S[2*nb],   qh[ks], bl4);
                MMA16816(S[2*nb+1], qh[ks], bl4 + 2);
                MMA16816(S[2*nb],   ql[ks], bh4);
                MMA16816(S[2*nb+1], ql[ks], bh4 + 2);
            }
        }

        float mnA = mA, mnB = mB;
#pragma unroll
        for (int nt = 0; nt < 16; nt++) {
            int c0 = nt * 8 + (lane & 3) * 2;
            int i0 = imgC[c0], i1 = imgC[c0 + 1];
            bool v0 = (j0 + c0) < len, v1 = (j0 + c0 + 1) < len;
            if (i0 == imgA && v0) mnA = fmaxf(mnA, S[nt][0]);
            if (i1 == imgA && v1) mnA = fmaxf(mnA, S[nt][1]);
            if (i0 == imgB && v0) mnB = fmaxf(mnB, S[nt][2]);
            if (i1 == imgB && v1) mnB = fmaxf(mnB, S[nt][3]);
        }
#pragma unroll
        for (int o = 1; o <= 2; o <<= 1) {
            mnA = fmaxf(mnA, __shfl_xor_sync(0xffffffffu, mnA, o));
            mnB = fmaxf(mnB, __shfl_xor_sync(0xffffffffu, mnB, o));
        }
        float scA = __expf(mA - mnA), scB = __expf(mB - mnB);
        mA = mnA; mB = mnB;
        lA *= scA; lB *= scB;
#pragma unroll
        for (int nt = 0; nt < 16; nt++) {
            int c0 = nt * 8 + (lane & 3) * 2;
            int i0 = imgC[c0], i1 = imgC[c0 + 1];
            bool v0 = (j0 + c0) < len, v1 = (j0 + c0 + 1) < len;
            float p0 = (i0 == imgA && v0) ? __expf(S[nt][0] - mnA) : 0.f;
            float p1 = (i1 == imgA && v1) ? __expf(S[nt][1] - mnA) : 0.f;
            float p2 = (i0 == imgB && v0) ? __expf(S[nt][2] - mnB) : 0.f;
            float p3 = (i1 == imgB && v1) ? __expf(S[nt][3] - mnB) : 0.f;
            lA += p0 + p1; lB += p2 + p3;
            S[nt][0] = p0; S[nt][1] = p1; S[nt][2] = p2; S[nt][3] = p3;
        }
#pragma unroll
        for (int nt = 0; nt < 8; nt++) {
            O[nt][0] *= scA; O[nt][1] *= scA; O[nt][2] *= scB; O[nt][3] *= scB;
        }

#pragma unroll
        for (int kt = 0; kt < 8; kt++) {
            uint32_t ah4[4], al4[4];
            {
                __nv_bfloat16 h0, l0, h1, l1;
                split2(S[2*kt][0], h0, l0);   split2(S[2*kt][1], h1, l1);
                ah4[0] = bfu(h0) | (bfu(h1) << 16);  al4[0] = bfu(l0) | (bfu(l1) << 16);
                split2(S[2*kt][2], h0, l0);   split2(S[2*kt][3], h1, l1);
                ah4[1] = bfu(h0) | (bfu(h1) << 16);  al4[1] = bfu(l0) | (bfu(l1) << 16);
                split2(S[2*kt+1][0], h0, l0); split2(S[2*kt+1][1], h1, l1);
                ah4[2] = bfu(h0) | (bfu(h1) << 16);  al4[2] = bfu(l0) | (bfu(l1) << 16);
                split2(S[2*kt+1][2], h0, l0); split2(S[2*kt+1][3], h1, l1);
                ah4[3] = bfu(h0) | (bfu(h1) << 16);  al4[3] = bfu(l0) | (bfu(l1) << 16);
            }
            uint32_t tb  = bV  + (kt >> 2) * 8192;
            uint32_t tbl = bVl + (kt >> 2) * 8192;
#pragma unroll
            for (int nb = 0; nb < 4; nb++) {
                uint32_t vh4[4], vl4[4];
                int row = nb * 16 + b_row_base;
                uint32_t off = row * 128 + ((b_cb + (kt & 3) * 32) ^ ((row & 7) << 4));
                LDSM4(vh4, tb + off);
                LDSM4(vl4, tbl + off);
                MMA16816(O[2*nb],   ah4, vh4);
                MMA16816(O[2*nb+1], ah4, vh4 + 2);
                MMA16816(O[2*nb],   ah4, vl4);
                MMA16816(O[2*nb+1], ah4, vl4 + 2);
                MMA16816(O[2*nb],   al4, vh4);
                MMA16816(O[2*nb+1], al4, vh4 + 2);
            }
        }
        __syncthreads();
    }

#pragma unroll
    for (int o = 1; o <= 2; o <<= 1) {
        lA += __shfl_xor_sync(0xffffffffu, lA, o);
        lB += __shfl_xor_sync(0xffffffffu, lB, o);
    }
    float iA = lA > 0.f ? 1.f / lA : 0.f;
    float iB = lB > 0.f ? 1.f / lB : 0.f;
    size_t rowA = (size_t)(b * 1024 + m0 + wid * 16 + rA);
#pragma unroll
    for (int nt = 0; nt < 8; nt++) {
        int c = nt * 8 + (lane & 3) * 2;
        size_t idx = rowA * 768 + h * 64 + c;
        *(__half2*)(O_ + idx) = __floats2half2_rn(O[nt][0] * iA, O[nt][1] * iA);
        idx = (rowA + 8) * 768 + h * 64 + c;
        *(__half2*)(O_ + idx) = __floats2half2_rn(O[nt][2] * iB, O[nt][3] * iB);
    }
}

// ---------------------------------------------------------------------------
// LayerNorm over width 768. fp32 and/or fp16 outputs. Optional pos add.
// ---------------------------------------------------------------------------
__global__ void ln_kernel(const float* __restrict__ in, const float* __restrict__ g,
                          float* __restrict__ outf, __half* __restrict__ outh,
                          const float* __restrict__ pos_h, const float* __restrict__ pos_w,
                          const int* __restrict__ ppos)
{
    int row = blockIdx.x;
    int tid = threadIdx.x;
    const float* xr = in + (size_t)row * 768;
    float v[3]; float s = 0.f, q = 0.f;
#pragma unroll
    for (int i = 0; i < 3; i++) { float t = xr[tid + i*256]; v[i] = t; s += t; q += t*t; }
#pragma unroll
    for (int o = 16; o; o >>= 1) {
        s += __shfl_xor_sync(0xffffffffu, s, o);
        q += __shfl_xor_sync(0xffffffffu, q, o);
    }
    __shared__ float shs[8], shq[8], st[2];
    int w = tid >> 5;
    if ((tid & 31) == 0) { shs[w] = s; shq[w] = q; }
    __syncthreads();
    if (tid == 0) {
        float S = 0.f, Q = 0.f;
#pragma unroll
        for (int i = 0; i < 8; i++) { S += shs[i]; Q += shq[i]; }
        float mu = S * (1.f/768.f);
        st[0] = mu;
        st[1] = rsqrtf(Q * (1.f/768.f) - mu*mu + 1e-5f);
    }
    __syncthreads();
    float mu = st[0], rs = st[1];
    int p0 = 0, p1 = 0;
    if (ppos) { p0 = ppos[row*2]; p1 = ppos[row*2 + 1]; }
#pragma unroll
    for (int i = 0; i < 3; i++) {
        int c = tid + i*256;
        float y = (v[i] - mu) * rs * g[c];
        if (ppos) y += pos_h[p0*768 + c] + pos_w[p1*768 + c];
        size_t idx = (size_t)row*768 + c;
        if (outf) outf[idx] = y;
        if (outh) outh[idx] = __float2half(y);
    }
}

// ---------------------------------------------------------------------------
// Fused QKV postprocess (bf16 hi/lo outputs for flash).
// ---------------------------------------------------------------------------
__global__ void rmsT_all(const float* __restrict__ qkv,
                         const float* __restrict__ qg, const float* __restrict__ kg,
                         __nv_bfloat16* __restrict__ qh, __nv_bfloat16* __restrict__ ql,
                         __nv_bfloat16* __restrict__ kh, __nv_bfloat16* __restrict__ kl,
                         __nv_bfloat16* __restrict__ vh, __nv_bfloat16* __restrict__ vl)
{
    int token = blockIdx.x;
    int b = token >> 10, n = token & 1023;
    int w = threadIdx.x >> 5, lane = threadIdx.x & 31;
    const float* base = qkv + (size_t)token * 2304 + w * 64;
    __nv_bfloat16 hh, ll;

    {
        float v0 = base[lane], v1 = base[lane + 32];
        float ss = v0*v0 + v1*v1;
#pragma unroll
        for (int o = 16; o; o >>= 1) ss += __shfl_xor_sync(0xffffffffu, ss, o);
        float inv = 8.0f / fmaxf(sqrtf(ss), 1e-12f);
        v0 *= inv * qg[w*64 + lane];
        v1 *= inv * qg[w*64 + lane + 32];
        size_t dst = ((size_t)(b*12 + w) * 1024 + n) * 64;
        split2(v0, hh, ll); qh[dst + lane] = hh;      ql[dst + lane] = ll;
        split2(v1, hh, ll); qh[dst + lane + 32] = hh; ql[dst + lane + 32] = ll;
    }
    {
        float v0 = base[768 + lane], v1 = base[768 + lane + 32];
        float ss = v0*v0 + v1*v1;
#pragma unroll
        for (int o = 16; o; o >>= 1) ss += __shfl_xor_sync(0xffffffffu, ss, o);
        float inv = 8.0f / fmaxf(sqrtf(ss), 1e-12f);
        v0 *= inv * kg[w*64 + lane];
        v1 *= inv * kg[w*64 + lane + 32];
        size_t dst = ((size_t)(b*12 + w) * 1024 + n) * 64;
        split2(v0, hh, ll); kh[dst + lane] = hh;      kl[dst + lane] = ll;
        split2(v1, hh, ll); kh[dst + lane + 32] = hh; kl[dst + lane + 32] = ll;
    }
    {
        float v0 = base[1536 + lane], v1 = base[1536 + lane + 32];
        size_t vb = ((size_t)(b*12 + w) * 64) * 1024 + n;
        split2(v0, hh, ll); vh[vb + (size_t)lane * 1024] = hh;        vl[vb + (size_t)lane * 1024] = ll;
        split2(v1, hh, ll); vh[vb + (size_t)(lane + 32) * 1024] = hh; vl[vb + (size_t)(lane + 32) * 1024] = ll;
    }
}

// Pool-path: one launch does k-rms + v copy (fp32 outputs).
__global__ void rmsT_pool(const float* __restrict__ kv,
                          const float* __restrict__ kg,
                          float* __restrict__ kT, float* __restrict__ vT)
{
    int token = blockIdx.x;
    int b = token >> 10, n = token & 1023;
    int w = threadIdx.x >> 5, lane = threadIdx.x & 31;
    const float* base = kv + (size_t)token * 1536 + w * 64;
    {
        float v0 = base[lane], v1 = base[lane + 32];
        float ss = v0*v0 + v1*v1;
#pragma unroll
        for (int o = 16; o; o >>= 1) ss += __shfl_xor_sync(0xffffffffu, ss, o);
        float inv = 8.0f / fmaxf(sqrtf(ss), 1e-12f);
        float* dst = kT + ((size_t)(b*12 + w) * 1024 + n) * 64;
        dst[lane]      = v0 * inv * kg[w*64 + lane];
        dst[lane + 32] = v1 * inv * kg[w*64 + lane + 32];
    }
    {
        float v0 = base[768 + lane], v1 = base[768 + lane + 32];
        float* dst = vT + ((size_t)(b*12 + w) * 1024 + n) * 64;
        dst[lane] = v0; dst[lane + 32] = v1;
    }
}

// ---------------------------------------------------------------------------
// Attention pooling (192 blocks), fp32 path.
// ---------------------------------------------------------------------------
__global__ void pool_attn_kernel(const float* __restrict__ pqn, const float* __restrict__ kT,
                                 const float* __restrict__ vT, const int* __restrict__ image_ids,
                                 const int* __restrict__ lengths, float* __restrict__ out)
{
    int idx = blockIdx.x;
    int h = idx % 12, img = (idx / 12) % 4, b = idx / 48;
    int tid = threadIdx.x;
    __shared__ float q[64];
    __shared__ float p[1024];
    __shared__ float sh[8];
    __shared__ float bs[2];
    __shared__ float sred[256];
    if (tid < 64) q[tid] = pqn[h*64 + tid];
    __syncthreads();

    const float* K = kT + (size_t)(b*12 + h) * 1024 * 64;
    int len = lengths[b];
    float loc[4]; float mx = -FLT_MAX;
#pragma unroll
    for (int t = 0; t < 4; t++) {
        int j = tid + t*256;
        const float* kr = K + (size_t)j * 64;
        float dot = 0.f;
#pragma unroll
        for (int d = 0; d < 64; d++) dot += q[d] * kr[d];
        bool ok = (image_ids[b*1024 + j] == img) && (j < len);
        loc[t] = ok ? dot : -FLT_MAX;
        mx = fmaxf(mx, loc[t]);
    }
#pragma unroll
    for (int o = 16; o; o >>= 1) mx = fmaxf(mx, __shfl_xor_sync(0xffffffffu, mx, o));
    int w = tid >> 5;
    if ((tid & 31) == 0) sh[w] = mx;
    __syncthreads();
    if (tid == 0) { float mm = sh[0]; for (int i = 1; i < 8; i++) mm = fmaxf(mm, sh[i]); bs[0] = mm; }
    __syncthreads();
    mx = bs[0];
    float s = 0.f;
#pragma unroll
    for (int t = 0; t < 4; t++) {
        float e = __expf(loc[t] - mx);
        p[tid + t*256] = e;
        s += e;
    }
#pragma unroll
    for (int o = 16; o; o >>= 1) s += __shfl_xor_sync(0xffffffffu, s, o);
    if ((tid & 31) == 0) sh[w] = s;
    __syncthreads();
    if (tid == 0) { float ss = 0.f; for (int i = 0; i < 8; i++) ss += sh[i]; bs[1] = 1.f / ss; }
    __syncthreads();
    float inv = bs[1];

    const float* V = vT + (size_t)(b*12 + h) * 1024 * 64;
    int d = tid & 63, grp = tid >> 6;
    float acc = 0.f;
    for (int j = grp; j < 1024; j += 4) acc += p[j] * V[(size_t)j*64 + d];
    sred[tid] = acc;
    __syncthreads();
    if (grp == 0) {
        float r = (sred[d] + sred[d + 64]) + (sred[d + 128] + sred[d + 192]);
        out[(size_t)(b*4 + img) * 768 + h*64 + d] = r * inv;
    }
}

__global__ void rms_vec_kernel(const float* __restrict__ in, const float* __restrict__ g,
                               float* __restrict__ out)
{
    int w = threadIdx.x >> 5, lane = threadIdx.x & 31;
    float v0 = in[w*64 + lane], v1 = in[w*64 + lane + 32];
    float ss = v0*v0 + v1*v1;
#pragma unroll
    for (int o = 16; o; o >>= 1) ss += __shfl_xor_sync(0xffffffffu, ss, o);
    float inv = 8.0f / fmaxf(sqrtf(ss), 1e-12f);
    out[w*64 + lane]      = v0 * inv * g[w*64 + lane];
    out[w*64 + lane + 32] = v1 * inv * g[w*64 + lane + 32];
}

__global__ void small_gemm_kernel(const float* __restrict__ A, const float* __restrict__ W,
                                  const float* __restrict__ addvec, float* __restrict__ C,
                                  int N, int K)
{
    __shared__ float a[768];
    int row = blockIdx.y;
    for (int i = threadIdx.x; i < K; i += 256) a[i] = A[(size_t)row*K + i];
    __syncthreads();
    int n = blockIdx.x * 256 + threadIdx.x;
    if (n >= N) return;
    float acc = addvec ? addvec[n] : 0.f;
#pragma unroll 4
    for (int k = 0; k < K; k++) acc += a[k] * W[(size_t)k*N + n];
    C[(size_t)row*N + n] = acc;
}

// ---------------------------------------------------------------------------
// Host side
// ---------------------------------------------------------------------------
extern "C" void kernel_launch(void* const* d_in, const int* in_sizes, int n_in,
                              void* d_out, int out_size)
{
    (void)in_sizes; (void)n_in; (void)out_size;
    const float* patches    = (const float*)d_in[0];
    const int*   ppos       = (const int*)  d_in[1];
    const int*   image_ids  = (const int*)  d_in[2];
    const int*   lengths    = (const int*)  d_in[3];
    const float* emb_ln_g   = (const float*)d_in[4];
    const float* W_emb      = (const float*)d_in[5];
    const float* b_emb      = (const float*)d_in[6];
    const float* emb_ln2_g  = (const float*)d_in[7];
    const float* pos_h      = (const float*)d_in[8];
    const float* pos_w      = (const float*)d_in[9];
    const float* ln_attn_g  = (const float*)d_in[10];
    const float* Wq         = (const float*)d_in[11];
    const float* Wkv        = (const float*)d_in[12];
    const float* qn_g       = (const float*)d_in[13];
    const float* kn_g       = (const float*)d_in[14];
    const float* Wo         = (const float*)d_in[15];
    const float* ln_ff_g    = (const float*)d_in[16];
    const float* W1         = (const float*)d_in[17];
    const float* b1         = (const float*)d_in[18];
    const float* W2         = (const float*)d_in[19];
    const float* b2         = (const float*)d_in[20];
    const float* final_ln_g = (const float*)d_in[21];
    const float* pool_q     = (const float*)d_in[22];
    const float* pool_ln_g  = (const float*)d_in[23];
    const float* pWq        = (const float*)d_in[24];
    const float* pWkv       = (const float*)d_in[25];
    const float* p_qn_g     = (const float*)d_in[26];
    const float* p_kn_g     = (const float*)d_in[27];
    const float* pWo        = (const float*)d_in[28];
    const float* head_ln_g  = (const float*)d_in[29];
    const float* W_head     = (const float*)d_in[30];

    float *x, *qkv, *kTf, *vTf, *sm, *pattn, *pool, *pln;
    __half *xn, *tmp, *ao, *w;
    __nv_bfloat16 *qTh, *qTl, *kTh, *kTl, *vTth, *vTtl;
    cudaGetSymbolAddress((void**)&x,    g_x);
    cudaGetSymbolAddress((void**)&qkv,  g_qkv);
    cudaGetSymbolAddress((void**)&kTf,  g_kTf);
    cudaGetSymbolAddress((void**)&vTf,  g_vTf);
    cudaGetSymbolAddress((void**)&sm,   g_sm);
    cudaGetSymbolAddress((void**)&pattn,g_pattn);
    cudaGetSymbolAddress((void**)&pool, g_pool);
    cudaGetSymbolAddress((void**)&pln,  g_pln);
    cudaGetSymbolAddress((void**)&xn,   g_xn);
    cudaGetSymbolAddress((void**)&tmp,  g_tmp);
    cudaGetSymbolAddress((void**)&ao,   g_ao);
    cudaGetSymbolAddress((void**)&qTh,  g_qTh);
    cudaGetSymbolAddress((void**)&qTl,  g_qTl);
    cudaGetSymbolAddress((void**)&kTh,  g_kTh);
    cudaGetSymbolAddress((void**)&kTl,  g_kTl);
    cudaGetSymbolAddress((void**)&vTth, g_vTth);
    cudaGetSymbolAddress((void**)&vTtl, g_vTtl);
    cudaGetSymbolAddress((void**)&w,    g_w);

    constexpr int SMEM128 = 98304;     // 3*(16384+16384)
    constexpr int SMEM256 = 147456;    // 3*(32768+16384)
    cudaFuncSetAttribute(mma_gemm<128>, cudaFuncAttributeMaxDynamicSharedMemorySize, SMEM128);
    cudaFuncSetAttribute(mma_gemm<256>, cudaFuncAttributeMaxDynamicSharedMemorySize, SMEM256);
    cudaFuncSetAttribute(flash_attn,    cudaFuncAttributeMaxDynamicSharedMemorySize, FA_SMEM);

    // ---- Convert + transpose weights to fp16 [N,K] ----
    dim3 wb(32, 8);
    wconv_kernel<<<dim3(DIM/32,  DIM/32),  wb>>>(W_emb, w + WOFF_EMB, DIM, DIM);
    for (int l = 0; l < 4; l++) {
        wconv_kernel<<<dim3(DIM/32,    DIM/32),  wb>>>(Wq  + (size_t)l*DIM*DIM,   w + WOFF_Q(l),  DIM,  DIM);
        wconv_kernel<<<dim3(2*DIM/32,  DIM/32),  wb>>>(Wkv + (size_t)l*DIM*2*DIM, w + WOFF_Q(l) + 589824ULL, DIM, 2*DIM);
        wconv_kernel<<<dim3(DIM/32,    DIM/32),  wb>>>(Wo  + (size_t)l*DIM*DIM,   w + WOFF_O(l),  DIM,  DIM);
        wconv_kernel<<<dim3(MLPD/32,   DIM/32),  wb>>>(W1  + (size_t)l*DIM*MLPD,  w + WOFF_W1(l), DIM,  MLPD);
        wconv_kernel<<<dim3(DIM/32,    MLPD/32), wb>>>(W2  + (size_t)l*MLPD*DIM,  w + WOFF_W2(l), MLPD, DIM);
    }
    wconv_kernel<<<dim3(2*DIM/32, DIM/32), wb>>>(pWkv, w + WOFF_PKV, DIM, 2*DIM);

    auto G128 = [&](const __half* a, const __half* bw,
                    const float* bias, const float* res,
                    float* C, __half* Ch, int M, int N, int K, int flags) {
        mma_gemm<128><<<dim3(N/128, M/128), 256, SMEM128>>>(a, bw, bias, res, C, Ch, M, N, K, flags);
    };
    auto G256 = [&](const __half* a, const __half* bw,
                    const float* bias, const float* res,
                    float* C, __half* Ch, int M, int N, int K, int flags) {
        mma_gemm<256><<<dim3(N/128, M/256), 256, SMEM256>>>(a, bw, bias, res, C, Ch, M, N, K, flags);
    };

    // ---- Embedding ----
    ln_kernel<<<TOKS, 256>>>(patches, emb_ln_g, nullptr, xn, nullptr, nullptr, nullptr);
    G128(xn, w + WOFF_EMB, b_emb, nullptr, x, nullptr, TOKS, DIM, DIM, FBIAS);
    ln_kernel<<<TOKS, 256>>>(x, emb_ln2_g, x, nullptr, pos_h, pos_w, ppos);

    // ---- Transformer layers ----
    for (int l = 0; l < 4; l++) {
        ln_kernel<<<TOKS, 256>>>(x, ln_attn_g + l*DIM, nullptr, xn, nullptr, nullptr, nullptr);
        G256(xn, w + WOFF_Q(l), nullptr, nullptr, qkv, nullptr, TOKS, 2304, DIM, 0);
        rmsT_all<<<TOKS, 384>>>(qkv, qn_g + l*DIM, kn_g + l*DIM, qTh, qTl, kTh, kTl, vTth, vTtl);
        flash_attn<<<dim3(8, BH), 256, FA_SMEM>>>(qTh, qTl, kTh, kTl, vTth, vTtl,
                                                  image_ids, lengths, ao);
        G128(ao, w + WOFF_O(l), nullptr, x, x, nullptr, TOKS, DIM, DIM, FRES);
        ln_kernel<<<TOKS, 256>>>(x, ln_ff_g + l*DIM, nullptr, xn, nullptr, nullptr, nullptr);
        G256(xn, w + WOFF_W1(l), b1 + l*MLPD, nullptr, nullptr, tmp, TOKS, MLPD, DIM, FBIAS|FGELU);
        G128(tmp, w + WOFF_W2(l), b2 + l*DIM, x, x, nullptr, TOKS, DIM, MLPD, FBIAS|FRES);
    }

    // ---- Final LN ----
    ln_kernel<<<TOKS, 256>>>(x, final_ln_g, nullptr, xn, nullptr, nullptr, nullptr);

    // ---- Attention pooling ----
    ln_kernel<<<1, 256>>>(pool_q, pool_ln_g, sm, nullptr, nullptr, nullptr, nullptr);
    small_gemm_kernel<<<dim3(3, 1), 256>>>(sm, pWq, nullptr, sm + 768, DIM, DIM);
    rms_vec_kernel<<<1, 384>>>(sm + 768, p_qn_g, sm + 1536);
    G256(xn, w + WOFF_PKV, nullptr, nullptr, qkv, nullptr, TOKS, 1536, DIM, 0);
    rmsT_pool<<<TOKS, 384>>>(qkv, p_kn_g, kTf, vTf);
    pool_attn_kernel<<<NB*IMGS*NHEAD, 256>>>(sm + 1536, kTf, vTf, image_ids, lengths, pattn);
    small_gemm_kernel<<<dim3(3, 16), 256>>>(pattn, pWo, pool_q, pool, DIM, DIM);
    ln_kernel<<<16, 256>>>(pool, head_ln_g, pln, nullptr, nullptr, nullptr, nullptr);
    small_gemm_kernel<<<dim3(4, 16), 256>>>(pln, W_head, nullptr, (float*)d_out, NCLS, DIM);
}

// round 10
// speedup vs baseline: 5.1001x; 1.1022x over previous
#include <cuda_runtime.h>
#include <cuda_bf16.h>
#include <cuda_fp16.h>
#include <math.h>
#include <float.h>
#include <stdint.h>

// ---------------------------------------------------------------------------
// Problem constants
// ---------------------------------------------------------------------------
#define NB      4
#define NTOK    1024
#define DIM     768
#define NHEAD   12
#define DHEAD   64
#define MLPD    3072
#define IMGS    4
#define NCLS    1000
#define TOKS    (NB*NTOK)
#define BH      (NB*NHEAD)

#define FBIAS 1
#define FGELU 2
#define FRES  4

#define WOFF_EMB 0ULL
#define WPERL    7077888ULL
#define WOFF_L(l)   (589824ULL + (unsigned long long)(l)*WPERL)
#define WOFF_Q(l)   (WOFF_L(l) + 0ULL)
#define WOFF_KV(l)  (WOFF_L(l) + 589824ULL)
#define WOFF_O(l)   (WOFF_L(l) + 1769472ULL)
#define WOFF_W1(l)  (WOFF_L(l) + 2359296ULL)
#define WOFF_W2(l)  (WOFF_L(l) + 4718592ULL)
#define WOFF_PKV    (589824ULL + 4ULL*WPERL)
#define WTOTAL      30081024ULL

// ---------------------------------------------------------------------------
// Device scratch
// ---------------------------------------------------------------------------
__device__ float g_x   [TOKS*DIM];
__device__ float g_qkv [TOKS*2304];
__device__ __half g_xn  [TOKS*DIM];
__device__ __half g_tmp [TOKS*MLPD];
__device__ __half g_ao  [TOKS*DIM];
__device__ __nv_bfloat16 g_qTh[BH*NTOK*DHEAD], g_qTl[BH*NTOK*DHEAD];
__device__ __nv_bfloat16 g_kTh[BH*NTOK*DHEAD], g_kTl[BH*NTOK*DHEAD];
__device__ __nv_bfloat16 g_vTth[BH*DHEAD*NTOK], g_vTtl[BH*DHEAD*NTOK];
__device__ float g_kTf[BH*NTOK*DHEAD], g_vTf[BH*NTOK*DHEAD];
__device__ float g_sm  [4096];
__device__ float g_pattn[16*DIM];
__device__ float g_pool [16*DIM];
__device__ float g_pln  [16*DIM];
__device__ __half g_w[WTOTAL];

// ---------------------------------------------------------------------------
// Helpers
// ---------------------------------------------------------------------------
__device__ __forceinline__ uint32_t smem_u32(const void* p) {
    uint32_t a;
    asm("{ .reg .u64 t; cvta.to.shared.u64 t, %1; cvt.u32.u64 %0, t; }" : "=r"(a) : "l"(p));
    return a;
}

#define LDSM4(r, addr) \
    asm volatile("ldmatrix.sync.aligned.m8n8.x4.shared.b16 {%0,%1,%2,%3}, [%4];" \
        : "=r"((r)[0]), "=r"((r)[1]), "=r"((r)[2]), "=r"((r)[3]) : "r"(addr))

#define MMA16816(d, a, b) \
    asm volatile("mma.sync.aligned.m16n8k16.row.col.f32.bf16.bf16.f32 " \
        "{%0,%1,%2,%3}, {%4,%5,%6,%7}, {%8,%9}, {%0,%1,%2,%3};" \
        : "+f"((d)[0]), "+f"((d)[1]), "+f"((d)[2]), "+f"((d)[3]) \
        : "r"((a)[0]), "r"((a)[1]), "r"((a)[2]), "r"((a)[3]), "r"((b)[0]), "r"((b)[1]))

#define MMAH16816(d, a, b) \
    asm volatile("mma.sync.aligned.m16n8k16.row.col.f32.f16.f16.f32 " \
        "{%0,%1,%2,%3}, {%4,%5,%6,%7}, {%8,%9}, {%0,%1,%2,%3};" \
        : "+f"((d)[0]), "+f"((d)[1]), "+f"((d)[2]), "+f"((d)[3]) \
        : "r"((a)[0]), "r"((a)[1]), "r"((a)[2]), "r"((a)[3]), "r"((b)[0]), "r"((b)[1]))

#define CPA16(dst, src) \
    asm volatile("cp.async.cg.shared.global [%0], [%1], 16;" :: "r"(dst), "l"(src))
#define CP_COMMIT() asm volatile("cp.async.commit_group;" ::: "memory")
#define CP_WAIT0()  asm volatile("cp.async.wait_group 0;" ::: "memory")
#define CP_WAIT1()  asm volatile("cp.async.wait_group 1;" ::: "memory")

__device__ __forceinline__ void split2(float v, __nv_bfloat16& h, __nv_bfloat16& l) {
    h = __float2bfloat16(v);
    l = __float2bfloat16(v - __bfloat162float(h));
}
__device__ __forceinline__ uint32_t bfu(__nv_bfloat16 b) { return (uint32_t)__bfloat16_as_ushort(b); }

template<typename T>
__device__ __forceinline__ void cpa_tile(uint32_t smbase, const T* __restrict__ g,
                                         int ldk, int chunks, int tid)
{
    for (int i = tid; i < chunks; i += 256) {
        int r = i >> 3, c = i & 7;
        uint32_t off = r * 128 + c * 16;
        uint32_t sw = off ^ ((off >> 3) & 0x70);
        CPA16(smbase + sw, g + (size_t)r * ldk + c * 8);
    }
}

// ---------------------------------------------------------------------------
// Weight convert+transpose, family-batched: z = layer.
// W[z][K,N] fp32 -> out[z*dstStride + n*K + k] fp16
// ---------------------------------------------------------------------------
__global__ void wconv_kernel(const float* __restrict__ W, __half* __restrict__ out,
                             int K, int N, long srcStride, long dstStride)
{
    __shared__ float t[32][33];
    int z = blockIdx.z;
    const float* Wz = W + (size_t)z * srcStride;
    __half* oz = out + (size_t)z * dstStride;
    int n0 = blockIdx.x * 32, k0 = blockIdx.y * 32;
    int tx = threadIdx.x, ty = threadIdx.y;
#pragma unroll
    for (int r = 0; r < 4; r++)
        t[ty + r*8][tx] = Wz[(size_t)(k0 + ty + r*8) * N + n0 + tx];
    __syncthreads();
#pragma unroll
    for (int r = 0; r < 4; r++) {
        int n = n0 + ty + r*8, k = k0 + tx;
        oz[(size_t)n * K + k] = __float2half(t[tx][ty + r*8]);
    }
}

// ---------------------------------------------------------------------------
// Pipelined mma.sync fp16 GEMM, single pass, 2-stage, 2 CTAs/SM.
// CTA tile 128x128, 8 warps 2Mx4N (warp 64x32).
// ---------------------------------------------------------------------------
__global__ void __launch_bounds__(256, 2) mma_gemm(
    const __half* __restrict__ A, const __half* __restrict__ B,
    const float* __restrict__ bias, const float* __restrict__ res,
    float* __restrict__ C, __half* __restrict__ Ch,
    int M, int N, int K, int flags)
{
    constexpr int A_SZ = 16384;           // 128 rows x 128B
    constexpr int STG  = 2 * A_SZ;        // A + B per stage

    extern __shared__ char smem[];
    uint32_t uS = smem_u32(smem);

    const int tid = threadIdx.x;
    const int wid = tid >> 5, lane = tid & 31;
    const int m0 = blockIdx.y * 128, n0 = blockIdx.x * 128;
    const int wm = wid & 1, wn = wid >> 1;

    const __half* Az = A + (size_t)m0 * K;
    const __half* Bz = B + (size_t)n0 * K;

    float acc[4][4][4] = {};

    const int a_row = wm * 64 + (lane & 15);
    const int a_cb  = (lane >> 4) * 16;
    const int b_row = wn * 32 + (lane & 7) + ((lane >> 4) << 3);
    const int b_cb  = ((lane >> 3) & 1) * 16;

    const int KT = K >> 6;
    {
        cpa_tile(uS,         Az, K, 1024, tid);
        cpa_tile(uS + A_SZ,  Bz, K, 1024, tid);
        CP_COMMIT();
    }

    for (int kt = 0; kt < KT; kt++) {
        if (kt + 1 < KT) {
            uint32_t base = uS + ((kt + 1) & 1) * STG;
            cpa_tile(base,        Az + (kt + 1) * 64, K, 1024, tid);
            cpa_tile(base + A_SZ, Bz + (kt + 1) * 64, K, 1024, tid);
            CP_COMMIT();
            CP_WAIT1();
        } else {
            CP_WAIT0();
        }
        __syncthreads();

        uint32_t bA = uS + (kt & 1) * STG;
        uint32_t bB = bA + A_SZ;

#pragma unroll
        for (int ks = 0; ks < 4; ks++) {
            uint32_t ah[4][4], bh[2][4];
#pragma unroll
            for (int mt = 0; mt < 4; mt++) {
                int row = a_row + mt * 16;
                uint32_t off = row * 128 + ((a_cb + ks * 32) ^ ((row & 7) << 4));
                LDSM4(ah[mt], bA + off);
            }
#pragma unroll
            for (int q = 0; q < 2; q++) {
                int row = b_row + q * 16;
                uint32_t off = row * 128 + ((b_cb + ks * 32) ^ ((row & 7) << 4));
                LDSM4(bh[q], bB + off);
            }
#pragma unroll
            for (int mt = 0; mt < 4; mt++)
#pragma unroll
                for (int nt = 0; nt < 4; nt++)
                    MMAH16816(acc[mt][nt], ah[mt], &bh[nt >> 1][(nt & 1) * 2]);
        }
        __syncthreads();
    }

    const int rbase = m0 + wm * 64;
#pragma unroll
    for (int mt = 0; mt < 4; mt++) {
#pragma unroll
        for (int nt = 0; nt < 4; nt++) {
            int c = n0 + wn * 32 + nt * 8 + (lane & 3) * 2;
            float bv0 = 0.f, bv1 = 0.f;
            if (flags & FBIAS) { bv0 = bias[c]; bv1 = bias[c + 1]; }
#pragma unroll
            for (int half = 0; half < 2; half++) {
                int r = rbase + mt * 16 + (lane >> 2) + half * 8;
                float v0 = acc[mt][nt][half * 2 + 0];
                float v1 = acc[mt][nt][half * 2 + 1];
                if (flags & FBIAS) { v0 += bv0; v1 += bv1; }
                if (flags & FGELU) {
                    v0 = 0.5f * v0 * (1.f + erff(v0 * 0.70710678118654752f));
                    v1 = 0.5f * v1 * (1.f + erff(v1 * 0.70710678118654752f));
                }
                long idx = (long)r * N + c;
                if (flags & FRES) { v0 += res[idx]; v1 += res[idx + 1]; }
                if (C) *(float2*)(C + idx) = make_float2(v0, v1);
                if (Ch) {
                    __half2 hv = __floats2half2_rn(v0, v1);
                    *(__half2*)(Ch + idx) = hv;
                }
            }
        }
    }
}

// ---------------------------------------------------------------------------
// Fused flash attention (bf16 3-pass; fp16 output). Unchanged from R9.
// ---------------------------------------------------------------------------
#define FA_SMEM 165504

__global__ void __launch_bounds__(256, 1) flash_attn(
    const __nv_bfloat16* __restrict__ Qh_, const __nv_bfloat16* __restrict__ Ql_,
    const __nv_bfloat16* __restrict__ Kh_, const __nv_bfloat16* __restrict__ Kl_,
    const __nv_bfloat16* __restrict__ Vh_, const __nv_bfloat16* __restrict__ Vl_,
    const int* __restrict__ image_ids, const int* __restrict__ lengths,
    __half* __restrict__ O_)
{
    extern __shared__ char smem[];
    uint32_t uS = smem_u32(smem);
    const int tid = threadIdx.x, wid = tid >> 5, lane = tid & 31;
    const int z = blockIdx.y, b = z / 12, h = z % 12;
    const int m0 = blockIdx.x * 128;

    int* s_cmin   = (int*)(smem + 163840);
    int* s_cmax   = s_cmin + 8;
    int* s_jlist  = s_cmax + 8;
    int* s_meta   = s_jlist + 8;
    int* s_imgRow = s_meta + 8;
    int* s_imgCol = s_imgRow + 128;

    const int len = lengths[b];

    {
        int4 v = *(const int4*)(image_ids + b*1024 + wid*128 + lane*4);
        int mn = min(min(v.x, v.y), min(v.z, v.w));
        int mx = max(max(v.x, v.y), max(v.z, v.w));
#pragma unroll
        for (int o = 16; o; o >>= 1) {
            mn = min(mn, __shfl_xor_sync(0xffffffffu, mn, o));
            mx = max(mx, __shfl_xor_sync(0xffffffffu, mx, o));
        }
        if (lane == 0) { s_cmin[wid] = mn; s_cmax[wid] = mx; }
    }
    if (tid < 128) s_imgRow[tid] = image_ids[b*1024 + m0 + tid];
    __syncthreads();
    if (tid == 0) {
        int rmin = s_cmin[blockIdx.x], rmax = s_cmax[blockIdx.x];
        int nj = 0;
        for (int jb = 0; jb < 8; jb++)
            if (jb * 128 < len && s_cmax[jb] >= rmin && s_cmin[jb] <= rmax)
                s_jlist[nj++] = jb;
        s_meta[0] = nj;
    }
    __syncthreads();
    const int nj = s_meta[0];

    const size_t qoff = ((size_t)z * 1024 + m0) * 64;
    cpa_tile(uS,         Qh_ + qoff, 64, 1024, tid);
    cpa_tile(uS + 16384, Ql_ + qoff, 64, 1024, tid);

    auto prefetch = [&](int t) {
        int jb = s_jlist[t];
        int st = t & 1;
        uint32_t base = uS + 32768 + st * 65536;
        size_t koff = ((size_t)z * 1024 + jb * 128) * 64;
        cpa_tile(base,         Kh_ + koff, 64, 1024, tid);
        cpa_tile(base + 16384, Kl_ + koff, 64, 1024, tid);
        const __nv_bfloat16* vh = Vh_ + (size_t)z * 64 * 1024 + jb * 128;
        const __nv_bfloat16* vl = Vl_ + (size_t)z * 64 * 1024 + jb * 128;
        for (int i = tid; i < 1024; i += 256) {
            int r = i >> 4, c = i & 15;
            int kc = c >> 3, cc = c & 7;
            uint32_t off = r * 128 + cc * 16;
            uint32_t sw = off ^ ((off >> 3) & 0x70);
            CPA16(base + 32768 + kc * 8192 + sw, vh + (size_t)r * 1024 + c * 8);
            CPA16(base + 49152 + kc * 8192 + sw, vl + (size_t)r * 1024 + c * 8);
        }
        if (tid < 128) s_imgCol[st * 128 + tid] = image_ids[b*1024 + jb*128 + tid];
    };
    prefetch(0);
    CP_COMMIT();

    float O[8][4] = {};
    float mA = -FLT_MAX, mB = -FLT_MAX, lA = 0.f, lB = 0.f;
    uint32_t qh[4][4], ql[4][4];
    bool qloaded = false;

    const int rA = lane >> 2;
    const int imgA = s_imgRow[wid * 16 + rA];
    const int imgB = s_imgRow[wid * 16 + rA + 8];

    const int a_row = wid * 16 + (lane & 15);
    const int a_cb  = (lane >> 4) * 16;
    const int b_row_base = (lane & 7) + ((lane >> 4) << 3);
    const int b_cb  = ((lane >> 3) & 1) * 16;

    for (int t = 0; t < nj; t++) {
        if (t + 1 < nj) { prefetch(t + 1); CP_COMMIT(); CP_WAIT1(); }
        else CP_WAIT0();
        __syncthreads();

        if (!qloaded) {
            qloaded = true;
#pragma unroll
            for (int ks = 0; ks < 4; ks++) {
                uint32_t off = a_row * 128 + ((a_cb + ks * 32) ^ ((a_row & 7) << 4));
                LDSM4(qh[ks], uS + off);
                LDSM4(ql[ks], uS + 16384 + off);
            }
        }

        int st = t & 1;
        uint32_t bK  = uS + 32768 + st * 65536;
        uint32_t bKl = bK + 16384;
        uint32_t bV  = bK + 32768;
        uint32_t bVl = bK + 49152;
        int jb = s_jlist[t];
        int j0 = jb * 128;
        const int* imgC = s_imgCol + st * 128;

        float S[16][4] = {};
#pragma unroll
        for (int ks = 0; ks < 4; ks++) {
#pragma unroll
            for (int nb = 0; nb < 8; nb++) {
                uint32_t bh4[4], bl4[4];
                int row = nb * 16 + b_row_base;
                uint32_t off = row * 128 + ((b_cb + ks * 32) ^ ((row & 7) << 4));
                LDSM4(bh4, bK + off);
                LDSM4(bl4, bKl + off);
                MMA16816(S[2*nb],   qh[ks], bh4);
                MMA16816(S[2*nb+1], qh[ks], bh4 + 2);
                MMA16816(S[2*nb],   qh[ks], bl4);
                MMA16816(S[2*nb+1], qh[ks], bl4 + 2);
                MMA16816(S[2*nb],   ql[ks], bh4);
                MMA16816(S[2*nb+1], ql[ks], bh4 + 2);
            }
        }

        float mnA = mA, mnB = mB;
#pragma unroll
        for (int nt = 0; nt < 16; nt++) {
            int c0 = nt * 8 + (lane & 3) * 2;
            int i0 = imgC[c0], i1 = imgC[c0 + 1];
            bool v0 = (j0 + c0) < len, v1 = (j0 + c0 + 1) < len;
            if (i0 == imgA && v0) mnA = fmaxf(mnA, S[nt][0]);
            if (i1 == imgA && v1) mnA = fmaxf(mnA, S[nt][1]);
            if (i0 == imgB && v0) mnB = fmaxf(mnB, S[nt][2]);
            if (i1 == imgB && v1) mnB = fmaxf(mnB, S[nt][3]);
        }
#pragma unroll
        for (int o = 1; o <= 2; o <<= 1) {
            mnA = fmaxf(mnA, __shfl_xor_sync(0xffffffffu, mnA, o));
            mnB = fmaxf(mnB, __shfl_xor_sync(0xffffffffu, mnB, o));
        }
        float scA = __expf(mA - mnA), scB = __expf(mB - mnB);
        mA = mnA; mB = mnB;
        lA *= scA; lB *= scB;
#pragma unroll
        for (int nt = 0; nt < 16; nt++) {
            int c0 = nt * 8 + (lane & 3) * 2;
            int i0 = imgC[c0], i1 = imgC[c0 + 1];
            bool v0 = (j0 + c0) < len, v1 = (j0 + c0 + 1) < len;
            float p0 = (i0 == imgA && v0) ? __expf(S[nt][0] - mnA) : 0.f;
            float p1 = (i1 == imgA && v1) ? __expf(S[nt][1] - mnA) : 0.f;
            float p2 = (i0 == imgB && v0) ? __expf(S[nt][2] - mnB) : 0.f;
            float p3 = (i1 == imgB && v1) ? __expf(S[nt][3] - mnB) : 0.f;
            lA += p0 + p1; lB += p2 + p3;
            S[nt][0] = p0; S[nt][1] = p1; S[nt][2] = p2; S[nt][3] = p3;
        }
#pragma unroll
        for (int nt = 0; nt < 8; nt++) {
            O[nt][0] *= scA; O[nt][1] *= scA; O[nt][2] *= scB; O[nt][3] *= scB;
        }

#pragma unroll
        for (int kt = 0; kt < 8; kt++) {
            uint32_t ah4[4], al4[4];
            {
                __nv_bfloat16 h0, l0, h1, l1;
                split2(S[2*kt][0], h0, l0);   split2(S[2*kt][1], h1, l1);
                ah4[0] = bfu(h0) | (bfu(h1) << 16);  al4[0] = bfu(l0) | (bfu(l1) << 16);
                split2(S[2*kt][2], h0, l0);   split2(S[2*kt][3], h1, l1);
                ah4[1] = bfu(h0) | (bfu(h1) << 16);  al4[1] = bfu(l0) | (bfu(l1) << 16);
                split2(S[2*kt+1][0], h0, l0); split2(S[2*kt+1][1], h1, l1);
                ah4[2] = bfu(h0) | (bfu(h1) << 16);  al4[2] = bfu(l0) | (bfu(l1) << 16);
                split2(S[2*kt+1][2], h0, l0); split2(S[2*kt+1][3], h1, l1);
                ah4[3] = bfu(h0) | (bfu(h1) << 16);  al4[3] = bfu(l0) | (bfu(l1) << 16);
            }
            uint32_t tb  = bV  + (kt >> 2) * 8192;
            uint32_t tbl = bVl + (kt >> 2) * 8192;
#pragma unroll
            for (int nb = 0; nb < 4; nb++) {
                uint32_t vh4[4], vl4[4];
                int row = nb * 16 + b_row_base;
                uint32_t off = row * 128 + ((b_cb + (kt & 3) * 32) ^ ((row & 7) << 4));
                LDSM4(vh4, tb + off);
                LDSM4(vl4, tbl + off);
                MMA16816(O[2*nb],   ah4, vh4);
                MMA16816(O[2*nb+1], ah4, vh4 + 2);
                MMA16816(O[2*nb],   ah4, vl4);
                MMA16816(O[2*nb+1], ah4, vl4 + 2);
                MMA16816(O[2*nb],   al4, vh4);
                MMA16816(O[2*nb+1], al4, vh4 + 2);
            }
        }
        __syncthreads();
    }

#pragma unroll
    for (int o = 1; o <= 2; o <<= 1) {
        lA += __shfl_xor_sync(0xffffffffu, lA, o);
        lB += __shfl_xor_sync(0xffffffffu, lB, o);
    }
    float iA = lA > 0.f ? 1.f / lA : 0.f;
    float iB = lB > 0.f ? 1.f / lB : 0.f;
    size_t rowA = (size_t)(b * 1024 + m0 + wid * 16 + rA);
#pragma unroll
    for (int nt = 0; nt < 8; nt++) {
        int c = nt * 8 + (lane & 3) * 2;
        size_t idx = rowA * 768 + h * 64 + c;
        *(__half2*)(O_ + idx) = __floats2half2_rn(O[nt][0] * iA, O[nt][1] * iA);
        idx = (rowA + 8) * 768 + h * 64 + c;
        *(__half2*)(O_ + idx) = __floats2half2_rn(O[nt][2] * iB, O[nt][3] * iB);
    }
}

// ---------------------------------------------------------------------------
// LayerNorm over width 768. fp32 and/or fp16 outputs. Optional pos add.
// ---------------------------------------------------------------------------
__global__ void ln_kernel(const float* __restrict__ in, const float* __restrict__ g,
                          float* __restrict__ outf, __half* __restrict__ outh,
                          const float* __restrict__ pos_h, const float* __restrict__ pos_w,
                          const int* __restrict__ ppos)
{
    int row = blockIdx.x;
    int tid = threadIdx.x;
    const float* xr = in + (size_t)row * 768;
    float v[3]; float s = 0.f, q = 0.f;
#pragma unroll
    for (int i = 0; i < 3; i++) { float t = xr[tid + i*256]; v[i] = t; s += t; q += t*t; }
#pragma unroll
    for (int o = 16; o; o >>= 1) {
        s += __shfl_xor_sync(0xffffffffu, s, o);
        q += __shfl_xor_sync(0xffffffffu, q, o);
    }
    __shared__ float shs[8], shq[8], st[2];
    int w = tid >> 5;
    if ((tid & 31) == 0) { shs[w] = s; shq[w] = q; }
    __syncthreads();
    if (tid == 0) {
        float S = 0.f, Q = 0.f;
#pragma unroll
        for (int i = 0; i < 8; i++) { S += shs[i]; Q += shq[i]; }
        float mu = S * (1.f/768.f);
        st[0] = mu;
        st[1] = rsqrtf(Q * (1.f/768.f) - mu*mu + 1e-5f);
    }
    __syncthreads();
    float mu = st[0], rs = st[1];
    int p0 = 0, p1 = 0;
    if (ppos) { p0 = ppos[row*2]; p1 = ppos[row*2 + 1]; }
#pragma unroll
    for (int i = 0; i < 3; i++) {
        int c = tid + i*256;
        float y = (v[i] - mu) * rs * g[c];
        if (ppos) y += pos_h[p0*768 + c] + pos_w[p1*768 + c];
        size_t idx = (size_t)row*768 + c;
        if (outf) outf[idx] = y;
        if (outh) outh[idx] = __float2half(y);
    }
}

// ---------------------------------------------------------------------------
// Fused QKV postprocess (bf16 hi/lo outputs for flash).
// ---------------------------------------------------------------------------
__global__ void rmsT_all(const float* __restrict__ qkv,
                         const float* __restrict__ qg, const float* __restrict__ kg,
                         __nv_bfloat16* __restrict__ qh, __nv_bfloat16* __restrict__ ql,
                         __nv_bfloat16* __restrict__ kh, __nv_bfloat16* __restrict__ kl,
                         __nv_bfloat16* __restrict__ vh, __nv_bfloat16* __restrict__ vl)
{
    int token = blockIdx.x;
    int b = token >> 10, n = token & 1023;
    int w = threadIdx.x >> 5, lane = threadIdx.x & 31;
    const float* base = qkv + (size_t)token * 2304 + w * 64;
    __nv_bfloat16 hh, ll;

    {
        float v0 = base[lane], v1 = base[lane + 32];
        float ss = v0*v0 + v1*v1;
#pragma unroll
        for (int o = 16; o; o >>= 1) ss += __shfl_xor_sync(0xffffffffu, ss, o);
        float inv = 8.0f / fmaxf(sqrtf(ss), 1e-12f);
        v0 *= inv * qg[w*64 + lane];
        v1 *= inv * qg[w*64 + lane + 32];
        size_t dst = ((size_t)(b*12 + w) * 1024 + n) * 64;
        split2(v0, hh, ll); qh[dst + lane] = hh;      ql[dst + lane] = ll;
        split2(v1, hh, ll); qh[dst + lane + 32] = hh; ql[dst + lane + 32] = ll;
    }
    {
        float v0 = base[768 + lane], v1 = base[768 + lane + 32];
        float ss = v0*v0 + v1*v1;
#pragma unroll
        for (int o = 16; o; o >>= 1) ss += __shfl_xor_sync(0xffffffffu, ss, o);
        float inv = 8.0f / fmaxf(sqrtf(ss), 1e-12f);
        v0 *= inv * kg[w*64 + lane];
        v1 *= inv * kg[w*64 + lane + 32];
        size_t dst = ((size_t)(b*12 + w) * 1024 + n) * 64;
        split2(v0, hh, ll); kh[dst + lane] = hh;      kl[dst + lane] = ll;
        split2(v1, hh, ll); kh[dst + lane + 32] = hh; kl[dst + lane + 32] = ll;
    }
    {
        float v0 = base[1536 + lane], v1 = base[1536 + lane + 32];
        size_t vb = ((size_t)(b*12 + w) * 64) * 1024 + n;
        split2(v0, hh, ll); vh[vb + (size_t)lane * 1024] = hh;        vl[vb + (size_t)lane * 1024] = ll;
        split2(v1, hh, ll); vh[vb + (size_t)(lane + 32) * 1024] = hh; vl[vb + (size_t)(lane + 32) * 1024] = ll;
    }
}

// Pool-path: one launch does k-rms + v copy (fp32 outputs).
__global__ void rmsT_pool(const float* __restrict__ kv,
                          const float* __restrict__ kg,
                          float* __restrict__ kT, float* __restrict__ vT)
{
    int token = blockIdx.x;
    int b = token >> 10, n = token & 1023;
    int w = threadIdx.x >> 5, lane = threadIdx.x & 31;
    const float* base = kv + (size_t)token * 1536 + w * 64;
    {
        float v0 = base[lane], v1 = base[lane + 32];
        float ss = v0*v0 + v1*v1;
#pragma unroll
        for (int o = 16; o; o >>= 1) ss += __shfl_xor_sync(0xffffffffu, ss, o);
        float inv = 8.0f / fmaxf(sqrtf(ss), 1e-12f);
        float* dst = kT + ((size_t)(b*12 + w) * 1024 + n) * 64;
        dst[lane]      = v0 * inv * kg[w*64 + lane];
        dst[lane + 32] = v1 * inv * kg[w*64 + lane + 32];
    }
    {
        float v0 = base[768 + lane], v1 = base[768 + lane + 32];
        float* dst = vT + ((size_t)(b*12 + w) * 1024 + n) * 64;
        dst[lane] = v0; dst[lane + 32] = v1;
    }
}

// ---------------------------------------------------------------------------
// Attention pooling (192 blocks), fp32 path.
// ---------------------------------------------------------------------------
__global__ void pool_attn_kernel(const float* __restrict__ pqn, const float* __restrict__ kT,
                                 const float* __restrict__ vT, const int* __restrict__ image_ids,
                                 const int* __restrict__ lengths, float* __restrict__ out)
{
    int idx = blockIdx.x;
    int h = idx % 12, img = (idx / 12) % 4, b = idx / 48;
    int tid = threadIdx.x;
    __shared__ float q[64];
    __shared__ float p[1024];
    __shared__ float sh[8];
    __shared__ float bs[2];
    __shared__ float sred[256];
    if (tid < 64) q[tid] = pqn[h*64 + tid];
    __syncthreads();

    const float* K = kT + (size_t)(b*12 + h) * 1024 * 64;
    int len = lengths[b];
    float loc[4]; float mx = -FLT_MAX;
#pragma unroll
    for (int t = 0; t < 4; t++) {
        int j = tid + t*256;
        const float* kr = K + (size_t)j * 64;
        float dot = 0.f;
#pragma unroll
        for (int d = 0; d < 64; d++) dot += q[d] * kr[d];
        bool ok = (image_ids[b*1024 + j] == img) && (j < len);
        loc[t] = ok ? dot : -FLT_MAX;
        mx = fmaxf(mx, loc[t]);
    }
#pragma unroll
    for (int o = 16; o; o >>= 1) mx = fmaxf(mx, __shfl_xor_sync(0xffffffffu, mx, o));
    int w = tid >> 5;
    if ((tid & 31) == 0) sh[w] = mx;
    __syncthreads();
    if (tid == 0) { float mm = sh[0]; for (int i = 1; i < 8; i++) mm = fmaxf(mm, sh[i]); bs[0] = mm; }
    __syncthreads();
    mx = bs[0];
    float s = 0.f;
#pragma unroll
    for (int t = 0; t < 4; t++) {
        float e = __expf(loc[t] - mx);
        p[tid + t*256] = e;
        s += e;
    }
#pragma unroll
    for (int o = 16; o; o >>= 1) s += __shfl_xor_sync(0xffffffffu, s, o);
    if ((tid & 31) == 0) sh[w] = s;
    __syncthreads();
    if (tid == 0) { float ss = 0.f; for (int i = 0; i < 8; i++) ss += sh[i]; bs[1] = 1.f / ss; }
    __syncthreads();
    float inv = bs[1];

    const float* V = vT + (size_t)(b*12 + h) * 1024 * 64;
    int d = tid & 63, grp = tid >> 6;
    float acc = 0.f;
    for (int j = grp; j < 1024; j += 4) acc += p[j] * V[(size_t)j*64 + d];
    sred[tid] = acc;
    __syncthreads();
    if (grp == 0) {
        float r = (sred[d] + sred[d + 64]) + (sred[d + 128] + sred[d + 192]);
        out[(size_t)(b*4 + img) * 768 + h*64 + d] = r * inv;
    }
}

__global__ void rms_vec_kernel(const float* __restrict__ in, const float* __restrict__ g,
                               float* __restrict__ out)
{
    int w = threadIdx.x >> 5, lane = threadIdx.x & 31;
    float v0 = in[w*64 + lane], v1 = in[w*64 + lane + 32];
    float ss = v0*v0 + v1*v1;
#pragma unroll
    for (int o = 16; o; o >>= 1) ss += __shfl_xor_sync(0xffffffffu, ss, o);
    float inv = 8.0f / fmaxf(sqrtf(ss), 1e-12f);
    out[w*64 + lane]      = v0 * inv * g[w*64 + lane];
    out[w*64 + lane + 32] = v1 * inv * g[w*64 + lane + 32];
}

__global__ void small_gemm_kernel(const float* __restrict__ A, const float* __restrict__ W,
                                  const float* __restrict__ addvec, float* __restrict__ C,
                                  int N, int K)
{
    __shared__ float a[768];
    int row = blockIdx.y;
    for (int i = threadIdx.x; i < K; i += 256) a[i] = A[(size_t)row*K + i];
    __syncthreads();
    int n = blockIdx.x * 256 + threadIdx.x;
    if (n >= N) return;
    float acc = addvec ? addvec[n] : 0.f;
#pragma unroll 4
    for (int k = 0; k < K; k++) acc += a[k] * W[(size_t)k*N + n];
    C[(size_t)row*N + n] = acc;
}

// ---------------------------------------------------------------------------
// Host side
// ---------------------------------------------------------------------------
extern "C" void kernel_launch(void* const* d_in, const int* in_sizes, int n_in,
                              void* d_out, int out_size)
{
    (void)in_sizes; (void)n_in; (void)out_size;
    const float* patches    = (const float*)d_in[0];
    const int*   ppos       = (const int*)  d_in[1];
    const int*   image_ids  = (const int*)  d_in[2];
    const int*   lengths    = (const int*)  d_in[3];
    const float* emb_ln_g   = (const float*)d_in[4];
    const float* W_emb      = (const float*)d_in[5];
    const float* b_emb      = (const float*)d_in[6];
    const float* emb_ln2_g  = (const float*)d_in[7];
    const float* pos_h      = (const float*)d_in[8];
    const float* pos_w      = (const float*)d_in[9];
    const float* ln_attn_g  = (const float*)d_in[10];
    const float* Wq         = (const float*)d_in[11];
    const float* Wkv        = (const float*)d_in[12];
    const float* qn_g       = (const float*)d_in[13];
    const float* kn_g       = (const float*)d_in[14];
    const float* Wo         = (const float*)d_in[15];
    const float* ln_ff_g    = (const float*)d_in[16];
    const float* W1         = (const float*)d_in[17];
    const float* b1         = (const float*)d_in[18];
    const float* W2         = (const float*)d_in[19];
    const float* b2         = (const float*)d_in[20];
    const float* final_ln_g = (const float*)d_in[21];
    const float* pool_q     = (const float*)d_in[22];
    const float* pool_ln_g  = (const float*)d_in[23];
    const float* pWq        = (const float*)d_in[24];
    const float* pWkv       = (const float*)d_in[25];
    const float* p_qn_g     = (const float*)d_in[26];
    const float* p_kn_g     = (const float*)d_in[27];
    const float* pWo        = (const float*)d_in[28];
    const float* head_ln_g  = (const float*)d_in[29];
    const float* W_head     = (const float*)d_in[30];

    float *x, *qkv, *kTf, *vTf, *sm, *pattn, *pool, *pln;
    __half *xn, *tmp, *ao, *w;
    __nv_bfloat16 *qTh, *qTl, *kTh, *kTl, *vTth, *vTtl;
    cudaGetSymbolAddress((void**)&x,    g_x);
    cudaGetSymbolAddress((void**)&qkv,  g_qkv);
    cudaGetSymbolAddress((void**)&kTf,  g_kTf);
    cudaGetSymbolAddress((void**)&vTf,  g_vTf);
    cudaGetSymbolAddress((void**)&sm,   g_sm);
    cudaGetSymbolAddress((void**)&pattn,g_pattn);
    cudaGetSymbolAddress((void**)&pool, g_pool);
    cudaGetSymbolAddress((void**)&pln,  g_pln);
    cudaGetSymbolAddress((void**)&xn,   g_xn);
    cudaGetSymbolAddress((void**)&tmp,  g_tmp);
    cudaGetSymbolAddress((void**)&ao,   g_ao);
    cudaGetSymbolAddress((void**)&qTh,  g_qTh);
    cudaGetSymbolAddress((void**)&qTl,  g_qTl);
    cudaGetSymbolAddress((void**)&kTh,  g_kTh);
    cudaGetSymbolAddress((void**)&kTl,  g_kTl);
    cudaGetSymbolAddress((void**)&vTth, g_vTth);
    cudaGetSymbolAddress((void**)&vTtl, g_vTtl);
    cudaGetSymbolAddress((void**)&w,    g_w);

    constexpr int SMEMG = 65536;    // 2 stages x (16KB A + 16KB B)
    cudaFuncSetAttribute(mma_gemm,   cudaFuncAttributeMaxDynamicSharedMemorySize, SMEMG);
    cudaFuncSetAttribute(flash_attn, cudaFuncAttributeMaxDynamicSharedMemorySize, FA_SMEM);

    // ---- Convert + transpose weights to fp16 [N,K], family-batched ----
    dim3 wb(32, 8);
    wconv_kernel<<<dim3(DIM/32,  DIM/32,  1), wb>>>(W_emb, w + WOFF_EMB, DIM, DIM, 0, 0);
    wconv_kernel<<<dim3(DIM/32,  DIM/32,  4), wb>>>(Wq,  w + WOFF_Q(0),  DIM,  DIM,   (long)DIM*DIM,   (long)WPERL);
    wconv_kernel<<<dim3(2*DIM/32,DIM/32,  4), wb>>>(Wkv, w + WOFF_KV(0), DIM,  2*DIM, (long)DIM*2*DIM, (long)WPERL);
    wconv_kernel<<<dim3(DIM/32,  DIM/32,  4), wb>>>(Wo,  w + WOFF_O(0),  DIM,  DIM,   (long)DIM*DIM,   (long)WPERL);
    wconv_kernel<<<dim3(MLPD/32, DIM/32,  4), wb>>>(W1,  w + WOFF_W1(0), DIM,  MLPD,  (long)DIM*MLPD,  (long)WPERL);
    wconv_kernel<<<dim3(DIM/32,  MLPD/32, 4), wb>>>(W2,  w + WOFF_W2(0), MLPD, DIM,   (long)MLPD*DIM,  (long)WPERL);
    wconv_kernel<<<dim3(2*DIM/32,DIM/32,  1), wb>>>(pWkv, w + WOFF_PKV, DIM, 2*DIM, 0, 0);

    auto G = [&](const __half* a, const __half* bw,
                 const float* bias, const float* res,
                 float* C, __half* Ch, int M, int N, int K, int flags) {
        mma_gemm<<<dim3(N/128, M/128), 256, SMEMG>>>(a, bw, bias, res, C, Ch, M, N, K, flags);
    };

    // ---- Embedding ----
    ln_kernel<<<TOKS, 256>>>(patches, emb_ln_g, nullptr, xn, nullptr, nullptr, nullptr);
    G(xn, w + WOFF_EMB, b_emb, nullptr, x, nullptr, TOKS, DIM, DIM, FBIAS);
    ln_kernel<<<TOKS, 256>>>(x, emb_ln2_g, x, nullptr, pos_h, pos_w, ppos);

    // ---- Transformer layers ----
    for (int l = 0; l < 4; l++) {
        ln_kernel<<<TOKS, 256>>>(x, ln_attn_g + l*DIM, nullptr, xn, nullptr, nullptr, nullptr);
        G(xn, w + WOFF_Q(l), nullptr, nullptr, qkv, nullptr, TOKS, 2304, DIM, 0);
        rmsT_all<<<TOKS, 384>>>(qkv, qn_g + l*DIM, kn_g + l*DIM, qTh, qTl, kTh, kTl, vTth, vTtl);
        flash_attn<<<dim3(8, BH), 256, FA_SMEM>>>(qTh, qTl, kTh, kTl, vTth, vTtl,
                                                  image_ids, lengths, ao);
        G(ao, w + WOFF_O(l), nullptr, x, x, nullptr, TOKS, DIM, DIM, FRES);
        ln_kernel<<<TOKS, 256>>>(x, ln_ff_g + l*DIM, nullptr, xn, nullptr, nullptr, nullptr);
        G(xn, w + WOFF_W1(l), b1 + l*MLPD, nullptr, nullptr, tmp, TOKS, MLPD, DIM, FBIAS|FGELU);
        G(tmp, w + WOFF_W2(l), b2 + l*DIM, x, x, nullptr, TOKS, DIM, MLPD, FBIAS|FRES);
    }

    // ---- Final LN ----
    ln_kernel<<<TOKS, 256>>>(x, final_ln_g, nullptr, xn, nullptr, nullptr, nullptr);

    // ---- Attention pooling ----
    ln_kernel<<<1, 256>>>(pool_q, pool_ln_g, sm, nullptr, nullptr, nullptr, nullptr);
    small_gemm_kernel<<<dim3(3, 1), 256>>>(sm, pWq, nullptr, sm + 768, DIM, DIM);
    rms_vec_kernel<<<1, 384>>>(sm + 768, p_qn_g, sm + 1536);
    G(xn, w + WOFF_PKV, nullptr, nullptr, qkv, nullptr, TOKS, 1536, DIM, 0);
    rmsT_pool<<<TOKS, 384>>>(qkv, p_kn_g, kTf, vTf);
    pool_attn_kernel<<<NB*IMGS*NHEAD, 256>>>(sm + 1536, kTf, vTf, image_ids, lengths, pattn);
    small_gemm_kernel<<<dim3(3, 16), 256>>>(pattn, pWo, pool_q, pool, DIM, DIM);
    ln_kernel<<<16, 256>>>(pool, head_ln_g, pln, nullptr, nullptr, nullptr, nullptr);
    small_gemm_kernel<<<dim3(4, 16), 256>>>(pln, W_head, nullptr, (float*)d_out, NCLS, DIM);
}